// round 3
// baseline (speedup 1.0000x reference)
#include <cuda_runtime.h>

#define BB 4
#define CC 512
#define TT 4096
#define NG 32
#define CPG 16
#define HEADS 4
#define HC 128
#define COUT3 1536
#define KQ 32
#define KP 5

// Scratch (allocation-free rule: __device__ globals).
// g_xn is reused as the attention-output buffer (dead after qkv conv).
__device__ float g_xn[(size_t)BB * CC * TT];      // 32 MB: normalized x, then attn out
__device__ float g_qkv[(size_t)BB * COUT3 * TT];  // 96 MB: qkv conv out

// ---------------------------------------------------------------------------
// GroupNorm: one block per (b, group). 16 ch x 4096 = 65536 elems per group.
// ---------------------------------------------------------------------------
__global__ void __launch_bounds__(256) gn_kernel(const float* __restrict__ x,
                                                 const float* __restrict__ gamma,
                                                 const float* __restrict__ beta) {
    int b = blockIdx.x / NG, g = blockIdx.x % NG;
    const float* xp = x + ((size_t)b * CC + g * CPG) * TT;
    float* op = g_xn + ((size_t)b * CC + g * CPG) * TT;
    int tid = threadIdx.x;
    const int N = CPG * TT;
    float s = 0.f, s2 = 0.f;
    const float4* xp4 = (const float4*)xp;
    for (int i = tid; i < N / 4; i += 256) {
        float4 v = xp4[i];
        s += v.x + v.y + v.z + v.w;
        s2 += v.x * v.x + v.y * v.y + v.z * v.z + v.w * v.w;
    }
    __shared__ float rs[256], rs2[256];
    rs[tid] = s; rs2[tid] = s2;
    __syncthreads();
    for (int st = 128; st > 0; st >>= 1) {
        if (tid < st) { rs[tid] += rs[tid + st]; rs2[tid] += rs2[tid + st]; }
        __syncthreads();
    }
    float mu = rs[0] / N;
    float var = rs2[0] / N - mu * mu;
    float rstd = rsqrtf(var + 1e-5f);
    float4* op4 = (float4*)op;
    for (int i = tid; i < N / 4; i += 256) {
        int c = g * CPG + (i * 4) / TT;
        float ga = gamma[c] * rstd, be = beta[c] - mu * ga;
        float4 v = xp4[i];
        v.x = v.x * ga + be; v.y = v.y * ga + be;
        v.z = v.z * ga + be; v.w = v.w * ga + be;
        op4[i] = v;
    }
}

// ---------------------------------------------------------------------------
// QKV conv1d, k=32, SAME (pad 15 left / 16 right) as implicit GEMM.
// Block tile: 128 co x 128 t, 256 threads, 8x8 register tile.
// Loop over ci; per ci: w tile [32 dk][128 co] in smem, x window [159] in smem.
// ---------------------------------------------------------------------------
#define QTM 128
#define QTN 128
__global__ void __launch_bounds__(256) qkv_kernel(const float* __restrict__ w,
                                                  const float* __restrict__ bias) {
    int t0 = blockIdx.x * QTN;
    int co0 = blockIdx.y * QTM;
    int b = blockIdx.z;
    __shared__ float w_s[KQ][QTM];
    __shared__ float x_s[QTN + KQ + 16];
    int tid = threadIdx.x;
    int tx = tid & 15;   // t direction (8 each)
    int ty = tid >> 4;   // co direction (8 each)
    float acc[8][8] = {};
    const float* xb = g_xn + (size_t)b * CC * TT;

    for (int ci = 0; ci < CC; ci++) {
        __syncthreads();
        // w[co0+col, ci, dk] -> w_s[dk][col]; dk contiguous -> float4 loads.
        // 128 cols x 8 float4 groups = 1024 = 256 threads x 4.
        {
            int col = tid >> 1;                 // 0..127, two threads per col
            int g4 = (tid & 1) * 4;             // float4 group start: 0 or 4 (of 8)
            const float4* wp =
                (const float4*)(w + (size_t)(co0 + col) * (CC * KQ) + ci * KQ);
#pragma unroll
            for (int q = 0; q < 4; q++) {
                float4 v = wp[g4 + q];
                int dk = (g4 + q) * 4;
                w_s[dk + 0][col] = v.x;
                w_s[dk + 1][col] = v.y;
                w_s[dk + 2][col] = v.z;
                w_s[dk + 3][col] = v.w;
            }
        }
        // x window t0-15 .. t0+127+16 (159 values, zero-padded)
        for (int i = tid; i < QTN + KQ - 1; i += 256) {
            int tg = t0 - 15 + i;
            x_s[i] = (tg >= 0 && tg < TT) ? xb[(size_t)ci * TT + tg] : 0.f;
        }
        __syncthreads();

        float xv[8];
#pragma unroll
        for (int c = 0; c < 8; c++) xv[c] = x_s[tx * 8 + c];
#pragma unroll
        for (int dk = 0; dk < KQ; dk++) {
            float wv[8];
#pragma unroll
            for (int r = 0; r < 8; r++) wv[r] = w_s[dk][ty * 8 + r];
#pragma unroll
            for (int r = 0; r < 8; r++)
#pragma unroll
                for (int c = 0; c < 8; c++) acc[r][c] += wv[r] * xv[c];
            // shift the x window by one
#pragma unroll
            for (int c = 0; c < 7; c++) xv[c] = xv[c + 1];
            xv[7] = x_s[tx * 8 + 8 + dk];
        }
    }
#pragma unroll
    for (int r = 0; r < 8; r++) {
        int co = co0 + ty * 8 + r;
        float bv = bias[co];
        float* dst = g_qkv + ((size_t)b * COUT3 + co) * TT + t0 + tx * 8;
#pragma unroll
        for (int c = 0; c < 8; c++) dst[c] = acc[r][c] + bv;
    }
}

// ---------------------------------------------------------------------------
// Flash attention, fp32. Block per (bh, 64-query tile). 256 threads.
// qkv layout per head: channels [q(128) | k(128) | v(128)] each [c][t].
// Writes output into g_xn (reused; g_xn is dead after qkv conv).
// ---------------------------------------------------------------------------
#define AQT 64
#define AKT 64
#define QPITCH 65
#define KPITCH 65
#define SPITCH 66

extern __shared__ float asmem[];

__global__ void __launch_bounds__(256) attn_kernel() {
    int q0 = blockIdx.x * AQT;
    int bh = blockIdx.y;
    int b = bh / HEADS, hh = bh % HEADS;
    const float* qkv = g_qkv + (size_t)b * COUT3 * TT + (size_t)hh * (3 * HC) * TT;

    float* q_s = asmem;                       // [HC][QPITCH]
    float* kv_s = q_s + HC * QPITCH;          // [HC][KPITCH]
    float* s_s = kv_s + HC * KPITCH;          // [AQT][SPITCH]
    float* m_s = s_s + AQT * SPITCH;          // [AQT]
    float* l_s = m_s + AQT;
    float* al_s = l_s + AQT;
    float* red = al_s + AQT;                  // [AQT][4]

    int tid = threadIdx.x;
    const float scale = 0.0883883476483184f;  // 128^-0.5 (q*128^-.25 * k*128^-.25)

    for (int i = tid; i < HC * AQT; i += 256) {
        int c = i / AQT, j = i % AQT;
        q_s[c * QPITCH + j] = qkv[(size_t)c * TT + q0 + j] * scale;
    }
    if (tid < AQT) { m_s[tid] = -1e30f; l_s[tid] = 0.f; }

    float o[8][4] = {};
    int oq = (tid >> 5) * 8;        // 8 query rows
    int oc = (tid & 31) * 4;        // 4 channels
    int sx = (tid & 15) * 4;        // S tile: 4 k-cols
    int sy = (tid >> 4) * 4;        // S tile: 4 q-rows
    int row = tid & 63, quad = tid >> 6;
    __syncthreads();

    for (int kt = 0; kt < TT; kt += AKT) {
        __syncthreads();  // prior PV reads of kv_s done
        for (int i = tid; i < HC * AKT; i += 256) {
            int c = i / AKT, j = i % AKT;
            kv_s[c * KPITCH + j] = qkv[(size_t)(HC + c) * TT + kt + j];
        }
        __syncthreads();

        // S = (scaled Q)^T K
        float sacc[4][4] = {};
        for (int c = 0; c < HC; c++) {
            float qv[4], kv[4];
#pragma unroll
            for (int i = 0; i < 4; i++) qv[i] = q_s[c * QPITCH + sy + i];
#pragma unroll
            for (int j = 0; j < 4; j++) kv[j] = kv_s[c * KPITCH + sx + j];
#pragma unroll
            for (int i = 0; i < 4; i++)
#pragma unroll
                for (int j = 0; j < 4; j++) sacc[i][j] += qv[i] * kv[j];
        }
#pragma unroll
        for (int i = 0; i < 4; i++)
#pragma unroll
            for (int j = 0; j < 4; j++) s_s[(sy + i) * SPITCH + sx + j] = sacc[i][j];
        __syncthreads();

        // online softmax: 4 threads per row (quad = 16-col slice)
        float mx = -1e30f;
#pragma unroll
        for (int j = 0; j < 16; j++) mx = fmaxf(mx, s_s[row * SPITCH + quad * 16 + j]);
        red[row * 4 + quad] = mx;
        __syncthreads();
        if (tid < AQT) {
            float m_old = m_s[tid];
            float mm = fmaxf(fmaxf(red[tid * 4], red[tid * 4 + 1]),
                             fmaxf(red[tid * 4 + 2], red[tid * 4 + 3]));
            float m_new = fmaxf(m_old, mm);
            al_s[tid] = __expf(m_old - m_new);
            m_s[tid] = m_new;
        }
        __syncthreads();
        float m_new = m_s[row];
        float ssum = 0.f;
#pragma unroll
        for (int j = 0; j < 16; j++) {
            float p = __expf(s_s[row * SPITCH + quad * 16 + j] - m_new);
            s_s[row * SPITCH + quad * 16 + j] = p;
            ssum += p;
        }
        red[row * 4 + quad] = ssum;
        __syncthreads();
        if (tid < AQT) {
            l_s[tid] = l_s[tid] * al_s[tid] +
                       red[tid * 4] + red[tid * 4 + 1] + red[tid * 4 + 2] + red[tid * 4 + 3];
        }
        __syncthreads();

        // load V over K
        for (int i = tid; i < HC * AKT; i += 256) {
            int c = i / AKT, j = i % AKT;
            kv_s[c * KPITCH + j] = qkv[(size_t)(2 * HC + c) * TT + kt + j];
        }
        __syncthreads();

        // O = O*alpha + P V^T
        float alv[8];
#pragma unroll
        for (int i = 0; i < 8; i++) alv[i] = al_s[oq + i];
#pragma unroll
        for (int i = 0; i < 8; i++)
#pragma unroll
            for (int j = 0; j < 4; j++) o[i][j] *= alv[i];
        for (int j = 0; j < AKT; j++) {
            float vv[4], pv[8];
#pragma unroll
            for (int cc2 = 0; cc2 < 4; cc2++) vv[cc2] = kv_s[(oc + cc2) * KPITCH + j];
#pragma unroll
            for (int i = 0; i < 8; i++) pv[i] = s_s[(oq + i) * SPITCH + j];
#pragma unroll
            for (int i = 0; i < 8; i++)
#pragma unroll
                for (int cc2 = 0; cc2 < 4; cc2++) o[i][cc2] += pv[i] * vv[cc2];
        }
    }

#pragma unroll
    for (int i = 0; i < 8; i++) {
        float inv = 1.f / l_s[oq + i];
#pragma unroll
        for (int j = 0; j < 4; j++)
            g_xn[((size_t)b * CC + hh * HC + oc + j) * TT + q0 + oq + i] = o[i][j] * inv;
    }
}

// ---------------------------------------------------------------------------
// Proj conv1d k=5 SAME (pad 2/2) + bias + residual, writes final output.
// Block tile 64 co x 128 t, 256 threads, 4x8 reg tile. Reads g_xn (attn out).
// ---------------------------------------------------------------------------
#define PTM 64
#define PTN 128
__global__ void __launch_bounds__(256) proj_kernel(const float* __restrict__ w,
                                                   const float* __restrict__ bias,
                                                   const float* __restrict__ x,
                                                   float* __restrict__ out) {
    int t0 = blockIdx.x * PTN;
    int co0 = blockIdx.y * PTM;
    int b = blockIdx.z;
    __shared__ float w_s[KP][PTM];
    __shared__ float x_s[PTN + 8];
    int tid = threadIdx.x;
    int tx = tid & 15;   // t (8 each)
    int ty = tid >> 4;   // co (4 each)
    float acc[4][8] = {};
    const float* hb = g_xn + (size_t)b * CC * TT;

    for (int ci = 0; ci < CC; ci++) {
        __syncthreads();
        for (int i = tid; i < PTM * KP; i += 256) {
            int col = i / KP, dk = i % KP;
            w_s[dk][col] = w[(size_t)(co0 + col) * (CC * KP) + ci * KP + dk];
        }
        for (int i = tid; i < PTN + KP - 1; i += 256) {
            int tg = t0 - 2 + i;
            x_s[i] = (tg >= 0 && tg < TT) ? hb[(size_t)ci * TT + tg] : 0.f;
        }
        __syncthreads();
        float xv[12];
#pragma unroll
        for (int c = 0; c < 12; c++) xv[c] = x_s[tx * 8 + c];
#pragma unroll
        for (int dk = 0; dk < KP; dk++) {
            float wv[4];
#pragma unroll
            for (int r = 0; r < 4; r++) wv[r] = w_s[dk][ty * 4 + r];
#pragma unroll
            for (int r = 0; r < 4; r++)
#pragma unroll
                for (int c = 0; c < 8; c++) acc[r][c] += wv[r] * xv[c + dk];
        }
    }
#pragma unroll
    for (int r = 0; r < 4; r++) {
        int co = co0 + ty * 4 + r;
        float bv = bias[co];
        size_t base = ((size_t)b * CC + co) * TT + t0 + tx * 8;
#pragma unroll
        for (int c = 0; c < 8; c++) out[base + c] = acc[r][c] + bv + x[base + c];
    }
}

// ---------------------------------------------------------------------------
extern "C" void kernel_launch(void* const* d_in, const int* in_sizes, int n_in,
                              void* d_out, int out_size) {
    const float* x = (const float*)d_in[0];
    const float* gn_gamma = (const float*)d_in[1];
    const float* gn_beta = (const float*)d_in[2];
    const float* qkv_w = (const float*)d_in[3];
    const float* qkv_b = (const float*)d_in[4];
    const float* proj_w = (const float*)d_in[5];
    const float* proj_b = (const float*)d_in[6];
    float* out = (float*)d_out;

    const int attn_smem = (HC * QPITCH + HC * KPITCH + AQT * SPITCH + 3 * AQT + 4 * AQT)
                          * (int)sizeof(float);
    cudaFuncSetAttribute(attn_kernel, cudaFuncAttributeMaxDynamicSharedMemorySize, attn_smem);

    gn_kernel<<<BB * NG, 256>>>(x, gn_gamma, gn_beta);
    qkv_kernel<<<dim3(TT / QTN, COUT3 / QTM, BB), 256>>>(qkv_w, qkv_b);
    attn_kernel<<<dim3(TT / AQT, BB * HEADS), 256, attn_smem>>>();
    proj_kernel<<<dim3(TT / PTN, CC / PTM, BB), 256>>>(proj_w, proj_b, x, out);
}

// round 6
// speedup vs baseline: 1.0055x; 1.0055x over previous
#include <cuda_runtime.h>

#define BB 4
#define CC 512
#define TT 4096
#define NG 32
#define CPG 16
#define HEADS 4
#define HC 128
#define COUT3 1536
#define KQ 32
#define KP 5

// Scratch (allocation-free rule: __device__ globals).
// g_xn is reused as the attention-output buffer (dead after qkv conv).
__device__ float g_xn[(size_t)BB * CC * TT];      // 32 MB: normalized x, then attn out
__device__ float g_qkv[(size_t)BB * COUT3 * TT];  // 96 MB: qkv conv out

// ---------------------------------------------------------------------------
// GroupNorm: one block per (b, group). 16 ch x 4096 = 65536 elems per group.
// ---------------------------------------------------------------------------
__global__ void __launch_bounds__(256) gn_kernel(const float* __restrict__ x,
                                                 const float* __restrict__ gamma,
                                                 const float* __restrict__ beta) {
    int b = blockIdx.x / NG, g = blockIdx.x % NG;
    const float* xp = x + ((size_t)b * CC + g * CPG) * TT;
    float* op = g_xn + ((size_t)b * CC + g * CPG) * TT;
    int tid = threadIdx.x;
    const int N = CPG * TT;
    float s = 0.f, s2 = 0.f;
    const float4* xp4 = (const float4*)xp;
    for (int i = tid; i < N / 4; i += 256) {
        float4 v = xp4[i];
        s += v.x + v.y + v.z + v.w;
        s2 += v.x * v.x + v.y * v.y + v.z * v.z + v.w * v.w;
    }
    __shared__ float rs[256], rs2[256];
    rs[tid] = s; rs2[tid] = s2;
    __syncthreads();
    for (int st = 128; st > 0; st >>= 1) {
        if (tid < st) { rs[tid] += rs[tid + st]; rs2[tid] += rs2[tid + st]; }
        __syncthreads();
    }
    float mu = rs[0] / N;
    float var = rs2[0] / N - mu * mu;
    float rstd = rsqrtf(var + 1e-5f);
    float4* op4 = (float4*)op;
    for (int i = tid; i < N / 4; i += 256) {
        int c = g * CPG + (i * 4) / TT;
        float ga = gamma[c] * rstd, be = beta[c] - mu * ga;
        float4 v = xp4[i];
        v.x = v.x * ga + be; v.y = v.y * ga + be;
        v.z = v.z * ga + be; v.w = v.w * ga + be;
        op4[i] = v;
    }
}

// ---------------------------------------------------------------------------
// QKV conv1d, k=32, SAME (pad 15 left / 16 right) as implicit GEMM.
// Block tile: 128 co x 128 t, 256 threads, 8x8 register tile.
// Loop over ci; per ci: w tile [32 dk][128 co] in smem, x window [159] in smem.
// ---------------------------------------------------------------------------
#define QTM 128
#define QTN 128
__global__ void __launch_bounds__(256) qkv_kernel(const float* __restrict__ w,
                                                  const float* __restrict__ bias) {
    int t0 = blockIdx.x * QTN;
    int co0 = blockIdx.y * QTM;
    int b = blockIdx.z;
    __shared__ float w_s[KQ][QTM];
    __shared__ float x_s[QTN + KQ + 16];
    int tid = threadIdx.x;
    int tx = tid & 15;   // t direction (8 each)
    int ty = tid >> 4;   // co direction (8 each)
    float acc[8][8] = {};
    const float* xb = g_xn + (size_t)b * CC * TT;

    for (int ci = 0; ci < CC; ci++) {
        __syncthreads();
        // w[co0+col, ci, dk] -> w_s[dk][col]; dk contiguous -> float4 loads.
        // 128 cols x 8 float4 groups = 1024 = 256 threads x 4.
        {
            int col = tid >> 1;                 // 0..127, two threads per col
            int g4 = (tid & 1) * 4;             // float4 group start: 0 or 4 (of 8)
            const float4* wp =
                (const float4*)(w + (size_t)(co0 + col) * (CC * KQ) + ci * KQ);
#pragma unroll
            for (int q = 0; q < 4; q++) {
                float4 v = wp[g4 + q];
                int dk = (g4 + q) * 4;
                w_s[dk + 0][col] = v.x;
                w_s[dk + 1][col] = v.y;
                w_s[dk + 2][col] = v.z;
                w_s[dk + 3][col] = v.w;
            }
        }
        // x window t0-15 .. t0+127+16 (159 values, zero-padded)
        for (int i = tid; i < QTN + KQ - 1; i += 256) {
            int tg = t0 - 15 + i;
            x_s[i] = (tg >= 0 && tg < TT) ? xb[(size_t)ci * TT + tg] : 0.f;
        }
        __syncthreads();

        float xv[8];
#pragma unroll
        for (int c = 0; c < 8; c++) xv[c] = x_s[tx * 8 + c];
#pragma unroll
        for (int dk = 0; dk < KQ; dk++) {
            float wv[8];
#pragma unroll
            for (int r = 0; r < 8; r++) wv[r] = w_s[dk][ty * 8 + r];
#pragma unroll
            for (int r = 0; r < 8; r++)
#pragma unroll
                for (int c = 0; c < 8; c++) acc[r][c] += wv[r] * xv[c];
            // shift the x window by one
#pragma unroll
            for (int c = 0; c < 7; c++) xv[c] = xv[c + 1];
            xv[7] = x_s[tx * 8 + 8 + dk];
        }
    }
#pragma unroll
    for (int r = 0; r < 8; r++) {
        int co = co0 + ty * 8 + r;
        float bv = bias[co];
        float* dst = g_qkv + ((size_t)b * COUT3 + co) * TT + t0 + tx * 8;
#pragma unroll
        for (int c = 0; c < 8; c++) dst[c] = acc[r][c] + bv;
    }
}

// ---------------------------------------------------------------------------
// Flash attention, fp32. Block per (bh, 64-query tile). 256 threads.
// qkv layout per head: channels [q(128) | k(128) | v(128)] each [c][t].
// Writes output into g_xn (reused; g_xn is dead after qkv conv).
// ---------------------------------------------------------------------------
#define AQT 64
#define AKT 64
#define QPITCH 65
#define KPITCH 65
#define SPITCH 66

extern __shared__ float asmem[];

__global__ void __launch_bounds__(256) attn_kernel() {
    int q0 = blockIdx.x * AQT;
    int bh = blockIdx.y;
    int b = bh / HEADS, hh = bh % HEADS;
    const float* qkv = g_qkv + (size_t)b * COUT3 * TT + (size_t)hh * (3 * HC) * TT;

    float* q_s = asmem;                       // [HC][QPITCH]
    float* kv_s = q_s + HC * QPITCH;          // [HC][KPITCH]
    float* s_s = kv_s + HC * KPITCH;          // [AQT][SPITCH]
    float* m_s = s_s + AQT * SPITCH;          // [AQT]
    float* l_s = m_s + AQT;
    float* al_s = l_s + AQT;
    float* red = al_s + AQT;                  // [AQT][4]

    int tid = threadIdx.x;
    const float scale = 0.0883883476483184f;  // 128^-0.5 (q*128^-.25 * k*128^-.25)

    for (int i = tid; i < HC * AQT; i += 256) {
        int c = i / AQT, j = i % AQT;
        q_s[c * QPITCH + j] = qkv[(size_t)c * TT + q0 + j] * scale;
    }
    if (tid < AQT) { m_s[tid] = -1e30f; l_s[tid] = 0.f; }

    float o[8][4] = {};
    int oq = (tid >> 5) * 8;        // 8 query rows
    int oc = (tid & 31) * 4;        // 4 channels
    int sx = (tid & 15) * 4;        // S tile: 4 k-cols
    int sy = (tid >> 4) * 4;        // S tile: 4 q-rows
    int row = tid & 63, quad = tid >> 6;
    __syncthreads();

    for (int kt = 0; kt < TT; kt += AKT) {
        __syncthreads();  // prior PV reads of kv_s done
        for (int i = tid; i < HC * AKT; i += 256) {
            int c = i / AKT, j = i % AKT;
            kv_s[c * KPITCH + j] = qkv[(size_t)(HC + c) * TT + kt + j];
        }
        __syncthreads();

        // S = (scaled Q)^T K
        float sacc[4][4] = {};
        for (int c = 0; c < HC; c++) {
            float qv[4], kv[4];
#pragma unroll
            for (int i = 0; i < 4; i++) qv[i] = q_s[c * QPITCH + sy + i];
#pragma unroll
            for (int j = 0; j < 4; j++) kv[j] = kv_s[c * KPITCH + sx + j];
#pragma unroll
            for (int i = 0; i < 4; i++)
#pragma unroll
                for (int j = 0; j < 4; j++) sacc[i][j] += qv[i] * kv[j];
        }
#pragma unroll
        for (int i = 0; i < 4; i++)
#pragma unroll
            for (int j = 0; j < 4; j++) s_s[(sy + i) * SPITCH + sx + j] = sacc[i][j];
        __syncthreads();

        // online softmax: 4 threads per row (quad = 16-col slice)
        float mx = -1e30f;
#pragma unroll
        for (int j = 0; j < 16; j++) mx = fmaxf(mx, s_s[row * SPITCH + quad * 16 + j]);
        red[row * 4 + quad] = mx;
        __syncthreads();
        if (tid < AQT) {
            float m_old = m_s[tid];
            float mm = fmaxf(fmaxf(red[tid * 4], red[tid * 4 + 1]),
                             fmaxf(red[tid * 4 + 2], red[tid * 4 + 3]));
            float m_new = fmaxf(m_old, mm);
            al_s[tid] = __expf(m_old - m_new);
            m_s[tid] = m_new;
        }
        __syncthreads();
        float m_new = m_s[row];
        float ssum = 0.f;
#pragma unroll
        for (int j = 0; j < 16; j++) {
            float p = __expf(s_s[row * SPITCH + quad * 16 + j] - m_new);
            s_s[row * SPITCH + quad * 16 + j] = p;
            ssum += p;
        }
        red[row * 4 + quad] = ssum;
        __syncthreads();
        if (tid < AQT) {
            l_s[tid] = l_s[tid] * al_s[tid] +
                       red[tid * 4] + red[tid * 4 + 1] + red[tid * 4 + 2] + red[tid * 4 + 3];
        }
        __syncthreads();

        // load V over K
        for (int i = tid; i < HC * AKT; i += 256) {
            int c = i / AKT, j = i % AKT;
            kv_s[c * KPITCH + j] = qkv[(size_t)(2 * HC + c) * TT + kt + j];
        }
        __syncthreads();

        // O = O*alpha + P V^T
        float alv[8];
#pragma unroll
        for (int i = 0; i < 8; i++) alv[i] = al_s[oq + i];
#pragma unroll
        for (int i = 0; i < 8; i++)
#pragma unroll
            for (int j = 0; j < 4; j++) o[i][j] *= alv[i];
        for (int j = 0; j < AKT; j++) {
            float vv[4], pv[8];
#pragma unroll
            for (int cc2 = 0; cc2 < 4; cc2++) vv[cc2] = kv_s[(oc + cc2) * KPITCH + j];
#pragma unroll
            for (int i = 0; i < 8; i++) pv[i] = s_s[(oq + i) * SPITCH + j];
#pragma unroll
            for (int i = 0; i < 8; i++)
#pragma unroll
                for (int cc2 = 0; cc2 < 4; cc2++) o[i][cc2] += pv[i] * vv[cc2];
        }
    }

#pragma unroll
    for (int i = 0; i < 8; i++) {
        float inv = 1.f / l_s[oq + i];
#pragma unroll
        for (int j = 0; j < 4; j++)
            g_xn[((size_t)b * CC + hh * HC + oc + j) * TT + q0 + oq + i] = o[i][j] * inv;
    }
}

// ---------------------------------------------------------------------------
// Proj conv1d k=5 SAME (pad 2/2) + bias + residual, writes final output.
// Block tile 64 co x 128 t, 256 threads, 4x8 reg tile. Reads g_xn (attn out).
// ---------------------------------------------------------------------------
#define PTM 64
#define PTN 128
__global__ void __launch_bounds__(256) proj_kernel(const float* __restrict__ w,
                                                   const float* __restrict__ bias,
                                                   const float* __restrict__ x,
                                                   float* __restrict__ out) {
    int t0 = blockIdx.x * PTN;
    int co0 = blockIdx.y * PTM;
    int b = blockIdx.z;
    __shared__ float w_s[KP][PTM];
    __shared__ float x_s[PTN + 8];
    int tid = threadIdx.x;
    int tx = tid & 15;   // t (8 each)
    int ty = tid >> 4;   // co (4 each)
    float acc[4][8] = {};
    const float* hb = g_xn + (size_t)b * CC * TT;

    for (int ci = 0; ci < CC; ci++) {
        __syncthreads();
        for (int i = tid; i < PTM * KP; i += 256) {
            int col = i / KP, dk = i % KP;
            w_s[dk][col] = w[(size_t)(co0 + col) * (CC * KP) + ci * KP + dk];
        }
        for (int i = tid; i < PTN + KP - 1; i += 256) {
            int tg = t0 - 2 + i;
            x_s[i] = (tg >= 0 && tg < TT) ? hb[(size_t)ci * TT + tg] : 0.f;
        }
        __syncthreads();
        float xv[12];
#pragma unroll
        for (int c = 0; c < 12; c++) xv[c] = x_s[tx * 8 + c];
#pragma unroll
        for (int dk = 0; dk < KP; dk++) {
            float wv[4];
#pragma unroll
            for (int r = 0; r < 4; r++) wv[r] = w_s[dk][ty * 4 + r];
#pragma unroll
            for (int r = 0; r < 4; r++)
#pragma unroll
                for (int c = 0; c < 8; c++) acc[r][c] += wv[r] * xv[c + dk];
        }
    }
#pragma unroll
    for (int r = 0; r < 4; r++) {
        int co = co0 + ty * 4 + r;
        float bv = bias[co];
        size_t base = ((size_t)b * CC + co) * TT + t0 + tx * 8;
#pragma unroll
        for (int c = 0; c < 8; c++) out[base + c] = acc[r][c] + bv + x[base + c];
    }
}

// ---------------------------------------------------------------------------
extern "C" void kernel_launch(void* const* d_in, const int* in_sizes, int n_in,
                              void* d_out, int out_size) {
    const float* x = (const float*)d_in[0];
    const float* gn_gamma = (const float*)d_in[1];
    const float* gn_beta = (const float*)d_in[2];
    const float* qkv_w = (const float*)d_in[3];
    const float* qkv_b = (const float*)d_in[4];
    const float* proj_w = (const float*)d_in[5];
    const float* proj_b = (const float*)d_in[6];
    float* out = (float*)d_out;

    const int attn_smem = (HC * QPITCH + HC * KPITCH + AQT * SPITCH + 3 * AQT + 4 * AQT)
                          * (int)sizeof(float);
    cudaFuncSetAttribute(attn_kernel, cudaFuncAttributeMaxDynamicSharedMemorySize, attn_smem);

    gn_kernel<<<BB * NG, 256>>>(x, gn_gamma, gn_beta);
    qkv_kernel<<<dim3(TT / QTN, COUT3 / QTM, BB), 256>>>(qkv_w, qkv_b);
    attn_kernel<<<dim3(TT / AQT, BB * HEADS), 256, attn_smem>>>();
    proj_kernel<<<dim3(TT / PTN, CC / PTM, BB), 256>>>(proj_w, proj_b, x, out);
}

// round 9
// speedup vs baseline: 1.6568x; 1.6478x over previous
#include <cuda_runtime.h>
#include <cuda_bf16.h>
#include <cstdint>

#define BB 4
#define CC 512
#define TT 4096
#define TP 4128
#define NG 32
#define CPG 16
#define HEADS 4
#define HC 128
#define COUT3 1536
#define KQ 32
#define KP 5

__device__ float g_xn[(size_t)BB * CC * TT];
__device__ float g_qkv[(size_t)BB * COUT3 * TT];
// transposed padded input: xt[b][t+15][ci], bf16 hi/lo
__device__ __nv_bfloat16 g_xth[(size_t)BB * TP * CC];
__device__ __nv_bfloat16 g_xtl[(size_t)BB * TP * CC];
// transposed weights: wt[dk][co][ci], bf16 hi/lo
__device__ __nv_bfloat16 g_wth[(size_t)KQ * COUT3 * CC];
__device__ __nv_bfloat16 g_wtl[(size_t)KQ * COUT3 * CC];

__device__ __forceinline__ uint32_t smem_to_u32(const void* p) {
    uint32_t a;
    asm("{ .reg .u64 t; cvta.to.shared.u64 t, %1; cvt.u32.u64 %0, t; }" : "=r"(a) : "l"(p));
    return a;
}
#define LDSM4(r, addr) \
    asm volatile("ldmatrix.sync.aligned.m8n8.x4.shared.b16 {%0,%1,%2,%3}, [%4];" \
        : "=r"((r)[0]), "=r"((r)[1]), "=r"((r)[2]), "=r"((r)[3]) : "r"(addr))
#define MMA16816(d, a, b0, b1) \
    asm volatile("mma.sync.aligned.m16n8k16.row.col.f32.bf16.bf16.f32 " \
        "{%0,%1,%2,%3}, {%4,%5,%6,%7}, {%8,%9}, {%0,%1,%2,%3};" \
        : "+f"((d)[0]), "+f"((d)[1]), "+f"((d)[2]), "+f"((d)[3]) \
        : "r"((a)[0]), "r"((a)[1]), "r"((a)[2]), "r"((a)[3]), "r"(b0), "r"(b1))

// --------------------------- GroupNorm (unchanged) ---------------------------
__global__ void __launch_bounds__(256) gn_kernel(const float* __restrict__ x,
                                                 const float* __restrict__ gamma,
                                                 const float* __restrict__ beta) {
    int b = blockIdx.x / NG, g = blockIdx.x % NG;
    const float* xp = x + ((size_t)b * CC + g * CPG) * TT;
    float* op = g_xn + ((size_t)b * CC + g * CPG) * TT;
    int tid = threadIdx.x;
    const int N = CPG * TT;
    float s = 0.f, s2 = 0.f;
    const float4* xp4 = (const float4*)xp;
    for (int i = tid; i < N / 4; i += 256) {
        float4 v = xp4[i];
        s += v.x + v.y + v.z + v.w;
        s2 += v.x * v.x + v.y * v.y + v.z * v.z + v.w * v.w;
    }
    __shared__ float rs[256], rs2[256];
    rs[tid] = s; rs2[tid] = s2;
    __syncthreads();
    for (int st = 128; st > 0; st >>= 1) {
        if (tid < st) { rs[tid] += rs[tid + st]; rs2[tid] += rs2[tid + st]; }
        __syncthreads();
    }
    float mu = rs[0] / N;
    float rstd = rsqrtf(rs2[0] / N - mu * mu + 1e-5f);
    float4* op4 = (float4*)op;
    for (int i = tid; i < N / 4; i += 256) {
        int c = g * CPG + (i * 4) / TT;
        float ga = gamma[c] * rstd, be = beta[c] - mu * ga;
        float4 v = xp4[i];
        v.x = v.x * ga + be; v.y = v.y * ga + be;
        v.z = v.z * ga + be; v.w = v.w * ga + be;
        op4[i] = v;
    }
}

// ------------- zero pad rows of xt: tp in [0,15) and [4111,4128) -------------
__global__ void __launch_bounds__(256) zed_kernel() {
    int b = blockIdx.x;
    size_t base = (size_t)b * TP * CC;
    __nv_bfloat16 z = __float2bfloat16(0.f);
    for (int i = threadIdx.x; i < 32 * CC; i += 256) {
        int rr = i / CC, c = i % CC;
        int row = (rr < 15) ? rr : (4096 + rr);   // 4111..4127
        g_xth[base + (size_t)row * CC + c] = z;
        g_xtl[base + (size_t)row * CC + c] = z;
    }
}

// xt transform: g_xn [b][c][t] -> xt[b][t+15][c] bf16 hi/lo
__global__ void __launch_bounds__(256) xt_kernel() {
    __shared__ float s[64][65];
    int t0 = blockIdx.x * 64, c0 = blockIdx.y * 64, b = blockIdx.z;
    int tid = threadIdx.x;
    const float* xp = g_xn + ((size_t)b * CC + c0) * TT + t0;
#pragma unroll
    for (int p = 0; p < 16; p++) {
        int idx = tid + p * 256;
        s[idx >> 6][idx & 63] = xp[(size_t)(idx >> 6) * TT + (idx & 63)];
    }
    __syncthreads();
    int tl0 = tid >> 4, c4 = (tid & 15) * 4;
    size_t rb = (size_t)b * TP * CC;
#pragma unroll
    for (int p = 0; p < 4; p++) {
        int tl = tl0 + p * 16;
        int tp = t0 + tl + 15;
        float v0 = s[c4 + 0][tl], v1 = s[c4 + 1][tl];
        float v2 = s[c4 + 2][tl], v3 = s[c4 + 3][tl];
        __nv_bfloat16 h0 = __float2bfloat16_rn(v0), h1 = __float2bfloat16_rn(v1);
        __nv_bfloat16 h2 = __float2bfloat16_rn(v2), h3 = __float2bfloat16_rn(v3);
        __nv_bfloat16 l0 = __float2bfloat16_rn(v0 - __bfloat162float(h0));
        __nv_bfloat16 l1 = __float2bfloat16_rn(v1 - __bfloat162float(h1));
        __nv_bfloat16 l2 = __float2bfloat16_rn(v2 - __bfloat162float(h2));
        __nv_bfloat16 l3 = __float2bfloat16_rn(v3 - __bfloat162float(h3));
        uint2 ph, pl;
        ph.x = (uint32_t)__bfloat16_as_ushort(h0) | ((uint32_t)__bfloat16_as_ushort(h1) << 16);
        ph.y = (uint32_t)__bfloat16_as_ushort(h2) | ((uint32_t)__bfloat16_as_ushort(h3) << 16);
        pl.x = (uint32_t)__bfloat16_as_ushort(l0) | ((uint32_t)__bfloat16_as_ushort(l1) << 16);
        pl.y = (uint32_t)__bfloat16_as_ushort(l2) | ((uint32_t)__bfloat16_as_ushort(l3) << 16);
        size_t off = rb + (size_t)tp * CC + c0 + c4;
        *(uint2*)(g_xth + off) = ph;
        *(uint2*)(g_xtl + off) = pl;
    }
}

// wt transform: w [co][ci][dk] -> wt[dk][co][ci] bf16 hi/lo
__global__ void __launch_bounds__(256) wt_kernel(const float* __restrict__ w) {
    __shared__ float s[KQ][129];
    int co = blockIdx.x, ci0 = blockIdx.y * 128;
    int tid = threadIdx.x;
    const float* wp = w + ((size_t)co * CC + ci0) * KQ;
#pragma unroll
    for (int p = 0; p < 16; p++) {
        int idx = tid + p * 256;
        s[idx & 31][idx >> 5] = wp[(size_t)(idx >> 5) * KQ + (idx & 31)];
    }
    __syncthreads();
#pragma unroll
    for (int p = 0; p < 16; p++) {
        int idx = tid + p * 256;
        int dk = idx >> 7, cil = idx & 127;
        float v = s[dk][cil];
        __nv_bfloat16 h = __float2bfloat16_rn(v);
        size_t off = ((size_t)dk * COUT3 + co) * CC + ci0 + cil;
        g_wth[off] = h;
        g_wtl[off] = __float2bfloat16_rn(v - __bfloat162float(h));
    }
}

// -------------- QKV conv as warp-mma bf16x3 implicit GEMM --------------------
// CTA: 128 co x 256 t, 512 threads (4x4 warps, warp tile 32 co x 64 t).
// D[co][t] = sum_{dk,ci} w[co][ci][dk] * x[ci][t+dk-15]; x[..] = xt[t+dk][..].
// Loop: 8 ci-chunks(64) x 32 dk x 4 k16. B window 287 rows resident per chunk.
#define PITCH 144
#define A_H 0
#define A_L 18432
#define B_H 36864
#define B_L 78336
#define QSMEM 119808

extern __shared__ char qsm[];

__global__ void __launch_bounds__(512, 1) qkvmma_kernel(const float* __restrict__ bias) {
    int t0 = blockIdx.x * 256, co0 = blockIdx.y * 128, b = blockIdx.z;
    int tid = threadIdx.x, wid = tid >> 5, lane = tid & 31;
    int co_w = (wid >> 2) * 32, t_w = (wid & 3) * 64;
    uint32_t sb = smem_to_u32(qsm);

    float acc[2][8][4] = {};

    for (int ch = 0; ch < 8; ch++) {
        int ci0 = ch * 64;
        __syncthreads();
        // load B window: 287 rows x 64 ci (8 uint4 granules), h + l
        {
            const __nv_bfloat16* bh = g_xth + ((size_t)b * TP + t0) * CC + ci0;
            const __nv_bfloat16* bl = g_xtl + ((size_t)b * TP + t0) * CC + ci0;
            for (int i = tid; i < 287 * 8; i += 512) {
                int row = i >> 3, g = i & 7;
                size_t go = (size_t)row * CC + g * 8;
                *(uint4*)(qsm + B_H + row * PITCH + g * 16) = *(const uint4*)(bh + go);
                *(uint4*)(qsm + B_L + row * PITCH + g * 16) = *(const uint4*)(bl + go);
            }
        }
        for (int dk = 0; dk < 32; dk++) {
            __syncthreads();
            // load A: 128 co x 64 ci, h + l
            {
                const __nv_bfloat16* ah = g_wth + ((size_t)dk * COUT3 + co0) * CC + ci0;
                const __nv_bfloat16* al = g_wtl + ((size_t)dk * COUT3 + co0) * CC + ci0;
                for (int i = tid; i < 128 * 8; i += 512) {
                    int row = i >> 3, g = i & 7;
                    size_t go = (size_t)row * CC + g * 8;
                    *(uint4*)(qsm + A_H + row * PITCH + g * 16) = *(const uint4*)(ah + go);
                    *(uint4*)(qsm + A_L + row * PITCH + g * 16) = *(const uint4*)(al + go);
                }
            }
            __syncthreads();

            int mtx = lane >> 3, r8 = lane & 7;
#pragma unroll
            for (int ks = 0; ks < 4; ks++) {
                uint32_t a_h[2][4], a_l[2][4];
                int aoff = ((mtx & 1) * 8 + r8) * PITCH + ks * 32 + (mtx >> 1) * 16;
#pragma unroll
                for (int m = 0; m < 2; m++) {
                    uint32_t ad = sb + (co_w + m * 16) * PITCH + aoff;
                    LDSM4(a_h[m], ad + A_H);
                    LDSM4(a_l[m], ad + A_L);
                }
#pragma unroll
                for (int n = 0; n < 8; n++) {
                    int brow = t_w + n * 8 + (lane >> 2) + dk;
                    const char* bp = qsm + brow * PITCH + ks * 32 + (lane & 3) * 4;
                    uint32_t bh0 = *(const uint32_t*)(bp + B_H);
                    uint32_t bh1 = *(const uint32_t*)(bp + B_H + 16);
                    uint32_t bl0 = *(const uint32_t*)(bp + B_L);
                    uint32_t bl1 = *(const uint32_t*)(bp + B_L + 16);
                    MMA16816(acc[0][n], a_h[0], bh0, bh1);
                    MMA16816(acc[0][n], a_l[0], bh0, bh1);
                    MMA16816(acc[0][n], a_h[0], bl0, bl1);
                    MMA16816(acc[1][n], a_h[1], bh0, bh1);
                    MMA16816(acc[1][n], a_l[1], bh0, bh1);
                    MMA16816(acc[1][n], a_h[1], bl0, bl1);
                }
            }
        }
    }

    // epilogue: d[m][n][0..3]: rows co_w+m*16+lane/4 (+8), cols t_w+n*8+(lane%3)*2
#pragma unroll
    for (int m = 0; m < 2; m++) {
        int r0 = co_w + m * 16 + (lane >> 2);
        float bv0 = bias[co0 + r0];
        float bv1 = bias[co0 + r0 + 8];
        float* d0 = g_qkv + ((size_t)b * COUT3 + co0 + r0) * TT + t0;
        float* d1 = d0 + (size_t)8 * TT;
#pragma unroll
        for (int n = 0; n < 8; n++) {
            int cp = t_w + n * 8 + (lane & 3) * 2;
            float2 v0, v1;
            v0.x = acc[m][n][0] + bv0; v0.y = acc[m][n][1] + bv0;
            v1.x = acc[m][n][2] + bv1; v1.y = acc[m][n][3] + bv1;
            *(float2*)(d0 + cp) = v0;
            *(float2*)(d1 + cp) = v1;
        }
    }
}

// --------------------------- Flash attention (unchanged) ---------------------
#define AQT 64
#define AKT 64
#define QPITCH 65
#define KPITCH 65
#define SPITCH 66
extern __shared__ float asmem[];
__global__ void __launch_bounds__(256) attn_kernel() {
    int q0 = blockIdx.x * AQT;
    int bh = blockIdx.y;
    int b = bh / HEADS, hh = bh % HEADS;
    const float* qkv = g_qkv + (size_t)b * COUT3 * TT + (size_t)hh * (3 * HC) * TT;
    float* q_s = asmem;
    float* kv_s = q_s + HC * QPITCH;
    float* s_s = kv_s + HC * KPITCH;
    float* m_s = s_s + AQT * SPITCH;
    float* l_s = m_s + AQT;
    float* al_s = l_s + AQT;
    float* red = al_s + AQT;
    int tid = threadIdx.x;
    const float scale = 0.0883883476483184f;
    for (int i = tid; i < HC * AQT; i += 256) {
        int c = i / AQT, j = i % AQT;
        q_s[c * QPITCH + j] = qkv[(size_t)c * TT + q0 + j] * scale;
    }
    if (tid < AQT) { m_s[tid] = -1e30f; l_s[tid] = 0.f; }
    float o[8][4] = {};
    int oq = (tid >> 5) * 8, oc = (tid & 31) * 4;
    int sx = (tid & 15) * 4, sy = (tid >> 4) * 4;
    int row = tid & 63, quad = tid >> 6;
    __syncthreads();
    for (int kt = 0; kt < TT; kt += AKT) {
        __syncthreads();
        for (int i = tid; i < HC * AKT; i += 256) {
            int c = i / AKT, j = i % AKT;
            kv_s[c * KPITCH + j] = qkv[(size_t)(HC + c) * TT + kt + j];
        }
        __syncthreads();
        float sacc[4][4] = {};
        for (int c = 0; c < HC; c++) {
            float qv[4], kv[4];
#pragma unroll
            for (int i = 0; i < 4; i++) qv[i] = q_s[c * QPITCH + sy + i];
#pragma unroll
            for (int j = 0; j < 4; j++) kv[j] = kv_s[c * KPITCH + sx + j];
#pragma unroll
            for (int i = 0; i < 4; i++)
#pragma unroll
                for (int j = 0; j < 4; j++) sacc[i][j] += qv[i] * kv[j];
        }
#pragma unroll
        for (int i = 0; i < 4; i++)
#pragma unroll
            for (int j = 0; j < 4; j++) s_s[(sy + i) * SPITCH + sx + j] = sacc[i][j];
        __syncthreads();
        float mx = -1e30f;
#pragma unroll
        for (int j = 0; j < 16; j++) mx = fmaxf(mx, s_s[row * SPITCH + quad * 16 + j]);
        red[row * 4 + quad] = mx;
        __syncthreads();
        if (tid < AQT) {
            float m_old = m_s[tid];
            float mm = fmaxf(fmaxf(red[tid * 4], red[tid * 4 + 1]),
                             fmaxf(red[tid * 4 + 2], red[tid * 4 + 3]));
            float m_new = fmaxf(m_old, mm);
            al_s[tid] = __expf(m_old - m_new);
            m_s[tid] = m_new;
        }
        __syncthreads();
        float m_new = m_s[row];
        float ssum = 0.f;
#pragma unroll
        for (int j = 0; j < 16; j++) {
            float p = __expf(s_s[row * SPITCH + quad * 16 + j] - m_new);
            s_s[row * SPITCH + quad * 16 + j] = p;
            ssum += p;
        }
        red[row * 4 + quad] = ssum;
        __syncthreads();
        if (tid < AQT)
            l_s[tid] = l_s[tid] * al_s[tid] +
                       red[tid * 4] + red[tid * 4 + 1] + red[tid * 4 + 2] + red[tid * 4 + 3];
        __syncthreads();
        for (int i = tid; i < HC * AKT; i += 256) {
            int c = i / AKT, j = i % AKT;
            kv_s[c * KPITCH + j] = qkv[(size_t)(2 * HC + c) * TT + kt + j];
        }
        __syncthreads();
        float alv[8];
#pragma unroll
        for (int i = 0; i < 8; i++) alv[i] = al_s[oq + i];
#pragma unroll
        for (int i = 0; i < 8; i++)
#pragma unroll
            for (int j = 0; j < 4; j++) o[i][j] *= alv[i];
        for (int j = 0; j < AKT; j++) {
            float vv[4], pv[8];
#pragma unroll
            for (int c2 = 0; c2 < 4; c2++) vv[c2] = kv_s[(oc + c2) * KPITCH + j];
#pragma unroll
            for (int i = 0; i < 8; i++) pv[i] = s_s[(oq + i) * SPITCH + j];
#pragma unroll
            for (int i = 0; i < 8; i++)
#pragma unroll
                for (int c2 = 0; c2 < 4; c2++) o[i][c2] += pv[i] * vv[c2];
        }
    }
#pragma unroll
    for (int i = 0; i < 8; i++) {
        float inv = 1.f / l_s[oq + i];
#pragma unroll
        for (int j = 0; j < 4; j++)
            g_xn[((size_t)b * CC + hh * HC + oc + j) * TT + q0 + oq + i] = o[i][j] * inv;
    }
}

// --------------------------- Proj conv (unchanged) ---------------------------
#define PTM 64
#define PTN 128
__global__ void __launch_bounds__(256) proj_kernel(const float* __restrict__ w,
                                                   const float* __restrict__ bias,
                                                   const float* __restrict__ x,
                                                   float* __restrict__ out) {
    int t0 = blockIdx.x * PTN, co0 = blockIdx.y * PTM, b = blockIdx.z;
    __shared__ float w_s[KP][PTM];
    __shared__ float x_s[PTN + 8];
    int tid = threadIdx.x, tx = tid & 15, ty = tid >> 4;
    float acc[4][8] = {};
    const float* hb = g_xn + (size_t)b * CC * TT;
    for (int ci = 0; ci < CC; ci++) {
        __syncthreads();
        for (int i = tid; i < PTM * KP; i += 256)
            w_s[i % KP][i / KP] = w[(size_t)(co0 + i / KP) * (CC * KP) + ci * KP + i % KP];
        for (int i = tid; i < PTN + KP - 1; i += 256) {
            int tg = t0 - 2 + i;
            x_s[i] = (tg >= 0 && tg < TT) ? hb[(size_t)ci * TT + tg] : 0.f;
        }
        __syncthreads();
        float xv[12];
#pragma unroll
        for (int c = 0; c < 12; c++) xv[c] = x_s[tx * 8 + c];
#pragma unroll
        for (int dk = 0; dk < KP; dk++) {
            float wv[4];
#pragma unroll
            for (int r = 0; r < 4; r++) wv[r] = w_s[dk][ty * 4 + r];
#pragma unroll
            for (int r = 0; r < 4; r++)
#pragma unroll
                for (int c = 0; c < 8; c++) acc[r][c] += wv[r] * xv[c + dk];
        }
    }
#pragma unroll
    for (int r = 0; r < 4; r++) {
        int co = co0 + ty * 4 + r;
        float bv = bias[co];
        size_t base = ((size_t)b * CC + co) * TT + t0 + tx * 8;
#pragma unroll
        for (int c = 0; c < 8; c++) out[base + c] = acc[r][c] + bv + x[base + c];
    }
}

// -----------------------------------------------------------------------------
extern "C" void kernel_launch(void* const* d_in, const int* in_sizes, int n_in,
                              void* d_out, int out_size) {
    const float* x = (const float*)d_in[0];
    const float* gn_gamma = (const float*)d_in[1];
    const float* gn_beta = (const float*)d_in[2];
    const float* qkv_w = (const float*)d_in[3];
    const float* qkv_b = (const float*)d_in[4];
    const float* proj_w = (const float*)d_in[5];
    const float* proj_b = (const float*)d_in[6];
    float* out = (float*)d_out;

    const int attn_smem = (HC * QPITCH + HC * KPITCH + AQT * SPITCH + 7 * AQT) * (int)sizeof(float);
    cudaFuncSetAttribute(attn_kernel, cudaFuncAttributeMaxDynamicSharedMemorySize, attn_smem);
    cudaFuncSetAttribute(qkvmma_kernel, cudaFuncAttributeMaxDynamicSharedMemorySize, QSMEM);

    gn_kernel<<<BB * NG, 256>>>(x, gn_gamma, gn_beta);
    zed_kernel<<<BB, 256>>>();
    xt_kernel<<<dim3(TT / 64, CC / 64, BB), 256>>>();
    wt_kernel<<<dim3(COUT3, CC / 128), 256>>>(qkv_w);
    qkvmma_kernel<<<dim3(TT / 256, COUT3 / 128, BB), 512, QSMEM>>>(qkv_b);
    attn_kernel<<<dim3(TT / AQT, BB * HEADS), 256, attn_smem>>>();
    proj_kernel<<<dim3(TT / PTN, CC / PTM, BB), 256>>>(proj_w, proj_b, x, out);
}

// round 10
// speedup vs baseline: 1.9832x; 1.1970x over previous
#include <cuda_runtime.h>
#include <cuda_bf16.h>
#include <cstdint>

#define BB 4
#define CC 512
#define TT 4096
#define TP 4128
#define NG 32
#define CPG 16
#define HEADS 4
#define HC 128
#define COUT3 1536
#define KQ 32
#define KP 5

__device__ float g_xn[(size_t)BB * CC * TT];
__device__ float g_qkv[(size_t)BB * COUT3 * TT];
__device__ __nv_bfloat16 g_xth[(size_t)BB * TP * CC];
__device__ __nv_bfloat16 g_xtl[(size_t)BB * TP * CC];
__device__ __nv_bfloat16 g_wth[(size_t)KQ * COUT3 * CC];
__device__ __nv_bfloat16 g_wtl[(size_t)KQ * COUT3 * CC];

__device__ __forceinline__ uint32_t smem_to_u32(const void* p) {
    uint32_t a;
    asm("{ .reg .u64 t; cvta.to.shared.u64 t, %1; cvt.u32.u64 %0, t; }" : "=r"(a) : "l"(p));
    return a;
}
#define LDSM4(r, addr) \
    asm volatile("ldmatrix.sync.aligned.m8n8.x4.shared.b16 {%0,%1,%2,%3}, [%4];" \
        : "=r"((r)[0]), "=r"((r)[1]), "=r"((r)[2]), "=r"((r)[3]) : "r"(addr))
#define LDSM4T(r, addr) \
    asm volatile("ldmatrix.sync.aligned.m8n8.x4.trans.shared.b16 {%0,%1,%2,%3}, [%4];" \
        : "=r"((r)[0]), "=r"((r)[1]), "=r"((r)[2]), "=r"((r)[3]) : "r"(addr))
#define MMA16816(d, a, b0, b1) \
    asm volatile("mma.sync.aligned.m16n8k16.row.col.f32.bf16.bf16.f32 " \
        "{%0,%1,%2,%3}, {%4,%5,%6,%7}, {%8,%9}, {%0,%1,%2,%3};" \
        : "+f"((d)[0]), "+f"((d)[1]), "+f"((d)[2]), "+f"((d)[3]) \
        : "r"((a)[0]), "r"((a)[1]), "r"((a)[2]), "r"((a)[3]), "r"(b0), "r"(b1))

__device__ __forceinline__ void split4(float4 v, uint2& ph, uint2& pl) {
    __nv_bfloat16 h0 = __float2bfloat16_rn(v.x), h1 = __float2bfloat16_rn(v.y);
    __nv_bfloat16 h2 = __float2bfloat16_rn(v.z), h3 = __float2bfloat16_rn(v.w);
    __nv_bfloat16 l0 = __float2bfloat16_rn(v.x - __bfloat162float(h0));
    __nv_bfloat16 l1 = __float2bfloat16_rn(v.y - __bfloat162float(h1));
    __nv_bfloat16 l2 = __float2bfloat16_rn(v.z - __bfloat162float(h2));
    __nv_bfloat16 l3 = __float2bfloat16_rn(v.w - __bfloat162float(h3));
    ph.x = (uint32_t)__bfloat16_as_ushort(h0) | ((uint32_t)__bfloat16_as_ushort(h1) << 16);
    ph.y = (uint32_t)__bfloat16_as_ushort(h2) | ((uint32_t)__bfloat16_as_ushort(h3) << 16);
    pl.x = (uint32_t)__bfloat16_as_ushort(l0) | ((uint32_t)__bfloat16_as_ushort(l1) << 16);
    pl.y = (uint32_t)__bfloat16_as_ushort(l2) | ((uint32_t)__bfloat16_as_ushort(l3) << 16);
}

// --------------------------- GroupNorm (unchanged) ---------------------------
__global__ void __launch_bounds__(256) gn_kernel(const float* __restrict__ x,
                                                 const float* __restrict__ gamma,
                                                 const float* __restrict__ beta) {
    int b = blockIdx.x / NG, g = blockIdx.x % NG;
    const float* xp = x + ((size_t)b * CC + g * CPG) * TT;
    float* op = g_xn + ((size_t)b * CC + g * CPG) * TT;
    int tid = threadIdx.x;
    const int N = CPG * TT;
    float s = 0.f, s2 = 0.f;
    const float4* xp4 = (const float4*)xp;
    for (int i = tid; i < N / 4; i += 256) {
        float4 v = xp4[i];
        s += v.x + v.y + v.z + v.w;
        s2 += v.x * v.x + v.y * v.y + v.z * v.z + v.w * v.w;
    }
    __shared__ float rs[256], rs2[256];
    rs[tid] = s; rs2[tid] = s2;
    __syncthreads();
    for (int st = 128; st > 0; st >>= 1) {
        if (tid < st) { rs[tid] += rs[tid + st]; rs2[tid] += rs2[tid + st]; }
        __syncthreads();
    }
    float mu = rs[0] / N;
    float rstd = rsqrtf(rs2[0] / N - mu * mu + 1e-5f);
    float4* op4 = (float4*)op;
    for (int i = tid; i < N / 4; i += 256) {
        int c = g * CPG + (i * 4) / TT;
        float ga = gamma[c] * rstd, be = beta[c] - mu * ga;
        float4 v = xp4[i];
        v.x = v.x * ga + be; v.y = v.y * ga + be;
        v.z = v.z * ga + be; v.w = v.w * ga + be;
        op4[i] = v;
    }
}

// ------------- zero pad rows of xt (unchanged) -------------------------------
__global__ void __launch_bounds__(256) zed_kernel() {
    int b = blockIdx.x;
    size_t base = (size_t)b * TP * CC;
    __nv_bfloat16 z = __float2bfloat16(0.f);
    for (int i = threadIdx.x; i < 32 * CC; i += 256) {
        int rr = i / CC, c = i % CC;
        int row = (rr < 15) ? rr : (4096 + rr);
        g_xth[base + (size_t)row * CC + c] = z;
        g_xtl[base + (size_t)row * CC + c] = z;
    }
}

// xt transform (unchanged)
__global__ void __launch_bounds__(256) xt_kernel() {
    __shared__ float s[64][65];
    int t0 = blockIdx.x * 64, c0 = blockIdx.y * 64, b = blockIdx.z;
    int tid = threadIdx.x;
    const float* xp = g_xn + ((size_t)b * CC + c0) * TT + t0;
#pragma unroll
    for (int p = 0; p < 16; p++) {
        int idx = tid + p * 256;
        s[idx >> 6][idx & 63] = xp[(size_t)(idx >> 6) * TT + (idx & 63)];
    }
    __syncthreads();
    int tl0 = tid >> 4, c4 = (tid & 15) * 4;
    size_t rb = (size_t)b * TP * CC;
#pragma unroll
    for (int p = 0; p < 4; p++) {
        int tl = tl0 + p * 16;
        int tp = t0 + tl + 15;
        float4 v = make_float4(s[c4 + 0][tl], s[c4 + 1][tl], s[c4 + 2][tl], s[c4 + 3][tl]);
        uint2 ph, pl;
        split4(v, ph, pl);
        size_t off = rb + (size_t)tp * CC + c0 + c4;
        *(uint2*)(g_xth + off) = ph;
        *(uint2*)(g_xtl + off) = pl;
    }
}

// wt transform (unchanged)
__global__ void __launch_bounds__(256) wt_kernel(const float* __restrict__ w) {
    __shared__ float s[KQ][129];
    int co = blockIdx.x, ci0 = blockIdx.y * 128;
    int tid = threadIdx.x;
    const float* wp = w + ((size_t)co * CC + ci0) * KQ;
#pragma unroll
    for (int p = 0; p < 16; p++) {
        int idx = tid + p * 256;
        s[idx & 31][idx >> 5] = wp[(size_t)(idx >> 5) * KQ + (idx & 31)];
    }
    __syncthreads();
#pragma unroll
    for (int p = 0; p < 16; p++) {
        int idx = tid + p * 256;
        int dk = idx >> 7, cil = idx & 127;
        float v = s[dk][cil];
        __nv_bfloat16 h = __float2bfloat16_rn(v);
        size_t off = ((size_t)dk * COUT3 + co) * CC + ci0 + cil;
        g_wth[off] = h;
        g_wtl[off] = __float2bfloat16_rn(v - __bfloat162float(h));
    }
}

// -------------- QKV conv warp-mma (unchanged, passing) -----------------------
#define PITCH 144
#define A_H 0
#define A_L 18432
#define B_H 36864
#define B_L 78336
#define QSMEM 119808

extern __shared__ char qsm[];

__global__ void __launch_bounds__(512, 1) qkvmma_kernel(const float* __restrict__ bias) {
    int t0 = blockIdx.x * 256, co0 = blockIdx.y * 128, b = blockIdx.z;
    int tid = threadIdx.x, wid = tid >> 5, lane = tid & 31;
    int co_w = (wid >> 2) * 32, t_w = (wid & 3) * 64;
    uint32_t sb = smem_to_u32(qsm);
    float acc[2][8][4] = {};

    for (int ch = 0; ch < 8; ch++) {
        int ci0 = ch * 64;
        __syncthreads();
        {
            const __nv_bfloat16* bh = g_xth + ((size_t)b * TP + t0) * CC + ci0;
            const __nv_bfloat16* bl = g_xtl + ((size_t)b * TP + t0) * CC + ci0;
            for (int i = tid; i < 287 * 8; i += 512) {
                int row = i >> 3, g = i & 7;
                size_t go = (size_t)row * CC + g * 8;
                *(uint4*)(qsm + B_H + row * PITCH + g * 16) = *(const uint4*)(bh + go);
                *(uint4*)(qsm + B_L + row * PITCH + g * 16) = *(const uint4*)(bl + go);
            }
        }
        for (int dk = 0; dk < 32; dk++) {
            __syncthreads();
            {
                const __nv_bfloat16* ah = g_wth + ((size_t)dk * COUT3 + co0) * CC + ci0;
                const __nv_bfloat16* al = g_wtl + ((size_t)dk * COUT3 + co0) * CC + ci0;
                for (int i = tid; i < 128 * 8; i += 512) {
                    int row = i >> 3, g = i & 7;
                    size_t go = (size_t)row * CC + g * 8;
                    *(uint4*)(qsm + A_H + row * PITCH + g * 16) = *(const uint4*)(ah + go);
                    *(uint4*)(qsm + A_L + row * PITCH + g * 16) = *(const uint4*)(al + go);
                }
            }
            __syncthreads();
            int mtx = lane >> 3, r8 = lane & 7;
#pragma unroll
            for (int ks = 0; ks < 4; ks++) {
                uint32_t a_h[2][4], a_l[2][4];
                int aoff = ((mtx & 1) * 8 + r8) * PITCH + ks * 32 + (mtx >> 1) * 16;
#pragma unroll
                for (int m = 0; m < 2; m++) {
                    uint32_t ad = sb + (co_w + m * 16) * PITCH + aoff;
                    LDSM4(a_h[m], ad + A_H);
                    LDSM4(a_l[m], ad + A_L);
                }
#pragma unroll
                for (int n = 0; n < 8; n++) {
                    int brow = t_w + n * 8 + (lane >> 2) + dk;
                    const char* bp = qsm + brow * PITCH + ks * 32 + (lane & 3) * 4;
                    uint32_t bh0 = *(const uint32_t*)(bp + B_H);
                    uint32_t bh1 = *(const uint32_t*)(bp + B_H + 16);
                    uint32_t bl0 = *(const uint32_t*)(bp + B_L);
                    uint32_t bl1 = *(const uint32_t*)(bp + B_L + 16);
                    MMA16816(acc[0][n], a_h[0], bh0, bh1);
                    MMA16816(acc[0][n], a_l[0], bh0, bh1);
                    MMA16816(acc[0][n], a_h[0], bl0, bl1);
                    MMA16816(acc[1][n], a_h[1], bh0, bh1);
                    MMA16816(acc[1][n], a_l[1], bh0, bh1);
                    MMA16816(acc[1][n], a_h[1], bl0, bl1);
                }
            }
        }
    }
#pragma unroll
    for (int m = 0; m < 2; m++) {
        int r0 = co_w + m * 16 + (lane >> 2);
        float bv0 = bias[co0 + r0];
        float bv1 = bias[co0 + r0 + 8];
        float* d0 = g_qkv + ((size_t)b * COUT3 + co0 + r0) * TT + t0;
        float* d1 = d0 + (size_t)8 * TT;
#pragma unroll
        for (int n = 0; n < 8; n++) {
            int cp = t_w + n * 8 + (lane & 3) * 2;
            float2 v0, v1;
            v0.x = acc[m][n][0] + bv0; v0.y = acc[m][n][1] + bv0;
            v1.x = acc[m][n][2] + bv1; v1.y = acc[m][n][3] + bv1;
            *(float2*)(d0 + cp) = v0;
            *(float2*)(d1 + cp) = v1;
        }
    }
}

// ---------------- Flash attention on tensor cores (bf16x3) -------------------
// CTA: 64 q x full K loop (64-chunks). 256 threads (8 warps).
// Tiles native [c][t] bf16 h/l, pitch 144B. S frags via ldmatrix.trans.
#define AT_QH 0
#define AT_QL 18432
#define AT_KH 36864
#define AT_KL 55296
#define AT_VH 73728
#define AT_VL 92160
#define AT_S  110592
#define AT_PH 127488
#define AT_PL 136704
#define AT_M  145920
#define AT_L  146176
#define AT_AL 146432
#define AT_RED 146688
#define ASMEM 147712

__global__ void __launch_bounds__(256, 1) attn2_kernel() {
    int q0 = blockIdx.x * 64;
    int bh = blockIdx.y;
    int b = bh / HEADS, hh = bh % HEADS;
    const float* qkv = g_qkv + (size_t)b * COUT3 * TT + (size_t)hh * (3 * HC) * TT;
    char* sm = qsm;
    uint32_t sb = smem_to_u32(sm);
    int tid = threadIdx.x, wid = tid >> 5, lane = tid & 31;
    int qw = (wid >> 2) * 32;     // q rows for this warp (S and PV)
    int kw = (wid & 3) * 16;      // S: k cols
    int cw = (wid & 3) * 32;      // PV: c cols
    int row = tid & 63, quad = tid >> 6;

    float* s_s = (float*)(sm + AT_S);        // [64][66]
    float* m_s = (float*)(sm + AT_M);
    float* l_s = (float*)(sm + AT_L);
    float* al_s = (float*)(sm + AT_AL);
    float* red = (float*)(sm + AT_RED);      // [64][4]

    const float scale = 0.0883883476483184f; // 128^-0.5 applied to Q
    // Q tile: [c=128][q 64], scaled, split
    for (int i = tid; i < 2048; i += 256) {
        int c = i >> 4, j4 = (i & 15) * 4;
        float4 v = *(const float4*)(qkv + (size_t)c * TT + q0 + j4);
        v.x *= scale; v.y *= scale; v.z *= scale; v.w *= scale;
        uint2 ph, pl;
        split4(v, ph, pl);
        *(uint2*)(sm + AT_QH + c * 144 + j4 * 2) = ph;
        *(uint2*)(sm + AT_QL + c * 144 + j4 * 2) = pl;
    }
    if (tid < 64) { m_s[tid] = -1e30f; l_s[tid] = 0.f; }

    float oacc[2][4][4] = {};
    __syncthreads();

    for (int kt = 0; kt < TT; kt += 64) {
        // K and V tiles: [c=128][64], split h/l
        for (int i = tid; i < 2048; i += 256) {
            int c = i >> 4, j4 = (i & 15) * 4;
            float4 kv4 = *(const float4*)(qkv + (size_t)(HC + c) * TT + kt + j4);
            uint2 ph, pl;
            split4(kv4, ph, pl);
            *(uint2*)(sm + AT_KH + c * 144 + j4 * 2) = ph;
            *(uint2*)(sm + AT_KL + c * 144 + j4 * 2) = pl;
            float4 vv4 = *(const float4*)(qkv + (size_t)(2 * HC + c) * TT + kt + j4);
            split4(vv4, ph, pl);
            *(uint2*)(sm + AT_VH + c * 144 + j4 * 2) = ph;
            *(uint2*)(sm + AT_VL + c * 144 + j4 * 2) = pl;
        }
        __syncthreads();

        // S = Q^T K: m=q(32/warp), n=k(16/warp), kk=c(128)
        float sacc[2][2][4] = {};
#pragma unroll
        for (int ks = 0; ks < 8; ks++) {
            int kk0 = ks * 16;
            // A frags (trans): row = kk0+(lane&7)+(lane>>4)*8, col = m0+((lane>>3)&1)*8
            int ar = kk0 + (lane & 7) + (lane >> 4) * 8;
            int acb = ((lane >> 3) & 1) * 16;
            uint32_t a_h[2][4], a_l[2][4];
#pragma unroll
            for (int m = 0; m < 2; m++) {
                uint32_t ad = sb + ar * 144 + (qw + m * 16) * 2 + acb;
                LDSM4T(a_h[m], ad + AT_QH);
                LDSM4T(a_l[m], ad + AT_QL);
            }
            // B frags (trans): row = kk0+(lane&7)+((lane>>3)&1)*8, col = kw+(lane>>4)*8
            int br = kk0 + (lane & 7) + ((lane >> 3) & 1) * 8;
            uint32_t bd = sb + br * 144 + kw * 2 + (lane >> 4) * 16;
            uint32_t b_h[4], b_l[4];
            LDSM4T(b_h, bd + AT_KH);
            LDSM4T(b_l, bd + AT_KL);
#pragma unroll
            for (int m = 0; m < 2; m++)
#pragma unroll
                for (int n = 0; n < 2; n++) {
                    MMA16816(sacc[m][n], a_h[m], b_h[2 * n], b_h[2 * n + 1]);
                    MMA16816(sacc[m][n], a_h[m], b_l[2 * n], b_l[2 * n + 1]);
                    MMA16816(sacc[m][n], a_l[m], b_h[2 * n], b_h[2 * n + 1]);
                }
        }
        // write S frags to smem fp32
#pragma unroll
        for (int m = 0; m < 2; m++) {
            int r0 = qw + m * 16 + (lane >> 2);
#pragma unroll
            for (int n = 0; n < 2; n++) {
                int c0 = kw + n * 8 + (lane & 3) * 2;
                s_s[r0 * 66 + c0] = sacc[m][n][0];
                s_s[r0 * 66 + c0 + 1] = sacc[m][n][1];
                s_s[(r0 + 8) * 66 + c0] = sacc[m][n][2];
                s_s[(r0 + 8) * 66 + c0 + 1] = sacc[m][n][3];
            }
        }
        __syncthreads();

        // softmax (fp32), P -> bf16 h/l
        float mx = -1e30f;
#pragma unroll
        for (int j = 0; j < 16; j++) mx = fmaxf(mx, s_s[row * 66 + quad * 16 + j]);
        red[row * 4 + quad] = mx;
        __syncthreads();
        if (tid < 64) {
            float m_old = m_s[tid];
            float mm = fmaxf(fmaxf(red[tid * 4], red[tid * 4 + 1]),
                             fmaxf(red[tid * 4 + 2], red[tid * 4 + 3]));
            float m_new = fmaxf(m_old, mm);
            al_s[tid] = __expf(m_old - m_new);
            m_s[tid] = m_new;
        }
        __syncthreads();
        {
            float m_new = m_s[row];
            float ssum = 0.f;
#pragma unroll
            for (int j = 0; j < 16; j += 2) {
                int cc0 = quad * 16 + j;
                float p0 = __expf(s_s[row * 66 + cc0] - m_new);
                float p1 = __expf(s_s[row * 66 + cc0 + 1] - m_new);
                ssum += p0 + p1;
                __nv_bfloat16 h0 = __float2bfloat16_rn(p0), h1 = __float2bfloat16_rn(p1);
                __nv_bfloat16 l0 = __float2bfloat16_rn(p0 - __bfloat162float(h0));
                __nv_bfloat16 l1 = __float2bfloat16_rn(p1 - __bfloat162float(h1));
                uint32_t ph = (uint32_t)__bfloat16_as_ushort(h0) |
                              ((uint32_t)__bfloat16_as_ushort(h1) << 16);
                uint32_t pl = (uint32_t)__bfloat16_as_ushort(l0) |
                              ((uint32_t)__bfloat16_as_ushort(l1) << 16);
                *(uint32_t*)(sm + AT_PH + row * 144 + cc0 * 2) = ph;
                *(uint32_t*)(sm + AT_PL + row * 144 + cc0 * 2) = pl;
            }
            red[row * 4 + quad] = ssum;
        }
        __syncthreads();
        if (tid < 64)
            l_s[tid] = l_s[tid] * al_s[tid] +
                       red[tid * 4] + red[tid * 4 + 1] + red[tid * 4 + 2] + red[tid * 4 + 3];
        __syncthreads();

        // rescale O by alpha
#pragma unroll
        for (int m = 0; m < 2; m++) {
            float a0 = al_s[qw + m * 16 + (lane >> 2)];
            float a1 = al_s[qw + m * 16 + 8 + (lane >> 2)];
#pragma unroll
            for (int n = 0; n < 4; n++) {
                oacc[m][n][0] *= a0; oacc[m][n][1] *= a0;
                oacc[m][n][2] *= a1; oacc[m][n][3] *= a1;
            }
        }
        // O += P V^T: m=q, n=c(32/warp), kk=k(64)
#pragma unroll
        for (int ks = 0; ks < 4; ks++) {
            int kk0 = ks * 16;
            // P a-frags (non-trans): row = m0+(lane&7)+((lane>>3)&1)*8, col = kk0+(lane>>4)*8
            int pr = (lane & 7) + ((lane >> 3) & 1) * 8;
            int pcb = kk0 * 2 + (lane >> 4) * 16;
            uint32_t pa_h[2][4], pa_l[2][4];
#pragma unroll
            for (int m = 0; m < 2; m++) {
                uint32_t ad = sb + (qw + m * 16 + pr) * 144 + pcb;
                LDSM4(pa_h[m], ad + AT_PH);
                LDSM4(pa_l[m], ad + AT_PL);
            }
            // V b-frags (non-trans): row = n0+(lane&7)+(lane>>4)*8, col = kk0+((lane>>3)&1)*8
            int vr = (lane & 7) + (lane >> 4) * 8;
            int vcb = kk0 * 2 + ((lane >> 3) & 1) * 16;
            uint32_t vb_h[2][4], vb_l[2][4];
#pragma unroll
            for (int nn = 0; nn < 2; nn++) {
                uint32_t vd = sb + (cw + nn * 16 + vr) * 144 + vcb;
                LDSM4(vb_h[nn], vd + AT_VH);
                LDSM4(vb_l[nn], vd + AT_VL);
            }
#pragma unroll
            for (int m = 0; m < 2; m++)
#pragma unroll
                for (int n = 0; n < 4; n++) {
                    int nn = n >> 1, o = (n & 1) * 2;
                    MMA16816(oacc[m][n], pa_h[m], vb_h[nn][o], vb_h[nn][o + 1]);
                    MMA16816(oacc[m][n], pa_h[m], vb_l[nn][o], vb_l[nn][o + 1]);
                    MMA16816(oacc[m][n], pa_l[m], vb_h[nn][o], vb_h[nn][o + 1]);
                }
        }
        __syncthreads();  // protect K/V/P/s_s before next iteration overwrites
    }

    // epilogue: O / l -> g_xn[(b*CC + hh*HC + c)][q0 + q]
#pragma unroll
    for (int m = 0; m < 2; m++) {
        int r0 = qw + m * 16 + (lane >> 2);
        float inv0 = 1.f / l_s[r0];
        float inv1 = 1.f / l_s[r0 + 8];
#pragma unroll
        for (int n = 0; n < 4; n++) {
            int c0 = cw + n * 8 + (lane & 3) * 2;
            float* base0 = g_xn + ((size_t)b * CC + hh * HC + c0) * TT + q0;
            base0[r0] = oacc[m][n][0] * inv0;
            base0[TT + r0] = oacc[m][n][1] * inv0;
            base0[r0 + 8] = oacc[m][n][2] * inv1;
            base0[TT + r0 + 8] = oacc[m][n][3] * inv1;
        }
    }
}

// --------------------------- Proj conv (unchanged) ---------------------------
#define PTM 64
#define PTN 128
__global__ void __launch_bounds__(256) proj_kernel(const float* __restrict__ w,
                                                   const float* __restrict__ bias,
                                                   const float* __restrict__ x,
                                                   float* __restrict__ out) {
    int t0 = blockIdx.x * PTN, co0 = blockIdx.y * PTM, b = blockIdx.z;
    __shared__ float w_s[KP][PTM];
    __shared__ float x_s[PTN + 8];
    int tid = threadIdx.x, tx = tid & 15, ty = tid >> 4;
    float acc[4][8] = {};
    const float* hb = g_xn + (size_t)b * CC * TT;
    for (int ci = 0; ci < CC; ci++) {
        __syncthreads();
        for (int i = tid; i < PTM * KP; i += 256)
            w_s[i % KP][i / KP] = w[(size_t)(co0 + i / KP) * (CC * KP) + ci * KP + i % KP];
        for (int i = tid; i < PTN + KP - 1; i += 256) {
            int tg = t0 - 2 + i;
            x_s[i] = (tg >= 0 && tg < TT) ? hb[(size_t)ci * TT + tg] : 0.f;
        }
        __syncthreads();
        float xv[12];
#pragma unroll
        for (int c = 0; c < 12; c++) xv[c] = x_s[tx * 8 + c];
#pragma unroll
        for (int dk = 0; dk < KP; dk++) {
            float wv[4];
#pragma unroll
            for (int r = 0; r < 4; r++) wv[r] = w_s[dk][ty * 4 + r];
#pragma unroll
            for (int r = 0; r < 4; r++)
#pragma unroll
                for (int c = 0; c < 8; c++) acc[r][c] += wv[r] * xv[c + dk];
        }
    }
#pragma unroll
    for (int r = 0; r < 4; r++) {
        int co = co0 + ty * 4 + r;
        float bv = bias[co];
        size_t base = ((size_t)b * CC + co) * TT + t0 + tx * 8;
#pragma unroll
        for (int c = 0; c < 8; c++) out[base + c] = acc[r][c] + bv + x[base + c];
    }
}

// -----------------------------------------------------------------------------
extern "C" void kernel_launch(void* const* d_in, const int* in_sizes, int n_in,
                              void* d_out, int out_size) {
    const float* x = (const float*)d_in[0];
    const float* gn_gamma = (const float*)d_in[1];
    const float* gn_beta = (const float*)d_in[2];
    const float* qkv_w = (const float*)d_in[3];
    const float* qkv_b = (const float*)d_in[4];
    const float* proj_w = (const float*)d_in[5];
    const float* proj_b = (const float*)d_in[6];
    float* out = (float*)d_out;

    cudaFuncSetAttribute(qkvmma_kernel, cudaFuncAttributeMaxDynamicSharedMemorySize, QSMEM);
    cudaFuncSetAttribute(attn2_kernel, cudaFuncAttributeMaxDynamicSharedMemorySize, ASMEM);

    gn_kernel<<<BB * NG, 256>>>(x, gn_gamma, gn_beta);
    zed_kernel<<<BB, 256>>>();
    xt_kernel<<<dim3(TT / 64, CC / 64, BB), 256>>>();
    wt_kernel<<<dim3(COUT3, CC / 128), 256>>>(qkv_w);
    qkvmma_kernel<<<dim3(TT / 256, COUT3 / 128, BB), 512, QSMEM>>>(qkv_b);
    attn2_kernel<<<dim3(TT / 64, BB * HEADS), 256, ASMEM>>>();
    proj_kernel<<<dim3(TT / PTN, CC / PTM, BB), 256>>>(proj_w, proj_b, x, out);
}

// round 13
// speedup vs baseline: 2.2389x; 1.1289x over previous
#include <cuda_runtime.h>
#include <cuda_bf16.h>
#include <cstdint>

#define BB 4
#define CC 512
#define TT 4096
#define TP 4128
#define NG 32
#define CPG 16
#define HEADS 4
#define HC 128
#define COUT3 1536
#define KQ 32
#define KP 5

__device__ float g_xn[(size_t)BB * CC * TT];
__device__ float g_qkv[(size_t)BB * COUT3 * TT];
__device__ __nv_bfloat16 g_xth[(size_t)BB * TP * CC];
__device__ __nv_bfloat16 g_xtl[(size_t)BB * TP * CC];
__device__ __nv_bfloat16 g_wth[(size_t)KQ * COUT3 * CC];
__device__ __nv_bfloat16 g_wtl[(size_t)KQ * COUT3 * CC];

__device__ __forceinline__ uint32_t smem_to_u32(const void* p) {
    uint32_t a;
    asm("{ .reg .u64 t; cvta.to.shared.u64 t, %1; cvt.u32.u64 %0, t; }" : "=r"(a) : "l"(p));
    return a;
}
#define LDSM4(r, addr) \
    asm volatile("ldmatrix.sync.aligned.m8n8.x4.shared.b16 {%0,%1,%2,%3}, [%4];" \
        : "=r"((r)[0]), "=r"((r)[1]), "=r"((r)[2]), "=r"((r)[3]) : "r"(addr))
#define LDSM4T(r, addr) \
    asm volatile("ldmatrix.sync.aligned.m8n8.x4.trans.shared.b16 {%0,%1,%2,%3}, [%4];" \
        : "=r"((r)[0]), "=r"((r)[1]), "=r"((r)[2]), "=r"((r)[3]) : "r"(addr))
#define MMA16816(d, a, b0, b1) \
    asm volatile("mma.sync.aligned.m16n8k16.row.col.f32.bf16.bf16.f32 " \
        "{%0,%1,%2,%3}, {%4,%5,%6,%7}, {%8,%9}, {%0,%1,%2,%3};" \
        : "+f"((d)[0]), "+f"((d)[1]), "+f"((d)[2]), "+f"((d)[3]) \
        : "r"((a)[0]), "r"((a)[1]), "r"((a)[2]), "r"((a)[3]), "r"(b0), "r"(b1))
#define CPASYNC16(dst, src) \
    asm volatile("cp.async.cg.shared.global [%0], [%1], 16;" :: "r"(dst), "l"(src))
#define CPCOMMIT() asm volatile("cp.async.commit_group;" ::: "memory")
#define CPWAIT0() asm volatile("cp.async.wait_group 0;" ::: "memory")

__device__ __forceinline__ void split4(float4 v, uint2& ph, uint2& pl) {
    __nv_bfloat16 h0 = __float2bfloat16_rn(v.x), h1 = __float2bfloat16_rn(v.y);
    __nv_bfloat16 h2 = __float2bfloat16_rn(v.z), h3 = __float2bfloat16_rn(v.w);
    __nv_bfloat16 l0 = __float2bfloat16_rn(v.x - __bfloat162float(h0));
    __nv_bfloat16 l1 = __float2bfloat16_rn(v.y - __bfloat162float(h1));
    __nv_bfloat16 l2 = __float2bfloat16_rn(v.z - __bfloat162float(h2));
    __nv_bfloat16 l3 = __float2bfloat16_rn(v.w - __bfloat162float(h3));
    ph.x = (uint32_t)__bfloat16_as_ushort(h0) | ((uint32_t)__bfloat16_as_ushort(h1) << 16);
    ph.y = (uint32_t)__bfloat16_as_ushort(h2) | ((uint32_t)__bfloat16_as_ushort(h3) << 16);
    pl.x = (uint32_t)__bfloat16_as_ushort(l0) | ((uint32_t)__bfloat16_as_ushort(l1) << 16);
    pl.y = (uint32_t)__bfloat16_as_ushort(l2) | ((uint32_t)__bfloat16_as_ushort(l3) << 16);
}

// --------------------------- GroupNorm ---------------------------
__global__ void __launch_bounds__(256) gn_kernel(const float* __restrict__ x,
                                                 const float* __restrict__ gamma,
                                                 const float* __restrict__ beta) {
    int b = blockIdx.x / NG, g = blockIdx.x % NG;
    const float* xp = x + ((size_t)b * CC + g * CPG) * TT;
    float* op = g_xn + ((size_t)b * CC + g * CPG) * TT;
    int tid = threadIdx.x;
    const int N = CPG * TT;
    float s = 0.f, s2 = 0.f;
    const float4* xp4 = (const float4*)xp;
    for (int i = tid; i < N / 4; i += 256) {
        float4 v = xp4[i];
        s += v.x + v.y + v.z + v.w;
        s2 += v.x * v.x + v.y * v.y + v.z * v.z + v.w * v.w;
    }
    __shared__ float rs[256], rs2[256];
    rs[tid] = s; rs2[tid] = s2;
    __syncthreads();
    for (int st = 128; st > 0; st >>= 1) {
        if (tid < st) { rs[tid] += rs[tid + st]; rs2[tid] += rs2[tid + st]; }
        __syncthreads();
    }
    float mu = rs[0] / N;
    float rstd = rsqrtf(rs2[0] / N - mu * mu + 1e-5f);
    float4* op4 = (float4*)op;
    for (int i = tid; i < N / 4; i += 256) {
        int c = g * CPG + (i * 4) / TT;
        float ga = gamma[c] * rstd, be = beta[c] - mu * ga;
        float4 v = xp4[i];
        v.x = v.x * ga + be; v.y = v.y * ga + be;
        v.z = v.z * ga + be; v.w = v.w * ga + be;
        op4[i] = v;
    }
}

// ------------- zero pad rows of xt -------------------------------
__global__ void __launch_bounds__(256) zed_kernel() {
    int b = blockIdx.x;
    size_t base = (size_t)b * TP * CC;
    __nv_bfloat16 z = __float2bfloat16(0.f);
    for (int i = threadIdx.x; i < 32 * CC; i += 256) {
        int rr = i / CC, c = i % CC;
        int row = (rr < 15) ? rr : (4096 + rr);
        g_xth[base + (size_t)row * CC + c] = z;
        g_xtl[base + (size_t)row * CC + c] = z;
    }
}

// xt transform
__global__ void __launch_bounds__(256) xt_kernel() {
    __shared__ float s[64][65];
    int t0 = blockIdx.x * 64, c0 = blockIdx.y * 64, b = blockIdx.z;
    int tid = threadIdx.x;
    const float* xp = g_xn + ((size_t)b * CC + c0) * TT + t0;
#pragma unroll
    for (int p = 0; p < 16; p++) {
        int idx = tid + p * 256;
        s[idx >> 6][idx & 63] = xp[(size_t)(idx >> 6) * TT + (idx & 63)];
    }
    __syncthreads();
    int tl0 = tid >> 4, c4 = (tid & 15) * 4;
    size_t rb = (size_t)b * TP * CC;
#pragma unroll
    for (int p = 0; p < 4; p++) {
        int tl = tl0 + p * 16;
        int tp = t0 + tl + 15;
        float4 v = make_float4(s[c4 + 0][tl], s[c4 + 1][tl], s[c4 + 2][tl], s[c4 + 3][tl]);
        uint2 ph, pl;
        split4(v, ph, pl);
        size_t off = rb + (size_t)tp * CC + c0 + c4;
        *(uint2*)(g_xth + off) = ph;
        *(uint2*)(g_xtl + off) = pl;
    }
}

// wt transform
__global__ void __launch_bounds__(256) wt_kernel(const float* __restrict__ w) {
    __shared__ float s[KQ][129];
    int co = blockIdx.x, ci0 = blockIdx.y * 128;
    int tid = threadIdx.x;
    const float* wp = w + ((size_t)co * CC + ci0) * KQ;
#pragma unroll
    for (int p = 0; p < 16; p++) {
        int idx = tid + p * 256;
        s[idx & 31][idx >> 5] = wp[(size_t)(idx >> 5) * KQ + (idx & 31)];
    }
    __syncthreads();
#pragma unroll
    for (int p = 0; p < 16; p++) {
        int idx = tid + p * 256;
        int dk = idx >> 7, cil = idx & 127;
        float v = s[dk][cil];
        __nv_bfloat16 h = __float2bfloat16_rn(v);
        size_t off = ((size_t)dk * COUT3 + co) * CC + ci0 + cil;
        g_wth[off] = h;
        g_wtl[off] = __float2bfloat16_rn(v - __bfloat162float(h));
    }
}

// -------------- QKV conv warp-mma, cp.async double-buffered A ----------------
#define PITCH 144
#define AB_STRIDE 36864
#define QB_H 73728
#define QB_L 115200
#define QSMEM 156672

extern __shared__ char qsm[];

__global__ void __launch_bounds__(512, 1) qkvmma_kernel(const float* __restrict__ bias) {
    int t0 = blockIdx.x * 256, co0 = blockIdx.y * 128, b = blockIdx.z;
    int tid = threadIdx.x, wid = tid >> 5, lane = tid & 31;
    int co_w = (wid >> 2) * 32, t_w = (wid & 3) * 64;
    uint32_t sb = smem_to_u32(qsm);
    float acc[2][8][4] = {};

    // prologue: prefetch A(s=0)
    {
        const __nv_bfloat16* ah = g_wth + (size_t)co0 * CC;
        const __nv_bfloat16* al = g_wtl + (size_t)co0 * CC;
        for (int i = tid; i < 2048; i += 512) {
            int part = i >> 10, j = i & 1023, row = j >> 3, g = j & 7;
            const __nv_bfloat16* src = (part ? al : ah) + (size_t)row * CC + g * 8;
            CPASYNC16(sb + part * 18432 + row * PITCH + g * 16, src);
        }
        CPCOMMIT();
    }

    for (int s = 0; s < 256; s++) {
        int ch = s >> 5, dk = s & 31, ci0 = ch * 64;
        if (dk == 0) {
            __syncthreads();  // all compute on old B done
            const __nv_bfloat16* bh = g_xth + ((size_t)b * TP + t0) * CC + ci0;
            const __nv_bfloat16* bl = g_xtl + ((size_t)b * TP + t0) * CC + ci0;
            for (int i = tid; i < 287 * 8; i += 512) {
                int row = i >> 3, g = i & 7;
                size_t go = (size_t)row * CC + g * 8;
                *(uint4*)(qsm + QB_H + row * PITCH + g * 16) = *(const uint4*)(bh + go);
                *(uint4*)(qsm + QB_L + row * PITCH + g * 16) = *(const uint4*)(bl + go);
            }
        }
        CPWAIT0();        // A(s) arrived (this thread's portion)
        __syncthreads();  // tile fully visible; compute(s-1) done in all warps

        if (s + 1 < 256) {  // prefetch A(s+1) into the other buffer
            int s1 = s + 1;
            int dk1 = s1 & 31, ci1 = (s1 >> 5) * 64;
            uint32_t ab = (uint32_t)(s1 & 1) * AB_STRIDE;
            const __nv_bfloat16* ah = g_wth + ((size_t)dk1 * COUT3 + co0) * CC + ci1;
            const __nv_bfloat16* al = g_wtl + ((size_t)dk1 * COUT3 + co0) * CC + ci1;
            for (int i = tid; i < 2048; i += 512) {
                int part = i >> 10, j = i & 1023, row = j >> 3, g = j & 7;
                const __nv_bfloat16* src = (part ? al : ah) + (size_t)row * CC + g * 8;
                CPASYNC16(sb + ab + part * 18432 + row * PITCH + g * 16, src);
            }
            CPCOMMIT();
        }

        // compute stage s on buffer s&1
        uint32_t abase = sb + (uint32_t)(s & 1) * AB_STRIDE;
        int mtx = lane >> 3, r8 = lane & 7;
        int vr = (lane & 7) + (lane >> 4) * 8;
        int vsel = ((lane >> 3) & 1) * 16;
#pragma unroll
        for (int ks = 0; ks < 4; ks++) {
            uint32_t a_h[2][4], a_l[2][4];
            int aoff = ((mtx & 1) * 8 + r8) * PITCH + ks * 32 + (mtx >> 1) * 16;
#pragma unroll
            for (int m = 0; m < 2; m++) {
                uint32_t ad = abase + (co_w + m * 16) * PITCH + aoff;
                LDSM4(a_h[m], ad);
                LDSM4(a_l[m], ad + 18432);
            }
            int vcb = ks * 32 + vsel;
#pragma unroll
            for (int nn = 0; nn < 4; nn++) {
                int brow = t_w + nn * 16 + vr + dk;
                uint32_t bd = sb + brow * PITCH + vcb;
                uint32_t b_h[4], b_l[4];
                LDSM4(b_h, bd + QB_H);
                LDSM4(b_l, bd + QB_L);
#pragma unroll
                for (int m = 0; m < 2; m++)
#pragma unroll
                    for (int j = 0; j < 2; j++) {
                        int n = nn * 2 + j, o = j * 2;
                        MMA16816(acc[m][n], a_h[m], b_h[o], b_h[o + 1]);
                        MMA16816(acc[m][n], a_l[m], b_h[o], b_h[o + 1]);
                        MMA16816(acc[m][n], a_h[m], b_l[o], b_l[o + 1]);
                    }
            }
        }
    }

    // epilogue
#pragma unroll
    for (int m = 0; m < 2; m++) {
        int r0 = co_w + m * 16 + (lane >> 2);
        float bv0 = bias[co0 + r0];
        float bv1 = bias[co0 + r0 + 8];
        float* d0 = g_qkv + ((size_t)b * COUT3 + co0 + r0) * TT + t0;
        float* d1 = d0 + (size_t)8 * TT;
#pragma unroll
        for (int n = 0; n < 8; n++) {
            int cp = t_w + n * 8 + (lane & 3) * 2;
            float2 v0, v1;
            v0.x = acc[m][n][0] + bv0; v0.y = acc[m][n][1] + bv0;
            v1.x = acc[m][n][2] + bv1; v1.y = acc[m][n][3] + bv1;
            *(float2*)(d0 + cp) = v0;
            *(float2*)(d1 + cp) = v1;
        }
    }
}

// ---------------- Flash attention on tensor cores (passing, unchanged) -------
#define AT_QH 0
#define AT_QL 18432
#define AT_KH 36864
#define AT_KL 55296
#define AT_VH 73728
#define AT_VL 92160
#define AT_S  110592
#define AT_PH 127488
#define AT_PL 136704
#define AT_M  145920
#define AT_L  146176
#define AT_AL 146432
#define AT_RED 146688
#define ASMEM 147712

__global__ void __launch_bounds__(256, 1) attn2_kernel() {
    int q0 = blockIdx.x * 64;
    int bh = blockIdx.y;
    int b = bh / HEADS, hh = bh % HEADS;
    const float* qkv = g_qkv + (size_t)b * COUT3 * TT + (size_t)hh * (3 * HC) * TT;
    char* sm = qsm;
    uint32_t sb = smem_to_u32(sm);
    int tid = threadIdx.x, wid = tid >> 5, lane = tid & 31;
    int qw = (wid >> 2) * 32;
    int kw = (wid & 3) * 16;
    int cw = (wid & 3) * 32;
    int row = tid & 63, quad = tid >> 6;

    float* s_s = (float*)(sm + AT_S);
    float* m_s = (float*)(sm + AT_M);
    float* l_s = (float*)(sm + AT_L);
    float* al_s = (float*)(sm + AT_AL);
    float* red = (float*)(sm + AT_RED);

    const float scale = 0.0883883476483184f;
    for (int i = tid; i < 2048; i += 256) {
        int c = i >> 4, j4 = (i & 15) * 4;
        float4 v = *(const float4*)(qkv + (size_t)c * TT + q0 + j4);
        v.x *= scale; v.y *= scale; v.z *= scale; v.w *= scale;
        uint2 ph, pl;
        split4(v, ph, pl);
        *(uint2*)(sm + AT_QH + c * 144 + j4 * 2) = ph;
        *(uint2*)(sm + AT_QL + c * 144 + j4 * 2) = pl;
    }
    if (tid < 64) { m_s[tid] = -1e30f; l_s[tid] = 0.f; }

    float oacc[2][4][4] = {};
    __syncthreads();

    for (int kt = 0; kt < TT; kt += 64) {
        for (int i = tid; i < 2048; i += 256) {
            int c = i >> 4, j4 = (i & 15) * 4;
            float4 kv4 = *(const float4*)(qkv + (size_t)(HC + c) * TT + kt + j4);
            uint2 ph, pl;
            split4(kv4, ph, pl);
            *(uint2*)(sm + AT_KH + c * 144 + j4 * 2) = ph;
            *(uint2*)(sm + AT_KL + c * 144 + j4 * 2) = pl;
            float4 vv4 = *(const float4*)(qkv + (size_t)(2 * HC + c) * TT + kt + j4);
            split4(vv4, ph, pl);
            *(uint2*)(sm + AT_VH + c * 144 + j4 * 2) = ph;
            *(uint2*)(sm + AT_VL + c * 144 + j4 * 2) = pl;
        }
        __syncthreads();

        float sacc[2][2][4] = {};
#pragma unroll
        for (int ks = 0; ks < 8; ks++) {
            int kk0 = ks * 16;
            int ar = kk0 + (lane & 7) + (lane >> 4) * 8;
            int acb = ((lane >> 3) & 1) * 16;
            uint32_t a_h[2][4], a_l[2][4];
#pragma unroll
            for (int m = 0; m < 2; m++) {
                uint32_t ad = sb + ar * 144 + (qw + m * 16) * 2 + acb;
                LDSM4T(a_h[m], ad + AT_QH);
                LDSM4T(a_l[m], ad + AT_QL);
            }
            int br = kk0 + (lane & 7) + ((lane >> 3) & 1) * 8;
            uint32_t bd = sb + br * 144 + kw * 2 + (lane >> 4) * 16;
            uint32_t b_h[4], b_l[4];
            LDSM4T(b_h, bd + AT_KH);
            LDSM4T(b_l, bd + AT_KL);
#pragma unroll
            for (int m = 0; m < 2; m++)
#pragma unroll
                for (int n = 0; n < 2; n++) {
                    MMA16816(sacc[m][n], a_h[m], b_h[2 * n], b_h[2 * n + 1]);
                    MMA16816(sacc[m][n], a_h[m], b_l[2 * n], b_l[2 * n + 1]);
                    MMA16816(sacc[m][n], a_l[m], b_h[2 * n], b_h[2 * n + 1]);
                }
        }
#pragma unroll
        for (int m = 0; m < 2; m++) {
            int r0 = qw + m * 16 + (lane >> 2);
#pragma unroll
            for (int n = 0; n < 2; n++) {
                int c0 = kw + n * 8 + (lane & 3) * 2;
                s_s[r0 * 66 + c0] = sacc[m][n][0];
                s_s[r0 * 66 + c0 + 1] = sacc[m][n][1];
                s_s[(r0 + 8) * 66 + c0] = sacc[m][n][2];
                s_s[(r0 + 8) * 66 + c0 + 1] = sacc[m][n][3];
            }
        }
        __syncthreads();

        float mx = -1e30f;
#pragma unroll
        for (int j = 0; j < 16; j++) mx = fmaxf(mx, s_s[row * 66 + quad * 16 + j]);
        red[row * 4 + quad] = mx;
        __syncthreads();
        if (tid < 64) {
            float m_old = m_s[tid];
            float mm = fmaxf(fmaxf(red[tid * 4], red[tid * 4 + 1]),
                             fmaxf(red[tid * 4 + 2], red[tid * 4 + 3]));
            float m_new = fmaxf(m_old, mm);
            al_s[tid] = __expf(m_old - m_new);
            m_s[tid] = m_new;
        }
        __syncthreads();
        {
            float m_new = m_s[row];
            float ssum = 0.f;
#pragma unroll
            for (int j = 0; j < 16; j += 2) {
                int cc0 = quad * 16 + j;
                float p0 = __expf(s_s[row * 66 + cc0] - m_new);
                float p1 = __expf(s_s[row * 66 + cc0 + 1] - m_new);
                ssum += p0 + p1;
                __nv_bfloat16 h0 = __float2bfloat16_rn(p0), h1 = __float2bfloat16_rn(p1);
                __nv_bfloat16 l0 = __float2bfloat16_rn(p0 - __bfloat162float(h0));
                __nv_bfloat16 l1 = __float2bfloat16_rn(p1 - __bfloat162float(h1));
                uint32_t ph = (uint32_t)__bfloat16_as_ushort(h0) |
                              ((uint32_t)__bfloat16_as_ushort(h1) << 16);
                uint32_t pl = (uint32_t)__bfloat16_as_ushort(l0) |
                              ((uint32_t)__bfloat16_as_ushort(l1) << 16);
                *(uint32_t*)(sm + AT_PH + row * 144 + cc0 * 2) = ph;
                *(uint32_t*)(sm + AT_PL + row * 144 + cc0 * 2) = pl;
            }
            red[row * 4 + quad] = ssum;
        }
        __syncthreads();
        if (tid < 64)
            l_s[tid] = l_s[tid] * al_s[tid] +
                       red[tid * 4] + red[tid * 4 + 1] + red[tid * 4 + 2] + red[tid * 4 + 3];
        __syncthreads();

#pragma unroll
        for (int m = 0; m < 2; m++) {
            float a0 = al_s[qw + m * 16 + (lane >> 2)];
            float a1 = al_s[qw + m * 16 + 8 + (lane >> 2)];
#pragma unroll
            for (int n = 0; n < 4; n++) {
                oacc[m][n][0] *= a0; oacc[m][n][1] *= a0;
                oacc[m][n][2] *= a1; oacc[m][n][3] *= a1;
            }
        }
#pragma unroll
        for (int ks = 0; ks < 4; ks++) {
            int kk0 = ks * 16;
            int pr = (lane & 7) + ((lane >> 3) & 1) * 8;
            int pcb = kk0 * 2 + (lane >> 4) * 16;
            uint32_t pa_h[2][4], pa_l[2][4];
#pragma unroll
            for (int m = 0; m < 2; m++) {
                uint32_t ad = sb + (qw + m * 16 + pr) * 144 + pcb;
                LDSM4(pa_h[m], ad + AT_PH);
                LDSM4(pa_l[m], ad + AT_PL);
            }
            int vr = (lane & 7) + (lane >> 4) * 8;
            int vcb = kk0 * 2 + ((lane >> 3) & 1) * 16;
            uint32_t vb_h[2][4], vb_l[2][4];
#pragma unroll
            for (int nn = 0; nn < 2; nn++) {
                uint32_t vd = sb + (cw + nn * 16 + vr) * 144 + vcb;
                LDSM4(vb_h[nn], vd + AT_VH);
                LDSM4(vb_l[nn], vd + AT_VL);
            }
#pragma unroll
            for (int m = 0; m < 2; m++)
#pragma unroll
                for (int n = 0; n < 4; n++) {
                    int nn = n >> 1, o = (n & 1) * 2;
                    MMA16816(oacc[m][n], pa_h[m], vb_h[nn][o], vb_h[nn][o + 1]);
                    MMA16816(oacc[m][n], pa_h[m], vb_l[nn][o], vb_l[nn][o + 1]);
                    MMA16816(oacc[m][n], pa_l[m], vb_h[nn][o], vb_h[nn][o + 1]);
                }
        }
        __syncthreads();
    }

#pragma unroll
    for (int m = 0; m < 2; m++) {
        int r0 = qw + m * 16 + (lane >> 2);
        float inv0 = 1.f / l_s[r0];
        float inv1 = 1.f / l_s[r0 + 8];
#pragma unroll
        for (int n = 0; n < 4; n++) {
            int c0 = cw + n * 8 + (lane & 3) * 2;
            float* base0 = g_xn + ((size_t)b * CC + hh * HC + c0) * TT + q0;
            base0[r0] = oacc[m][n][0] * inv0;
            base0[TT + r0] = oacc[m][n][1] * inv0;
            base0[r0 + 8] = oacc[m][n][2] * inv1;
            base0[TT + r0 + 8] = oacc[m][n][3] * inv1;
        }
    }
}

// --------------------------- Proj conv ---------------------------
#define PTM 64
#define PTN 128
__global__ void __launch_bounds__(256) proj_kernel(const float* __restrict__ w,
                                                   const float* __restrict__ bias,
                                                   const float* __restrict__ x,
                                                   float* __restrict__ out) {
    int t0 = blockIdx.x * PTN, co0 = blockIdx.y * PTM, b = blockIdx.z;
    __shared__ float w_s[KP][PTM];
    __shared__ float x_s[PTN + 8];
    int tid = threadIdx.x, tx = tid & 15, ty = tid >> 4;
    float acc[4][8] = {};
    const float* hb = g_xn + (size_t)b * CC * TT;
    for (int ci = 0; ci < CC; ci++) {
        __syncthreads();
        for (int i = tid; i < PTM * KP; i += 256)
            w_s[i % KP][i / KP] = w[(size_t)(co0 + i / KP) * (CC * KP) + ci * KP + i % KP];
        for (int i = tid; i < PTN + KP - 1; i += 256) {
            int tg = t0 - 2 + i;
            x_s[i] = (tg >= 0 && tg < TT) ? hb[(size_t)ci * TT + tg] : 0.f;
        }
        __syncthreads();
        float xv[12];
#pragma unroll
        for (int c = 0; c < 12; c++) xv[c] = x_s[tx * 8 + c];
#pragma unroll
        for (int dk = 0; dk < KP; dk++) {
            float wv[4];
#pragma unroll
            for (int r = 0; r < 4; r++) wv[r] = w_s[dk][ty * 4 + r];
#pragma unroll
            for (int r = 0; r < 4; r++)
#pragma unroll
                for (int c = 0; c < 8; c++) acc[r][c] += wv[r] * xv[c + dk];
        }
    }
#pragma unroll
    for (int r = 0; r < 4; r++) {
        int co = co0 + ty * 4 + r;
        float bv = bias[co];
        size_t base = ((size_t)b * CC + co) * TT + t0 + tx * 8;
#pragma unroll
        for (int c = 0; c < 8; c++) out[base + c] = acc[r][c] + bv + x[base + c];
    }
}

// -----------------------------------------------------------------------------
extern "C" void kernel_launch(void* const* d_in, const int* in_sizes, int n_in,
                              void* d_out, int out_size) {
    const float* x = (const float*)d_in[0];
    const float* gn_gamma = (const float*)d_in[1];
    const float* gn_beta = (const float*)d_in[2];
    const float* qkv_w = (const float*)d_in[3];
    const float* qkv_b = (const float*)d_in[4];
    const float* proj_w = (const float*)d_in[5];
    const float* proj_b = (const float*)d_in[6];
    float* out = (float*)d_out;

    cudaFuncSetAttribute(qkvmma_kernel, cudaFuncAttributeMaxDynamicSharedMemorySize, QSMEM);
    cudaFuncSetAttribute(attn2_kernel, cudaFuncAttributeMaxDynamicSharedMemorySize, ASMEM);

    gn_kernel<<<BB * NG, 256>>>(x, gn_gamma, gn_beta);
    zed_kernel<<<BB, 256>>>();
    xt_kernel<<<dim3(TT / 64, CC / 64, BB), 256>>>();
    wt_kernel<<<dim3(COUT3, CC / 128), 256>>>(qkv_w);
    qkvmma_kernel<<<dim3(TT / 256, COUT3 / 128, BB), 512, QSMEM>>>(qkv_b);
    attn2_kernel<<<dim3(TT / 64, BB * HEADS), 256, ASMEM>>>();
    proj_kernel<<<dim3(TT / PTN, CC / PTM, BB), 256>>>(proj_w, proj_b, x, out);
}

// round 14
// speedup vs baseline: 2.6226x; 1.1714x over previous
#include <cuda_runtime.h>
#include <cuda_bf16.h>
#include <cstdint>

#define BB 4
#define CC 512
#define TT 4096
#define TP 4128
#define NG 32
#define CPG 16
#define HEADS 4
#define HC 128
#define COUT3 1536
#define KQ 32
#define KP 5

__device__ float g_xn[(size_t)BB * CC * TT];
__device__ float g_qkv[(size_t)BB * COUT3 * TT];
__device__ __nv_bfloat16 g_xth[(size_t)BB * TP * CC];   // qkv input, later attn out (pad 2)
__device__ __nv_bfloat16 g_xtl[(size_t)BB * TP * CC];
__device__ __nv_bfloat16 g_wth[(size_t)KQ * COUT3 * CC];
__device__ __nv_bfloat16 g_wtl[(size_t)KQ * COUT3 * CC];
__device__ __nv_bfloat16 g_w2h[(size_t)KP * CC * CC];   // proj weights [dk][co][ci]
__device__ __nv_bfloat16 g_w2l[(size_t)KP * CC * CC];

__device__ __forceinline__ uint32_t smem_to_u32(const void* p) {
    uint32_t a;
    asm("{ .reg .u64 t; cvta.to.shared.u64 t, %1; cvt.u32.u64 %0, t; }" : "=r"(a) : "l"(p));
    return a;
}
#define LDSM4(r, addr) \
    asm volatile("ldmatrix.sync.aligned.m8n8.x4.shared.b16 {%0,%1,%2,%3}, [%4];" \
        : "=r"((r)[0]), "=r"((r)[1]), "=r"((r)[2]), "=r"((r)[3]) : "r"(addr))
#define LDSM4T(r, addr) \
    asm volatile("ldmatrix.sync.aligned.m8n8.x4.trans.shared.b16 {%0,%1,%2,%3}, [%4];" \
        : "=r"((r)[0]), "=r"((r)[1]), "=r"((r)[2]), "=r"((r)[3]) : "r"(addr))
#define MMA16816(d, a, b0, b1) \
    asm volatile("mma.sync.aligned.m16n8k16.row.col.f32.bf16.bf16.f32 " \
        "{%0,%1,%2,%3}, {%4,%5,%6,%7}, {%8,%9}, {%0,%1,%2,%3};" \
        : "+f"((d)[0]), "+f"((d)[1]), "+f"((d)[2]), "+f"((d)[3]) \
        : "r"((a)[0]), "r"((a)[1]), "r"((a)[2]), "r"((a)[3]), "r"(b0), "r"(b1))
#define CPASYNC16(dst, src) \
    asm volatile("cp.async.cg.shared.global [%0], [%1], 16;" :: "r"(dst), "l"(src))
#define CPCOMMIT() asm volatile("cp.async.commit_group;" ::: "memory")
#define CPWAIT0() asm volatile("cp.async.wait_group 0;" ::: "memory")

__device__ __forceinline__ void split4(float4 v, uint2& ph, uint2& pl) {
    __nv_bfloat16 h0 = __float2bfloat16_rn(v.x), h1 = __float2bfloat16_rn(v.y);
    __nv_bfloat16 h2 = __float2bfloat16_rn(v.z), h3 = __float2bfloat16_rn(v.w);
    __nv_bfloat16 l0 = __float2bfloat16_rn(v.x - __bfloat162float(h0));
    __nv_bfloat16 l1 = __float2bfloat16_rn(v.y - __bfloat162float(h1));
    __nv_bfloat16 l2 = __float2bfloat16_rn(v.z - __bfloat162float(h2));
    __nv_bfloat16 l3 = __float2bfloat16_rn(v.w - __bfloat162float(h3));
    ph.x = (uint32_t)__bfloat16_as_ushort(h0) | ((uint32_t)__bfloat16_as_ushort(h1) << 16);
    ph.y = (uint32_t)__bfloat16_as_ushort(h2) | ((uint32_t)__bfloat16_as_ushort(h3) << 16);
    pl.x = (uint32_t)__bfloat16_as_ushort(l0) | ((uint32_t)__bfloat16_as_ushort(l1) << 16);
    pl.y = (uint32_t)__bfloat16_as_ushort(l2) | ((uint32_t)__bfloat16_as_ushort(l3) << 16);
}
__device__ __forceinline__ void pack2(float a, float b, uint32_t& h, uint32_t& l) {
    __nv_bfloat16 ha = __float2bfloat16_rn(a), hb = __float2bfloat16_rn(b);
    __nv_bfloat16 la = __float2bfloat16_rn(a - __bfloat162float(ha));
    __nv_bfloat16 lb = __float2bfloat16_rn(b - __bfloat162float(hb));
    h = (uint32_t)__bfloat16_as_ushort(ha) | ((uint32_t)__bfloat16_as_ushort(hb) << 16);
    l = (uint32_t)__bfloat16_as_ushort(la) | ((uint32_t)__bfloat16_as_ushort(lb) << 16);
}

// --------------------------- GroupNorm ---------------------------
__global__ void __launch_bounds__(256) gn_kernel(const float* __restrict__ x,
                                                 const float* __restrict__ gamma,
                                                 const float* __restrict__ beta) {
    int b = blockIdx.x / NG, g = blockIdx.x % NG;
    const float* xp = x + ((size_t)b * CC + g * CPG) * TT;
    float* op = g_xn + ((size_t)b * CC + g * CPG) * TT;
    int tid = threadIdx.x;
    const int N = CPG * TT;
    float s = 0.f, s2 = 0.f;
    const float4* xp4 = (const float4*)xp;
    for (int i = tid; i < N / 4; i += 256) {
        float4 v = xp4[i];
        s += v.x + v.y + v.z + v.w;
        s2 += v.x * v.x + v.y * v.y + v.z * v.z + v.w * v.w;
    }
    __shared__ float rs[256], rs2[256];
    rs[tid] = s; rs2[tid] = s2;
    __syncthreads();
    for (int st = 128; st > 0; st >>= 1) {
        if (tid < st) { rs[tid] += rs[tid + st]; rs2[tid] += rs2[tid + st]; }
        __syncthreads();
    }
    float mu = rs[0] / N;
    float rstd = rsqrtf(rs2[0] / N - mu * mu + 1e-5f);
    float4* op4 = (float4*)op;
    for (int i = tid; i < N / 4; i += 256) {
        int c = g * CPG + (i * 4) / TT;
        float ga = gamma[c] * rstd, be = beta[c] - mu * ga;
        float4 v = xp4[i];
        v.x = v.x * ga + be; v.y = v.y * ga + be;
        v.z = v.z * ga + be; v.w = v.w * ga + be;
        op4[i] = v;
    }
}

// ------------- zero pad rows of xt (qkv input, pad 15) -----------------------
__global__ void __launch_bounds__(256) zed_kernel() {
    int b = blockIdx.x;
    size_t base = (size_t)b * TP * CC;
    __nv_bfloat16 z = __float2bfloat16(0.f);
    for (int i = threadIdx.x; i < 32 * CC; i += 256) {
        int rr = i / CC, c = i % CC;
        int row = (rr < 15) ? rr : (4096 + rr);
        g_xth[base + (size_t)row * CC + c] = z;
        g_xtl[base + (size_t)row * CC + c] = z;
    }
}

// ------------- zero pad rows for attn output (pad 2): rows {0,1, 4098..4103} -
__global__ void __launch_bounds__(256) zed2_kernel() {
    int b = blockIdx.x;
    size_t base = (size_t)b * TP * CC;
    __nv_bfloat16 z = __float2bfloat16(0.f);
    for (int i = threadIdx.x; i < 8 * CC; i += 256) {
        int rr = i / CC, c = i % CC;
        int row = (rr < 2) ? rr : (4096 + rr);
        g_xth[base + (size_t)row * CC + c] = z;
        g_xtl[base + (size_t)row * CC + c] = z;
    }
}

// xt transform (pad 15)
__global__ void __launch_bounds__(256) xt_kernel() {
    __shared__ float s[64][65];
    int t0 = blockIdx.x * 64, c0 = blockIdx.y * 64, b = blockIdx.z;
    int tid = threadIdx.x;
    const float* xp = g_xn + ((size_t)b * CC + c0) * TT + t0;
#pragma unroll
    for (int p = 0; p < 16; p++) {
        int idx = tid + p * 256;
        s[idx >> 6][idx & 63] = xp[(size_t)(idx >> 6) * TT + (idx & 63)];
    }
    __syncthreads();
    int tl0 = tid >> 4, c4 = (tid & 15) * 4;
    size_t rb = (size_t)b * TP * CC;
#pragma unroll
    for (int p = 0; p < 4; p++) {
        int tl = tl0 + p * 16;
        int tp = t0 + tl + 15;
        float4 v = make_float4(s[c4 + 0][tl], s[c4 + 1][tl], s[c4 + 2][tl], s[c4 + 3][tl]);
        uint2 ph, pl;
        split4(v, ph, pl);
        size_t off = rb + (size_t)tp * CC + c0 + c4;
        *(uint2*)(g_xth + off) = ph;
        *(uint2*)(g_xtl + off) = pl;
    }
}

// wt transform (qkv weights)
__global__ void __launch_bounds__(256) wt_kernel(const float* __restrict__ w) {
    __shared__ float s[KQ][129];
    int co = blockIdx.x, ci0 = blockIdx.y * 128;
    int tid = threadIdx.x;
    const float* wp = w + ((size_t)co * CC + ci0) * KQ;
#pragma unroll
    for (int p = 0; p < 16; p++) {
        int idx = tid + p * 256;
        s[idx & 31][idx >> 5] = wp[(size_t)(idx >> 5) * KQ + (idx & 31)];
    }
    __syncthreads();
#pragma unroll
    for (int p = 0; p < 16; p++) {
        int idx = tid + p * 256;
        int dk = idx >> 7, cil = idx & 127;
        float v = s[dk][cil];
        __nv_bfloat16 h = __float2bfloat16_rn(v);
        size_t off = ((size_t)dk * COUT3 + co) * CC + ci0 + cil;
        g_wth[off] = h;
        g_wtl[off] = __float2bfloat16_rn(v - __bfloat162float(h));
    }
}

// wt2 transform (proj weights): w [co][ci][5] -> [dk][co][ci] bf16 h/l
__global__ void __launch_bounds__(256) wt2_kernel(const float* __restrict__ w) {
    __shared__ float s[KP][129];
    int co = blockIdx.x, ci0 = blockIdx.y * 128;
    int tid = threadIdx.x;
    const float* wp = w + ((size_t)co * CC + ci0) * KP;
    for (int idx = tid; idx < 128 * KP; idx += 256)
        s[idx % KP][idx / KP] = wp[(size_t)(idx / KP) * KP + idx % KP];
    __syncthreads();
    for (int idx = tid; idx < KP * 128; idx += 256) {
        int dk = idx / 128, cil = idx % 128;
        float v = s[dk][cil];
        __nv_bfloat16 h = __float2bfloat16_rn(v);
        size_t off = ((size_t)dk * CC + co) * CC + ci0 + cil;
        g_w2h[off] = h;
        g_w2l[off] = __float2bfloat16_rn(v - __bfloat162float(h));
    }
}

// -------------- QKV conv warp-mma (passing, unchanged) -----------------------
#define PITCH 144
#define AB_STRIDE 36864
#define QB_H 73728
#define QB_L 115200
#define QSMEM 156672

extern __shared__ char qsm[];

__global__ void __launch_bounds__(512, 1) qkvmma_kernel(const float* __restrict__ bias) {
    int t0 = blockIdx.x * 256, co0 = blockIdx.y * 128, b = blockIdx.z;
    int tid = threadIdx.x, wid = tid >> 5, lane = tid & 31;
    int co_w = (wid >> 2) * 32, t_w = (wid & 3) * 64;
    uint32_t sb = smem_to_u32(qsm);
    float acc[2][8][4] = {};

    {
        const __nv_bfloat16* ah = g_wth + (size_t)co0 * CC;
        const __nv_bfloat16* al = g_wtl + (size_t)co0 * CC;
        for (int i = tid; i < 2048; i += 512) {
            int part = i >> 10, j = i & 1023, row = j >> 3, g = j & 7;
            const __nv_bfloat16* src = (part ? al : ah) + (size_t)row * CC + g * 8;
            CPASYNC16(sb + part * 18432 + row * PITCH + g * 16, src);
        }
        CPCOMMIT();
    }

    for (int s = 0; s < 256; s++) {
        int ch = s >> 5, dk = s & 31, ci0 = ch * 64;
        if (dk == 0) {
            __syncthreads();
            const __nv_bfloat16* bh = g_xth + ((size_t)b * TP + t0) * CC + ci0;
            const __nv_bfloat16* bl = g_xtl + ((size_t)b * TP + t0) * CC + ci0;
            for (int i = tid; i < 287 * 8; i += 512) {
                int row = i >> 3, g = i & 7;
                size_t go = (size_t)row * CC + g * 8;
                *(uint4*)(qsm + QB_H + row * PITCH + g * 16) = *(const uint4*)(bh + go);
                *(uint4*)(qsm + QB_L + row * PITCH + g * 16) = *(const uint4*)(bl + go);
            }
        }
        CPWAIT0();
        __syncthreads();

        if (s + 1 < 256) {
            int s1 = s + 1;
            int dk1 = s1 & 31, ci1 = (s1 >> 5) * 64;
            uint32_t ab = (uint32_t)(s1 & 1) * AB_STRIDE;
            const __nv_bfloat16* ah = g_wth + ((size_t)dk1 * COUT3 + co0) * CC + ci1;
            const __nv_bfloat16* al = g_wtl + ((size_t)dk1 * COUT3 + co0) * CC + ci1;
            for (int i = tid; i < 2048; i += 512) {
                int part = i >> 10, j = i & 1023, row = j >> 3, g = j & 7;
                const __nv_bfloat16* src = (part ? al : ah) + (size_t)row * CC + g * 8;
                CPASYNC16(sb + ab + part * 18432 + row * PITCH + g * 16, src);
            }
            CPCOMMIT();
        }

        uint32_t abase = sb + (uint32_t)(s & 1) * AB_STRIDE;
        int mtx = lane >> 3, r8 = lane & 7;
        int vr = (lane & 7) + (lane >> 4) * 8;
        int vsel = ((lane >> 3) & 1) * 16;
#pragma unroll
        for (int ks = 0; ks < 4; ks++) {
            uint32_t a_h[2][4], a_l[2][4];
            int aoff = ((mtx & 1) * 8 + r8) * PITCH + ks * 32 + (mtx >> 1) * 16;
#pragma unroll
            for (int m = 0; m < 2; m++) {
                uint32_t ad = abase + (co_w + m * 16) * PITCH + aoff;
                LDSM4(a_h[m], ad);
                LDSM4(a_l[m], ad + 18432);
            }
            int vcb = ks * 32 + vsel;
#pragma unroll
            for (int nn = 0; nn < 4; nn++) {
                int brow = t_w + nn * 16 + vr + dk;
                uint32_t bd = sb + brow * PITCH + vcb;
                uint32_t b_h[4], b_l[4];
                LDSM4(b_h, bd + QB_H);
                LDSM4(b_l, bd + QB_L);
#pragma unroll
                for (int m = 0; m < 2; m++)
#pragma unroll
                    for (int j = 0; j < 2; j++) {
                        int n = nn * 2 + j, o = j * 2;
                        MMA16816(acc[m][n], a_h[m], b_h[o], b_h[o + 1]);
                        MMA16816(acc[m][n], a_l[m], b_h[o], b_h[o + 1]);
                        MMA16816(acc[m][n], a_h[m], b_l[o], b_l[o + 1]);
                    }
            }
        }
    }

#pragma unroll
    for (int m = 0; m < 2; m++) {
        int r0 = co_w + m * 16 + (lane >> 2);
        float bv0 = bias[co0 + r0];
        float bv1 = bias[co0 + r0 + 8];
        float* d0 = g_qkv + ((size_t)b * COUT3 + co0 + r0) * TT + t0;
        float* d1 = d0 + (size_t)8 * TT;
#pragma unroll
        for (int n = 0; n < 8; n++) {
            int cp = t_w + n * 8 + (lane & 3) * 2;
            float2 v0, v1;
            v0.x = acc[m][n][0] + bv0; v0.y = acc[m][n][1] + bv0;
            v1.x = acc[m][n][2] + bv1; v1.y = acc[m][n][3] + bv1;
            *(float2*)(d0 + cp) = v0;
            *(float2*)(d1 + cp) = v1;
        }
    }
}

// ---------------- Flash attention (epilogue now writes bf16 h/l transposed) --
#define AT_QH 0
#define AT_QL 18432
#define AT_KH 36864
#define AT_KL 55296
#define AT_VH 73728
#define AT_VL 92160
#define AT_S  110592
#define AT_PH 127488
#define AT_PL 136704
#define AT_M  145920
#define AT_L  146176
#define AT_AL 146432
#define AT_RED 146688
#define ASMEM 147712

__global__ void __launch_bounds__(256, 1) attn2_kernel() {
    int q0 = blockIdx.x * 64;
    int bh = blockIdx.y;
    int b = bh / HEADS, hh = bh % HEADS;
    const float* qkv = g_qkv + (size_t)b * COUT3 * TT + (size_t)hh * (3 * HC) * TT;
    char* sm = qsm;
    uint32_t sb = smem_to_u32(sm);
    int tid = threadIdx.x, wid = tid >> 5, lane = tid & 31;
    int qw = (wid >> 2) * 32;
    int kw = (wid & 3) * 16;
    int cw = (wid & 3) * 32;
    int row = tid & 63, quad = tid >> 6;

    float* s_s = (float*)(sm + AT_S);
    float* m_s = (float*)(sm + AT_M);
    float* l_s = (float*)(sm + AT_L);
    float* al_s = (float*)(sm + AT_AL);
    float* red = (float*)(sm + AT_RED);

    const float scale = 0.0883883476483184f;
    for (int i = tid; i < 2048; i += 256) {
        int c = i >> 4, j4 = (i & 15) * 4;
        float4 v = *(const float4*)(qkv + (size_t)c * TT + q0 + j4);
        v.x *= scale; v.y *= scale; v.z *= scale; v.w *= scale;
        uint2 ph, pl;
        split4(v, ph, pl);
        *(uint2*)(sm + AT_QH + c * 144 + j4 * 2) = ph;
        *(uint2*)(sm + AT_QL + c * 144 + j4 * 2) = pl;
    }
    if (tid < 64) { m_s[tid] = -1e30f; l_s[tid] = 0.f; }

    float oacc[2][4][4] = {};
    __syncthreads();

    for (int kt = 0; kt < TT; kt += 64) {
        for (int i = tid; i < 2048; i += 256) {
            int c = i >> 4, j4 = (i & 15) * 4;
            float4 kv4 = *(const float4*)(qkv + (size_t)(HC + c) * TT + kt + j4);
            uint2 ph, pl;
            split4(kv4, ph, pl);
            *(uint2*)(sm + AT_KH + c * 144 + j4 * 2) = ph;
            *(uint2*)(sm + AT_KL + c * 144 + j4 * 2) = pl;
            float4 vv4 = *(const float4*)(qkv + (size_t)(2 * HC + c) * TT + kt + j4);
            split4(vv4, ph, pl);
            *(uint2*)(sm + AT_VH + c * 144 + j4 * 2) = ph;
            *(uint2*)(sm + AT_VL + c * 144 + j4 * 2) = pl;
        }
        __syncthreads();

        float sacc[2][2][4] = {};
#pragma unroll
        for (int ks = 0; ks < 8; ks++) {
            int kk0 = ks * 16;
            int ar = kk0 + (lane & 7) + (lane >> 4) * 8;
            int acb = ((lane >> 3) & 1) * 16;
            uint32_t a_h[2][4], a_l[2][4];
#pragma unroll
            for (int m = 0; m < 2; m++) {
                uint32_t ad = sb + ar * 144 + (qw + m * 16) * 2 + acb;
                LDSM4T(a_h[m], ad + AT_QH);
                LDSM4T(a_l[m], ad + AT_QL);
            }
            int br = kk0 + (lane & 7) + ((lane >> 3) & 1) * 8;
            uint32_t bd = sb + br * 144 + kw * 2 + (lane >> 4) * 16;
            uint32_t b_h[4], b_l[4];
            LDSM4T(b_h, bd + AT_KH);
            LDSM4T(b_l, bd + AT_KL);
#pragma unroll
            for (int m = 0; m < 2; m++)
#pragma unroll
                for (int n = 0; n < 2; n++) {
                    MMA16816(sacc[m][n], a_h[m], b_h[2 * n], b_h[2 * n + 1]);
                    MMA16816(sacc[m][n], a_h[m], b_l[2 * n], b_l[2 * n + 1]);
                    MMA16816(sacc[m][n], a_l[m], b_h[2 * n], b_h[2 * n + 1]);
                }
        }
#pragma unroll
        for (int m = 0; m < 2; m++) {
            int r0 = qw + m * 16 + (lane >> 2);
#pragma unroll
            for (int n = 0; n < 2; n++) {
                int c0 = kw + n * 8 + (lane & 3) * 2;
                s_s[r0 * 66 + c0] = sacc[m][n][0];
                s_s[r0 * 66 + c0 + 1] = sacc[m][n][1];
                s_s[(r0 + 8) * 66 + c0] = sacc[m][n][2];
                s_s[(r0 + 8) * 66 + c0 + 1] = sacc[m][n][3];
            }
        }
        __syncthreads();

        float mx = -1e30f;
#pragma unroll
        for (int j = 0; j < 16; j++) mx = fmaxf(mx, s_s[row * 66 + quad * 16 + j]);
        red[row * 4 + quad] = mx;
        __syncthreads();
        if (tid < 64) {
            float m_old = m_s[tid];
            float mm = fmaxf(fmaxf(red[tid * 4], red[tid * 4 + 1]),
                             fmaxf(red[tid * 4 + 2], red[tid * 4 + 3]));
            float m_new = fmaxf(m_old, mm);
            al_s[tid] = __expf(m_old - m_new);
            m_s[tid] = m_new;
        }
        __syncthreads();
        {
            float m_new = m_s[row];
            float ssum = 0.f;
#pragma unroll
            for (int j = 0; j < 16; j += 2) {
                int cc0 = quad * 16 + j;
                float p0 = __expf(s_s[row * 66 + cc0] - m_new);
                float p1 = __expf(s_s[row * 66 + cc0 + 1] - m_new);
                ssum += p0 + p1;
                uint32_t ph, pl;
                pack2(p0, p1, ph, pl);
                *(uint32_t*)(sm + AT_PH + row * 144 + cc0 * 2) = ph;
                *(uint32_t*)(sm + AT_PL + row * 144 + cc0 * 2) = pl;
            }
            red[row * 4 + quad] = ssum;
        }
        __syncthreads();
        if (tid < 64)
            l_s[tid] = l_s[tid] * al_s[tid] +
                       red[tid * 4] + red[tid * 4 + 1] + red[tid * 4 + 2] + red[tid * 4 + 3];
        __syncthreads();

#pragma unroll
        for (int m = 0; m < 2; m++) {
            float a0 = al_s[qw + m * 16 + (lane >> 2)];
            float a1 = al_s[qw + m * 16 + 8 + (lane >> 2)];
#pragma unroll
            for (int n = 0; n < 4; n++) {
                oacc[m][n][0] *= a0; oacc[m][n][1] *= a0;
                oacc[m][n][2] *= a1; oacc[m][n][3] *= a1;
            }
        }
#pragma unroll
        for (int ks = 0; ks < 4; ks++) {
            int kk0 = ks * 16;
            int pr = (lane & 7) + ((lane >> 3) & 1) * 8;
            int pcb = kk0 * 2 + (lane >> 4) * 16;
            uint32_t pa_h[2][4], pa_l[2][4];
#pragma unroll
            for (int m = 0; m < 2; m++) {
                uint32_t ad = sb + (qw + m * 16 + pr) * 144 + pcb;
                LDSM4(pa_h[m], ad + AT_PH);
                LDSM4(pa_l[m], ad + AT_PL);
            }
            int vr = (lane & 7) + (lane >> 4) * 8;
            int vcb = kk0 * 2 + ((lane >> 3) & 1) * 16;
            uint32_t vb_h[2][4], vb_l[2][4];
#pragma unroll
            for (int nn = 0; nn < 2; nn++) {
                uint32_t vd = sb + (cw + nn * 16 + vr) * 144 + vcb;
                LDSM4(vb_h[nn], vd + AT_VH);
                LDSM4(vb_l[nn], vd + AT_VL);
            }
#pragma unroll
            for (int m = 0; m < 2; m++)
#pragma unroll
                for (int n = 0; n < 4; n++) {
                    int nn = n >> 1, o = (n & 1) * 2;
                    MMA16816(oacc[m][n], pa_h[m], vb_h[nn][o], vb_h[nn][o + 1]);
                    MMA16816(oacc[m][n], pa_h[m], vb_l[nn][o], vb_l[nn][o + 1]);
                    MMA16816(oacc[m][n], pa_l[m], vb_h[nn][o], vb_h[nn][o + 1]);
                }
        }
        __syncthreads();
    }

    // epilogue: write bf16 h/l to g_xth/g_xtl[b][q + 2][hh*HC + c] (pad-2 layout)
#pragma unroll
    for (int m = 0; m < 2; m++) {
        int r0 = qw + m * 16 + (lane >> 2);
        float inv0 = 1.f / l_s[r0];
        float inv1 = 1.f / l_s[r0 + 8];
        size_t row0 = ((size_t)b * TP + q0 + r0 + 2) * CC;
        size_t row1 = ((size_t)b * TP + q0 + r0 + 10) * CC;
#pragma unroll
        for (int n = 0; n < 4; n++) {
            int c0 = hh * HC + cw + n * 8 + (lane & 3) * 2;
            uint32_t h0, l0, h1, l1;
            pack2(oacc[m][n][0] * inv0, oacc[m][n][1] * inv0, h0, l0);
            pack2(oacc[m][n][2] * inv1, oacc[m][n][3] * inv1, h1, l1);
            *(uint32_t*)(g_xth + row0 + c0) = h0;
            *(uint32_t*)(g_xtl + row0 + c0) = l0;
            *(uint32_t*)(g_xth + row1 + c0) = h1;
            *(uint32_t*)(g_xtl + row1 + c0) = l1;
        }
    }
}

// -------------- Proj conv warp-mma (bf16x3, cp.async A, ldmatrix B) ----------
// CTA: 128 co x 256 t, 512 threads. 40 stages (8 ci-chunks x 5 taps), pad 2.
#define PB_H 73728
#define PB_L 111168
#define PSMEM 148608

__global__ void __launch_bounds__(512, 1) projmma_kernel(const float* __restrict__ bias,
                                                         const float* __restrict__ x,
                                                         float* __restrict__ out) {
    int t0 = blockIdx.x * 256, co0 = blockIdx.y * 128, b = blockIdx.z;
    int tid = threadIdx.x, wid = tid >> 5, lane = tid & 31;
    int co_w = (wid >> 2) * 32, t_w = (wid & 3) * 64;
    uint32_t sb = smem_to_u32(qsm);
    float acc[2][8][4] = {};

    {   // prologue: prefetch A(s=0): dk=0, ci=0
        const __nv_bfloat16* ah = g_w2h + (size_t)co0 * CC;
        const __nv_bfloat16* al = g_w2l + (size_t)co0 * CC;
        for (int i = tid; i < 2048; i += 512) {
            int part = i >> 10, j = i & 1023, row = j >> 3, g = j & 7;
            const __nv_bfloat16* src = (part ? al : ah) + (size_t)row * CC + g * 8;
            CPASYNC16(sb + part * 18432 + row * PITCH + g * 16, src);
        }
        CPCOMMIT();
    }

    for (int s = 0; s < 40; s++) {
        int ch = s / 5, dk = s % 5, ci0 = ch * 64;
        if (dk == 0) {
            __syncthreads();
            const __nv_bfloat16* bh = g_xth + ((size_t)b * TP + t0) * CC + ci0;
            const __nv_bfloat16* bl = g_xtl + ((size_t)b * TP + t0) * CC + ci0;
            for (int i = tid; i < 260 * 8; i += 512) {
                int row = i >> 3, g = i & 7;
                size_t go = (size_t)row * CC + g * 8;
                *(uint4*)(qsm + PB_H + row * PITCH + g * 16) = *(const uint4*)(bh + go);
                *(uint4*)(qsm + PB_L + row * PITCH + g * 16) = *(const uint4*)(bl + go);
            }
        }
        CPWAIT0();
        __syncthreads();

        if (s + 1 < 40) {
            int s1 = s + 1;
            int dk1 = s1 % 5, ci1 = (s1 / 5) * 64;
            uint32_t ab = (uint32_t)(s1 & 1) * AB_STRIDE;
            const __nv_bfloat16* ah = g_w2h + ((size_t)dk1 * CC + co0) * CC + ci1;
            const __nv_bfloat16* al = g_w2l + ((size_t)dk1 * CC + co0) * CC + ci1;
            for (int i = tid; i < 2048; i += 512) {
                int part = i >> 10, j = i & 1023, row = j >> 3, g = j & 7;
                const __nv_bfloat16* src = (part ? al : ah) + (size_t)row * CC + g * 8;
                CPASYNC16(sb + ab + part * 18432 + row * PITCH + g * 16, src);
            }
            CPCOMMIT();
        }

        uint32_t abase = sb + (uint32_t)(s & 1) * AB_STRIDE;
        int mtx = lane >> 3, r8 = lane & 7;
        int vr = (lane & 7) + (lane >> 4) * 8;
        int vsel = ((lane >> 3) & 1) * 16;
#pragma unroll
        for (int ks = 0; ks < 4; ks++) {
            uint32_t a_h[2][4], a_l[2][4];
            int aoff = ((mtx & 1) * 8 + r8) * PITCH + ks * 32 + (mtx >> 1) * 16;
#pragma unroll
            for (int m = 0; m < 2; m++) {
                uint32_t ad = abase + (co_w + m * 16) * PITCH + aoff;
                LDSM4(a_h[m], ad);
                LDSM4(a_l[m], ad + 18432);
            }
            int vcb = ks * 32 + vsel;
#pragma unroll
            for (int nn = 0; nn < 4; nn++) {
                int brow = t_w + nn * 16 + vr + dk;
                uint32_t bd = sb + brow * PITCH + vcb;
                uint32_t b_h[4], b_l[4];
                LDSM4(b_h, bd + PB_H);
                LDSM4(b_l, bd + PB_L);
#pragma unroll
                for (int m = 0; m < 2; m++)
#pragma unroll
                    for (int j = 0; j < 2; j++) {
                        int n = nn * 2 + j, o = j * 2;
                        MMA16816(acc[m][n], a_h[m], b_h[o], b_h[o + 1]);
                        MMA16816(acc[m][n], a_l[m], b_h[o], b_h[o + 1]);
                        MMA16816(acc[m][n], a_h[m], b_l[o], b_l[o + 1]);
                    }
            }
        }
    }

    // epilogue: out = acc + bias + residual x
#pragma unroll
    for (int m = 0; m < 2; m++) {
        int r0 = co_w + m * 16 + (lane >> 2);
        float bv0 = bias[co0 + r0];
        float bv1 = bias[co0 + r0 + 8];
        const float* x0 = x + ((size_t)b * CC + co0 + r0) * TT + t0;
        const float* x1 = x0 + (size_t)8 * TT;
        float* d0 = out + ((size_t)b * CC + co0 + r0) * TT + t0;
        float* d1 = d0 + (size_t)8 * TT;
#pragma unroll
        for (int n = 0; n < 8; n++) {
            int cp = t_w + n * 8 + (lane & 3) * 2;
            float2 r0v = *(const float2*)(x0 + cp);
            float2 r1v = *(const float2*)(x1 + cp);
            float2 v0, v1;
            v0.x = acc[m][n][0] + bv0 + r0v.x; v0.y = acc[m][n][1] + bv0 + r0v.y;
            v1.x = acc[m][n][2] + bv1 + r1v.x; v1.y = acc[m][n][3] + bv1 + r1v.y;
            *(float2*)(d0 + cp) = v0;
            *(float2*)(d1 + cp) = v1;
        }
    }
}

// -----------------------------------------------------------------------------
extern "C" void kernel_launch(void* const* d_in, const int* in_sizes, int n_in,
                              void* d_out, int out_size) {
    const float* x = (const float*)d_in[0];
    const float* gn_gamma = (const float*)d_in[1];
    const float* gn_beta = (const float*)d_in[2];
    const float* qkv_w = (const float*)d_in[3];
    const float* qkv_b = (const float*)d_in[4];
    const float* proj_w = (const float*)d_in[5];
    const float* proj_b = (const float*)d_in[6];
    float* out = (float*)d_out;

    cudaFuncSetAttribute(qkvmma_kernel, cudaFuncAttributeMaxDynamicSharedMemorySize, QSMEM);
    cudaFuncSetAttribute(attn2_kernel, cudaFuncAttributeMaxDynamicSharedMemorySize, ASMEM);
    cudaFuncSetAttribute(projmma_kernel, cudaFuncAttributeMaxDynamicSharedMemorySize, PSMEM);

    gn_kernel<<<BB * NG, 256>>>(x, gn_gamma, gn_beta);
    zed_kernel<<<BB, 256>>>();
    xt_kernel<<<dim3(TT / 64, CC / 64, BB), 256>>>();
    wt_kernel<<<dim3(COUT3, CC / 128), 256>>>(qkv_w);
    qkvmma_kernel<<<dim3(TT / 256, COUT3 / 128, BB), 512, QSMEM>>>(qkv_b);
    wt2_kernel<<<dim3(CC, CC / 128), 256>>>(proj_w);
    zed2_kernel<<<BB, 256>>>();
    attn2_kernel<<<dim3(TT / 64, BB * HEADS), 256, ASMEM>>>();
    projmma_kernel<<<dim3(TT / 256, CC / 128, BB), 512, PSMEM>>>(proj_b, x, out);
}

// round 16
// speedup vs baseline: 3.2683x; 1.2462x over previous
#include <cuda_runtime.h>
#include <cuda_bf16.h>
#include <cuda_fp16.h>
#include <cstdint>

#define BB 4
#define CC 512
#define TT 4096
#define TP 4128
#define NG 32
#define CPG 16
#define HEADS 4
#define HC 128
#define COUT3 1536
#define KQ 32
#define KP 5

__device__ float g_xn[(size_t)BB * CC * TT];
__device__ float g_qkv[(size_t)BB * COUT3 * TT];
__device__ __half g_xth[(size_t)BB * TP * CC];        // fp16 activations (qkv in / attn out)
__device__ __half g_wth[(size_t)KQ * COUT3 * CC];     // qkv weights hi
__device__ __half g_wtl[(size_t)KQ * COUT3 * CC];     // qkv weights lo (subnormal ok)
__device__ __half g_w2h[(size_t)KP * CC * CC];        // proj weights hi
__device__ __half g_w2l[(size_t)KP * CC * CC];        // proj weights lo

__device__ __forceinline__ uint32_t smem_to_u32(const void* p) {
    uint32_t a;
    asm("{ .reg .u64 t; cvta.to.shared.u64 t, %1; cvt.u32.u64 %0, t; }" : "=r"(a) : "l"(p));
    return a;
}
#define LDSM4(r, addr) \
    asm volatile("ldmatrix.sync.aligned.m8n8.x4.shared.b16 {%0,%1,%2,%3}, [%4];" \
        : "=r"((r)[0]), "=r"((r)[1]), "=r"((r)[2]), "=r"((r)[3]) : "r"(addr))
#define LDSM4T(r, addr) \
    asm volatile("ldmatrix.sync.aligned.m8n8.x4.trans.shared.b16 {%0,%1,%2,%3}, [%4];" \
        : "=r"((r)[0]), "=r"((r)[1]), "=r"((r)[2]), "=r"((r)[3]) : "r"(addr))
#define MMA16816(d, a, b0, b1) \
    asm volatile("mma.sync.aligned.m16n8k16.row.col.f32.bf16.bf16.f32 " \
        "{%0,%1,%2,%3}, {%4,%5,%6,%7}, {%8,%9}, {%0,%1,%2,%3};" \
        : "+f"((d)[0]), "+f"((d)[1]), "+f"((d)[2]), "+f"((d)[3]) \
        : "r"((a)[0]), "r"((a)[1]), "r"((a)[2]), "r"((a)[3]), "r"(b0), "r"(b1))
#define MMA16816H(d, a, b0, b1) \
    asm volatile("mma.sync.aligned.m16n8k16.row.col.f32.f16.f16.f32 " \
        "{%0,%1,%2,%3}, {%4,%5,%6,%7}, {%8,%9}, {%0,%1,%2,%3};" \
        : "+f"((d)[0]), "+f"((d)[1]), "+f"((d)[2]), "+f"((d)[3]) \
        : "r"((a)[0]), "r"((a)[1]), "r"((a)[2]), "r"((a)[3]), "r"(b0), "r"(b1))
#define CPASYNC16(dst, src) \
    asm volatile("cp.async.cg.shared.global [%0], [%1], 16;" :: "r"(dst), "l"(src))
#define CPCOMMIT() asm volatile("cp.async.commit_group;" ::: "memory")
#define CPWAIT0() asm volatile("cp.async.wait_group 0;" ::: "memory")

// bf16 helpers (attn2 internals)
__device__ __forceinline__ void split4(float4 v, uint2& ph, uint2& pl) {
    __nv_bfloat16 h0 = __float2bfloat16_rn(v.x), h1 = __float2bfloat16_rn(v.y);
    __nv_bfloat16 h2 = __float2bfloat16_rn(v.z), h3 = __float2bfloat16_rn(v.w);
    __nv_bfloat16 l0 = __float2bfloat16_rn(v.x - __bfloat162float(h0));
    __nv_bfloat16 l1 = __float2bfloat16_rn(v.y - __bfloat162float(h1));
    __nv_bfloat16 l2 = __float2bfloat16_rn(v.z - __bfloat162float(h2));
    __nv_bfloat16 l3 = __float2bfloat16_rn(v.w - __bfloat162float(h3));
    ph.x = (uint32_t)__bfloat16_as_ushort(h0) | ((uint32_t)__bfloat16_as_ushort(h1) << 16);
    ph.y = (uint32_t)__bfloat16_as_ushort(h2) | ((uint32_t)__bfloat16_as_ushort(h3) << 16);
    pl.x = (uint32_t)__bfloat16_as_ushort(l0) | ((uint32_t)__bfloat16_as_ushort(l1) << 16);
    pl.y = (uint32_t)__bfloat16_as_ushort(l2) | ((uint32_t)__bfloat16_as_ushort(l3) << 16);
}
__device__ __forceinline__ void pack2(float a, float b, uint32_t& h, uint32_t& l) {
    __nv_bfloat16 ha = __float2bfloat16_rn(a), hb = __float2bfloat16_rn(b);
    __nv_bfloat16 la = __float2bfloat16_rn(a - __bfloat162float(ha));
    __nv_bfloat16 lb = __float2bfloat16_rn(b - __bfloat162float(hb));
    h = (uint32_t)__bfloat16_as_ushort(ha) | ((uint32_t)__bfloat16_as_ushort(hb) << 16);
    l = (uint32_t)__bfloat16_as_ushort(la) | ((uint32_t)__bfloat16_as_ushort(lb) << 16);
}
// fp16 helpers
__device__ __forceinline__ uint32_t packh2(float a, float b) {
    __half2 hv = __floats2half2_rn(a, b);
    return *(uint32_t*)&hv;
}
__device__ __forceinline__ uint2 h4(float4 v) {
    uint2 r;
    r.x = packh2(v.x, v.y);
    r.y = packh2(v.z, v.w);
    return r;
}

// --------------------------- GroupNorm ---------------------------
__global__ void __launch_bounds__(256) gn_kernel(const float* __restrict__ x,
                                                 const float* __restrict__ gamma,
                                                 const float* __restrict__ beta) {
    int b = blockIdx.x / NG, g = blockIdx.x % NG;
    const float* xp = x + ((size_t)b * CC + g * CPG) * TT;
    float* op = g_xn + ((size_t)b * CC + g * CPG) * TT;
    int tid = threadIdx.x;
    const int N = CPG * TT;
    float s = 0.f, s2 = 0.f;
    const float4* xp4 = (const float4*)xp;
    for (int i = tid; i < N / 4; i += 256) {
        float4 v = xp4[i];
        s += v.x + v.y + v.z + v.w;
        s2 += v.x * v.x + v.y * v.y + v.z * v.z + v.w * v.w;
    }
    __shared__ float rs[256], rs2[256];
    rs[tid] = s; rs2[tid] = s2;
    __syncthreads();
    for (int st = 128; st > 0; st >>= 1) {
        if (tid < st) { rs[tid] += rs[tid + st]; rs2[tid] += rs2[tid + st]; }
        __syncthreads();
    }
    float mu = rs[0] / N;
    float rstd = rsqrtf(rs2[0] / N - mu * mu + 1e-5f);
    float4* op4 = (float4*)op;
    for (int i = tid; i < N / 4; i += 256) {
        int c = g * CPG + (i * 4) / TT;
        float ga = gamma[c] * rstd, be = beta[c] - mu * ga;
        float4 v = xp4[i];
        v.x = v.x * ga + be; v.y = v.y * ga + be;
        v.z = v.z * ga + be; v.w = v.w * ga + be;
        op4[i] = v;
    }
}

// ------------- zero pad rows (qkv input, pad 15) -----------------------------
__global__ void __launch_bounds__(256) zed_kernel() {
    int b = blockIdx.x;
    size_t base = (size_t)b * TP * CC;
    __half z = __float2half(0.f);
    for (int i = threadIdx.x; i < 32 * CC; i += 256) {
        int rr = i / CC, c = i % CC;
        int row = (rr < 15) ? rr : (4096 + rr);
        g_xth[base + (size_t)row * CC + c] = z;
    }
}

// ------------- zero pad rows for attn output (pad 2) -------------------------
__global__ void __launch_bounds__(256) zed2_kernel() {
    int b = blockIdx.x;
    size_t base = (size_t)b * TP * CC;
    __half z = __float2half(0.f);
    for (int i = threadIdx.x; i < 8 * CC; i += 256) {
        int rr = i / CC, c = i % CC;
        int row = (rr < 2) ? rr : (4096 + rr);
        g_xth[base + (size_t)row * CC + c] = z;
    }
}

// xt transform (pad 15): fp16 hi only
__global__ void __launch_bounds__(256) xt_kernel() {
    __shared__ float s[64][65];
    int t0 = blockIdx.x * 64, c0 = blockIdx.y * 64, b = blockIdx.z;
    int tid = threadIdx.x;
    const float* xp = g_xn + ((size_t)b * CC + c0) * TT + t0;
#pragma unroll
    for (int p = 0; p < 16; p++) {
        int idx = tid + p * 256;
        s[idx >> 6][idx & 63] = xp[(size_t)(idx >> 6) * TT + (idx & 63)];
    }
    __syncthreads();
    int tl0 = tid >> 4, c4 = (tid & 15) * 4;
    size_t rb = (size_t)b * TP * CC;
#pragma unroll
    for (int p = 0; p < 4; p++) {
        int tl = tl0 + p * 16;
        int tp = t0 + tl + 15;
        float4 v = make_float4(s[c4 + 0][tl], s[c4 + 1][tl], s[c4 + 2][tl], s[c4 + 3][tl]);
        *(uint2*)(g_xth + rb + (size_t)tp * CC + c0 + c4) = h4(v);
    }
}

// wt transform (qkv weights): fp16 hi/lo
__global__ void __launch_bounds__(256) wt_kernel(const float* __restrict__ w) {
    __shared__ float s[KQ][129];
    int co = blockIdx.x, ci0 = blockIdx.y * 128;
    int tid = threadIdx.x;
    const float* wp = w + ((size_t)co * CC + ci0) * KQ;
#pragma unroll
    for (int p = 0; p < 16; p++) {
        int idx = tid + p * 256;
        s[idx & 31][idx >> 5] = wp[(size_t)(idx >> 5) * KQ + (idx & 31)];
    }
    __syncthreads();
#pragma unroll
    for (int p = 0; p < 16; p++) {
        int idx = tid + p * 256;
        int dk = idx >> 7, cil = idx & 127;
        float v = s[dk][cil];
        __half h = __float2half_rn(v);
        size_t off = ((size_t)dk * COUT3 + co) * CC + ci0 + cil;
        g_wth[off] = h;
        g_wtl[off] = __float2half_rn(v - __half2float(h));
    }
}

// wt2 transform (proj weights): fp16 hi/lo
__global__ void __launch_bounds__(256) wt2_kernel(const float* __restrict__ w) {
    __shared__ float s[KP][129];
    int co = blockIdx.x, ci0 = blockIdx.y * 128;
    int tid = threadIdx.x;
    const float* wp = w + ((size_t)co * CC + ci0) * KP;
    for (int idx = tid; idx < 128 * KP; idx += 256)
        s[idx % KP][idx / KP] = wp[(size_t)(idx / KP) * KP + idx % KP];
    __syncthreads();
    for (int idx = tid; idx < KP * 128; idx += 256) {
        int dk = idx / 128, cil = idx % 128;
        float v = s[dk][cil];
        __half h = __float2half_rn(v);
        size_t off = ((size_t)dk * CC + co) * CC + ci0 + cil;
        g_w2h[off] = h;
        g_w2l[off] = __float2half_rn(v - __half2float(h));
    }
}

// -------------- QKV conv warp-mma fp16 2-pass, cp.async A --------------------
#define PITCH 144
#define AB_STRIDE 36864
#define QB_H 73728
#define QSMEM 115056

extern __shared__ char qsm[];

__global__ void __launch_bounds__(512, 1) qkvmma_kernel(const float* __restrict__ bias) {
    int t0 = blockIdx.x * 256, co0 = blockIdx.y * 128, b = blockIdx.z;
    int tid = threadIdx.x, wid = tid >> 5, lane = tid & 31;
    int co_w = (wid >> 2) * 32, t_w = (wid & 3) * 64;
    uint32_t sb = smem_to_u32(qsm);
    float acc[2][8][4] = {};

    {
        const __half* ah = g_wth + (size_t)co0 * CC;
        const __half* al = g_wtl + (size_t)co0 * CC;
        for (int i = tid; i < 2048; i += 512) {
            int part = i >> 10, j = i & 1023, row = j >> 3, g = j & 7;
            const __half* src = (part ? al : ah) + (size_t)row * CC + g * 8;
            CPASYNC16(sb + part * 18432 + row * PITCH + g * 16, src);
        }
        CPCOMMIT();
    }

    for (int s = 0; s < 256; s++) {
        int ch = s >> 5, dk = s & 31, ci0 = ch * 64;
        if (dk == 0) {
            __syncthreads();
            const __half* bh = g_xth + ((size_t)b * TP + t0) * CC + ci0;
            for (int i = tid; i < 287 * 8; i += 512) {
                int row = i >> 3, g = i & 7;
                *(uint4*)(qsm + QB_H + row * PITCH + g * 16) =
                    *(const uint4*)(bh + (size_t)row * CC + g * 8);
            }
        }
        CPWAIT0();
        __syncthreads();

        if (s + 1 < 256) {
            int s1 = s + 1;
            int dk1 = s1 & 31, ci1 = (s1 >> 5) * 64;
            uint32_t ab = (uint32_t)(s1 & 1) * AB_STRIDE;
            const __half* ah = g_wth + ((size_t)dk1 * COUT3 + co0) * CC + ci1;
            const __half* al = g_wtl + ((size_t)dk1 * COUT3 + co0) * CC + ci1;
            for (int i = tid; i < 2048; i += 512) {
                int part = i >> 10, j = i & 1023, row = j >> 3, g = j & 7;
                const __half* src = (part ? al : ah) + (size_t)row * CC + g * 8;
                CPASYNC16(sb + ab + part * 18432 + row * PITCH + g * 16, src);
            }
            CPCOMMIT();
        }

        uint32_t abase = sb + (uint32_t)(s & 1) * AB_STRIDE;
        int mtx = lane >> 3, r8 = lane & 7;
        int vr = (lane & 7) + (lane >> 4) * 8;
        int vsel = ((lane >> 3) & 1) * 16;
#pragma unroll
        for (int ks = 0; ks < 4; ks++) {
            uint32_t a_h[2][4], a_l[2][4];
            int aoff = ((mtx & 1) * 8 + r8) * PITCH + ks * 32 + (mtx >> 1) * 16;
#pragma unroll
            for (int m = 0; m < 2; m++) {
                uint32_t ad = abase + (co_w + m * 16) * PITCH + aoff;
                LDSM4(a_h[m], ad);
                LDSM4(a_l[m], ad + 18432);
            }
            int vcb = ks * 32 + vsel;
#pragma unroll
            for (int nn = 0; nn < 4; nn++) {
                int brow = t_w + nn * 16 + vr + dk;
                uint32_t bd = sb + brow * PITCH + vcb;
                uint32_t b_h[4];
                LDSM4(b_h, bd + QB_H);
#pragma unroll
                for (int m = 0; m < 2; m++)
#pragma unroll
                    for (int j = 0; j < 2; j++) {
                        int n = nn * 2 + j, o = j * 2;
                        MMA16816H(acc[m][n], a_h[m], b_h[o], b_h[o + 1]);
                        MMA16816H(acc[m][n], a_l[m], b_h[o], b_h[o + 1]);
                    }
            }
        }
    }

#pragma unroll
    for (int m = 0; m < 2; m++) {
        int r0 = co_w + m * 16 + (lane >> 2);
        float bv0 = bias[co0 + r0];
        float bv1 = bias[co0 + r0 + 8];
        float* d0 = g_qkv + ((size_t)b * COUT3 + co0 + r0) * TT + t0;
        float* d1 = d0 + (size_t)8 * TT;
#pragma unroll
        for (int n = 0; n < 8; n++) {
            int cp = t_w + n * 8 + (lane & 3) * 2;
            float2 v0, v1;
            v0.x = acc[m][n][0] + bv0; v0.y = acc[m][n][1] + bv0;
            v1.x = acc[m][n][2] + bv1; v1.y = acc[m][n][3] + bv1;
            *(float2*)(d0 + cp) = v0;
            *(float2*)(d1 + cp) = v1;
        }
    }
}

// ---------------- Flash attention (bf16x3 internals, fp16 epilogue) ----------
#define AT_QH 0
#define AT_QL 18432
#define AT_KH 36864
#define AT_KL 55296
#define AT_VH 73728
#define AT_VL 92160
#define AT_S  110592
#define AT_PH 127488
#define AT_PL 136704
#define AT_M  145920
#define AT_L  146176
#define AT_AL 146432
#define AT_RED 146688
#define ASMEM 147712

__global__ void __launch_bounds__(256, 1) attn2_kernel() {
    int q0 = blockIdx.x * 64;
    int bh = blockIdx.y;
    int b = bh / HEADS, hh = bh % HEADS;
    const float* qkv = g_qkv + (size_t)b * COUT3 * TT + (size_t)hh * (3 * HC) * TT;
    char* sm = qsm;
    uint32_t sb = smem_to_u32(sm);
    int tid = threadIdx.x, wid = tid >> 5, lane = tid & 31;
    int qw = (wid >> 2) * 32;
    int kw = (wid & 3) * 16;
    int cw = (wid & 3) * 32;
    int row = tid & 63, quad = tid >> 6;

    float* s_s = (float*)(sm + AT_S);
    float* m_s = (float*)(sm + AT_M);
    float* l_s = (float*)(sm + AT_L);
    float* al_s = (float*)(sm + AT_AL);
    float* red = (float*)(sm + AT_RED);

    const float scale = 0.0883883476483184f;
    for (int i = tid; i < 2048; i += 256) {
        int c = i >> 4, j4 = (i & 15) * 4;
        float4 v = *(const float4*)(qkv + (size_t)c * TT + q0 + j4);
        v.x *= scale; v.y *= scale; v.z *= scale; v.w *= scale;
        uint2 ph, pl;
        split4(v, ph, pl);
        *(uint2*)(sm + AT_QH + c * 144 + j4 * 2) = ph;
        *(uint2*)(sm + AT_QL + c * 144 + j4 * 2) = pl;
    }
    if (tid < 64) { m_s[tid] = -1e30f; l_s[tid] = 0.f; }

    float oacc[2][4][4] = {};
    __syncthreads();

    for (int kt = 0; kt < TT; kt += 64) {
        for (int i = tid; i < 2048; i += 256) {
            int c = i >> 4, j4 = (i & 15) * 4;
            float4 kv4 = *(const float4*)(qkv + (size_t)(HC + c) * TT + kt + j4);
            uint2 ph, pl;
            split4(kv4, ph, pl);
            *(uint2*)(sm + AT_KH + c * 144 + j4 * 2) = ph;
            *(uint2*)(sm + AT_KL + c * 144 + j4 * 2) = pl;
            float4 vv4 = *(const float4*)(qkv + (size_t)(2 * HC + c) * TT + kt + j4);
            split4(vv4, ph, pl);
            *(uint2*)(sm + AT_VH + c * 144 + j4 * 2) = ph;
            *(uint2*)(sm + AT_VL + c * 144 + j4 * 2) = pl;
        }
        __syncthreads();

        float sacc[2][2][4] = {};
#pragma unroll
        for (int ks = 0; ks < 8; ks++) {
            int kk0 = ks * 16;
            int ar = kk0 + (lane & 7) + (lane >> 4) * 8;
            int acb = ((lane >> 3) & 1) * 16;
            uint32_t a_h[2][4], a_l[2][4];
#pragma unroll
            for (int m = 0; m < 2; m++) {
                uint32_t ad = sb + ar * 144 + (qw + m * 16) * 2 + acb;
                LDSM4T(a_h[m], ad + AT_QH);
                LDSM4T(a_l[m], ad + AT_QL);
            }
            int br = kk0 + (lane & 7) + ((lane >> 3) & 1) * 8;
            uint32_t bd = sb + br * 144 + kw * 2 + (lane >> 4) * 16;
            uint32_t b_h[4], b_l[4];
            LDSM4T(b_h, bd + AT_KH);
            LDSM4T(b_l, bd + AT_KL);
#pragma unroll
            for (int m = 0; m < 2; m++)
#pragma unroll
                for (int n = 0; n < 2; n++) {
                    MMA16816(sacc[m][n], a_h[m], b_h[2 * n], b_h[2 * n + 1]);
                    MMA16816(sacc[m][n], a_h[m], b_l[2 * n], b_l[2 * n + 1]);
                    MMA16816(sacc[m][n], a_l[m], b_h[2 * n], b_h[2 * n + 1]);
                }
        }
#pragma unroll
        for (int m = 0; m < 2; m++) {
            int r0 = qw + m * 16 + (lane >> 2);
#pragma unroll
            for (int n = 0; n < 2; n++) {
                int c0 = kw + n * 8 + (lane & 3) * 2;
                s_s[r0 * 66 + c0] = sacc[m][n][0];
                s_s[r0 * 66 + c0 + 1] = sacc[m][n][1];
                s_s[(r0 + 8) * 66 + c0] = sacc[m][n][2];
                s_s[(r0 + 8) * 66 + c0 + 1] = sacc[m][n][3];
            }
        }
        __syncthreads();

        float mx = -1e30f;
#pragma unroll
        for (int j = 0; j < 16; j++) mx = fmaxf(mx, s_s[row * 66 + quad * 16 + j]);
        red[row * 4 + quad] = mx;
        __syncthreads();
        if (tid < 64) {
            float m_old = m_s[tid];
            float mm = fmaxf(fmaxf(red[tid * 4], red[tid * 4 + 1]),
                             fmaxf(red[tid * 4 + 2], red[tid * 4 + 3]));
            float m_new = fmaxf(m_old, mm);
            al_s[tid] = __expf(m_old - m_new);
            m_s[tid] = m_new;
        }
        __syncthreads();
        {
            float m_new = m_s[row];
            float ssum = 0.f;
#pragma unroll
            for (int j = 0; j < 16; j += 2) {
                int cc0 = quad * 16 + j;
                float p0 = __expf(s_s[row * 66 + cc0] - m_new);
                float p1 = __expf(s_s[row * 66 + cc0 + 1] - m_new);
                ssum += p0 + p1;
                uint32_t ph, pl;
                pack2(p0, p1, ph, pl);
                *(uint32_t*)(sm + AT_PH + row * 144 + cc0 * 2) = ph;
                *(uint32_t*)(sm + AT_PL + row * 144 + cc0 * 2) = pl;
            }
            red[row * 4 + quad] = ssum;
        }
        __syncthreads();
        if (tid < 64)
            l_s[tid] = l_s[tid] * al_s[tid] +
                       red[tid * 4] + red[tid * 4 + 1] + red[tid * 4 + 2] + red[tid * 4 + 3];
        __syncthreads();

#pragma unroll
        for (int m = 0; m < 2; m++) {
            float a0 = al_s[qw + m * 16 + (lane >> 2)];
            float a1 = al_s[qw + m * 16 + 8 + (lane >> 2)];
#pragma unroll
            for (int n = 0; n < 4; n++) {
                oacc[m][n][0] *= a0; oacc[m][n][1] *= a0;
                oacc[m][n][2] *= a1; oacc[m][n][3] *= a1;
            }
        }
#pragma unroll
        for (int ks = 0; ks < 4; ks++) {
            int kk0 = ks * 16;
            int pr = (lane & 7) + ((lane >> 3) & 1) * 8;
            int pcb = kk0 * 2 + (lane >> 4) * 16;
            uint32_t pa_h[2][4], pa_l[2][4];
#pragma unroll
            for (int m = 0; m < 2; m++) {
                uint32_t ad = sb + (qw + m * 16 + pr) * 144 + pcb;
                LDSM4(pa_h[m], ad + AT_PH);
                LDSM4(pa_l[m], ad + AT_PL);
            }
            int vr = (lane & 7) + (lane >> 4) * 8;
            int vcb = kk0 * 2 + ((lane >> 3) & 1) * 16;
            uint32_t vb_h[2][4], vb_l[2][4];
#pragma unroll
            for (int nn = 0; nn < 2; nn++) {
                uint32_t vd = sb + (cw + nn * 16 + vr) * 144 + vcb;
                LDSM4(vb_h[nn], vd + AT_VH);
                LDSM4(vb_l[nn], vd + AT_VL);
            }
#pragma unroll
            for (int m = 0; m < 2; m++)
#pragma unroll
                for (int n = 0; n < 4; n++) {
                    int nn = n >> 1, o = (n & 1) * 2;
                    MMA16816(oacc[m][n], pa_h[m], vb_h[nn][o], vb_h[nn][o + 1]);
                    MMA16816(oacc[m][n], pa_h[m], vb_l[nn][o], vb_l[nn][o + 1]);
                    MMA16816(oacc[m][n], pa_l[m], vb_h[nn][o], vb_h[nn][o + 1]);
                }
        }
        __syncthreads();
    }

    // epilogue: write fp16 hi to g_xth[b][q + 2][hh*HC + c] (pad-2 layout)
#pragma unroll
    for (int m = 0; m < 2; m++) {
        int r0 = qw + m * 16 + (lane >> 2);
        float inv0 = 1.f / l_s[r0];
        float inv1 = 1.f / l_s[r0 + 8];
        size_t row0 = ((size_t)b * TP + q0 + r0 + 2) * CC;
        size_t row1 = ((size_t)b * TP + q0 + r0 + 10) * CC;
#pragma unroll
        for (int n = 0; n < 4; n++) {
            int c0 = hh * HC + cw + n * 8 + (lane & 3) * 2;
            *(uint32_t*)(g_xth + row0 + c0) =
                packh2(oacc[m][n][0] * inv0, oacc[m][n][1] * inv0);
            *(uint32_t*)(g_xth + row1 + c0) =
                packh2(oacc[m][n][2] * inv1, oacc[m][n][3] * inv1);
        }
    }
}

// -------------- Proj conv warp-mma fp16 2-pass -------------------------------
#define PB_H 73728
#define PSMEM 111168

__global__ void __launch_bounds__(512, 1) projmma_kernel(const float* __restrict__ bias,
                                                         const float* __restrict__ x,
                                                         float* __restrict__ out) {
    int t0 = blockIdx.x * 256, co0 = blockIdx.y * 128, b = blockIdx.z;
    int tid = threadIdx.x, wid = tid >> 5, lane = tid & 31;
    int co_w = (wid >> 2) * 32, t_w = (wid & 3) * 64;
    uint32_t sb = smem_to_u32(qsm);
    float acc[2][8][4] = {};

    {
        const __half* ah = g_w2h + (size_t)co0 * CC;
        const __half* al = g_w2l + (size_t)co0 * CC;
        for (int i = tid; i < 2048; i += 512) {
            int part = i >> 10, j = i & 1023, row = j >> 3, g = j & 7;
            const __half* src = (part ? al : ah) + (size_t)row * CC + g * 8;
            CPASYNC16(sb + part * 18432 + row * PITCH + g * 16, src);
        }
        CPCOMMIT();
    }

    for (int s = 0; s < 40; s++) {
        int ch = s / 5, dk = s % 5, ci0 = ch * 64;
        if (dk == 0) {
            __syncthreads();
            const __half* bh = g_xth + ((size_t)b * TP + t0) * CC + ci0;
            for (int i = tid; i < 260 * 8; i += 512) {
                int row = i >> 3, g = i & 7;
                *(uint4*)(qsm + PB_H + row * PITCH + g * 16) =
                    *(const uint4*)(bh + (size_t)row * CC + g * 8);
            }
        }
        CPWAIT0();
        __syncthreads();

        if (s + 1 < 40) {
            int s1 = s + 1;
            int dk1 = s1 % 5, ci1 = (s1 / 5) * 64;
            uint32_t ab = (uint32_t)(s1 & 1) * AB_STRIDE;
            const __half* ah = g_w2h + ((size_t)dk1 * CC + co0) * CC + ci1;
            const __half* al = g_w2l + ((size_t)dk1 * CC + co0) * CC + ci1;
            for (int i = tid; i < 2048; i += 512) {
                int part = i >> 10, j = i & 1023, row = j >> 3, g = j & 7;
                const __half* src = (part ? al : ah) + (size_t)row * CC + g * 8;
                CPASYNC16(sb + ab + part * 18432 + row * PITCH + g * 16, src);
            }
            CPCOMMIT();
        }

        uint32_t abase = sb + (uint32_t)(s & 1) * AB_STRIDE;
        int mtx = lane >> 3, r8 = lane & 7;
        int vr = (lane & 7) + (lane >> 4) * 8;
        int vsel = ((lane >> 3) & 1) * 16;
#pragma unroll
        for (int ks = 0; ks < 4; ks++) {
            uint32_t a_h[2][4], a_l[2][4];
            int aoff = ((mtx & 1) * 8 + r8) * PITCH + ks * 32 + (mtx >> 1) * 16;
#pragma unroll
            for (int m = 0; m < 2; m++) {
                uint32_t ad = abase + (co_w + m * 16) * PITCH + aoff;
                LDSM4(a_h[m], ad);
                LDSM4(a_l[m], ad + 18432);
            }
            int vcb = ks * 32 + vsel;
#pragma unroll
            for (int nn = 0; nn < 4; nn++) {
                int brow = t_w + nn * 16 + vr + dk;
                uint32_t bd = sb + brow * PITCH + vcb;
                uint32_t b_h[4];
                LDSM4(b_h, bd + PB_H);
#pragma unroll
                for (int m = 0; m < 2; m++)
#pragma unroll
                    for (int j = 0; j < 2; j++) {
                        int n = nn * 2 + j, o = j * 2;
                        MMA16816H(acc[m][n], a_h[m], b_h[o], b_h[o + 1]);
                        MMA16816H(acc[m][n], a_l[m], b_h[o], b_h[o + 1]);
                    }
            }
        }
    }

#pragma unroll
    for (int m = 0; m < 2; m++) {
        int r0 = co_w + m * 16 + (lane >> 2);
        float bv0 = bias[co0 + r0];
        float bv1 = bias[co0 + r0 + 8];
        const float* x0 = x + ((size_t)b * CC + co0 + r0) * TT + t0;
        const float* x1 = x0 + (size_t)8 * TT;
        float* d0 = out + ((size_t)b * CC + co0 + r0) * TT + t0;
        float* d1 = d0 + (size_t)8 * TT;
#pragma unroll
        for (int n = 0; n < 8; n++) {
            int cp = t_w + n * 8 + (lane & 3) * 2;
            float2 r0v = *(const float2*)(x0 + cp);
            float2 r1v = *(const float2*)(x1 + cp);
            float2 v0, v1;
            v0.x = acc[m][n][0] + bv0 + r0v.x; v0.y = acc[m][n][1] + bv0 + r0v.y;
            v1.x = acc[m][n][2] + bv1 + r1v.x; v1.y = acc[m][n][3] + bv1 + r1v.y;
            *(float2*)(d0 + cp) = v0;
            *(float2*)(d1 + cp) = v1;
        }
    }
}

// -----------------------------------------------------------------------------
extern "C" void kernel_launch(void* const* d_in, const int* in_sizes, int n_in,
                              void* d_out, int out_size) {
    const float* x = (const float*)d_in[0];
    const float* gn_gamma = (const float*)d_in[1];
    const float* gn_beta = (const float*)d_in[2];
    const float* qkv_w = (const float*)d_in[3];
    const float* qkv_b = (const float*)d_in[4];
    const float* proj_w = (const float*)d_in[5];
    const float* proj_b = (const float*)d_in[6];
    float* out = (float*)d_out;

    cudaFuncSetAttribute(qkvmma_kernel, cudaFuncAttributeMaxDynamicSharedMemorySize, QSMEM);
    cudaFuncSetAttribute(attn2_kernel, cudaFuncAttributeMaxDynamicSharedMemorySize, ASMEM);
    cudaFuncSetAttribute(projmma_kernel, cudaFuncAttributeMaxDynamicSharedMemorySize, PSMEM);

    gn_kernel<<<BB * NG, 256>>>(x, gn_gamma, gn_beta);
    zed_kernel<<<BB, 256>>>();
    xt_kernel<<<dim3(TT / 64, CC / 64, BB), 256>>>();
    wt_kernel<<<dim3(COUT3, CC / 128), 256>>>(qkv_w);
    qkvmma_kernel<<<dim3(TT / 256, COUT3 / 128, BB), 512, QSMEM>>>(qkv_b);
    wt2_kernel<<<dim3(CC, CC / 128), 256>>>(proj_w);
    zed2_kernel<<<BB, 256>>>();
    attn2_kernel<<<dim3(TT / 64, BB * HEADS), 256, ASMEM>>>();
    projmma_kernel<<<dim3(TT / 256, CC / 128, BB), 512, PSMEM>>>(proj_b, x, out);
}

// round 17
// speedup vs baseline: 3.4099x; 1.0433x over previous
#include <cuda_runtime.h>
#include <cuda_bf16.h>
#include <cuda_fp16.h>
#include <cstdint>

#define BB 4
#define CC 512
#define TT 4096
#define TP 4128
#define NG 32
#define CPG 16
#define HEADS 4
#define HC 128
#define COUT3 1536
#define KQ 32
#define KP 5

__device__ float g_xn[(size_t)BB * CC * TT];
__device__ float g_qkv[(size_t)BB * COUT3 * TT];
__device__ __half g_xth[(size_t)BB * TP * CC];        // fp16 activations hi (qkv in / attn out)
__device__ __half g_xtl[(size_t)BB * TP * CC];        // fp16 activations lo (attn out only)
__device__ __half g_wth[(size_t)KQ * COUT3 * CC];     // qkv weights hi
__device__ __half g_wtl[(size_t)KQ * COUT3 * CC];     // qkv weights lo (subnormal ok)
__device__ __half g_w2h[(size_t)KP * CC * CC];        // proj weights hi
__device__ __half g_w2l[(size_t)KP * CC * CC];        // proj weights lo

__device__ __forceinline__ uint32_t smem_to_u32(const void* p) {
    uint32_t a;
    asm("{ .reg .u64 t; cvta.to.shared.u64 t, %1; cvt.u32.u64 %0, t; }" : "=r"(a) : "l"(p));
    return a;
}
#define LDSM4(r, addr) \
    asm volatile("ldmatrix.sync.aligned.m8n8.x4.shared.b16 {%0,%1,%2,%3}, [%4];" \
        : "=r"((r)[0]), "=r"((r)[1]), "=r"((r)[2]), "=r"((r)[3]) : "r"(addr))
#define LDSM4T(r, addr) \
    asm volatile("ldmatrix.sync.aligned.m8n8.x4.trans.shared.b16 {%0,%1,%2,%3}, [%4];" \
        : "=r"((r)[0]), "=r"((r)[1]), "=r"((r)[2]), "=r"((r)[3]) : "r"(addr))
#define MMA16816(d, a, b0, b1) \
    asm volatile("mma.sync.aligned.m16n8k16.row.col.f32.bf16.bf16.f32 " \
        "{%0,%1,%2,%3}, {%4,%5,%6,%7}, {%8,%9}, {%0,%1,%2,%3};" \
        : "+f"((d)[0]), "+f"((d)[1]), "+f"((d)[2]), "+f"((d)[3]) \
        : "r"((a)[0]), "r"((a)[1]), "r"((a)[2]), "r"((a)[3]), "r"(b0), "r"(b1))
#define MMA16816H(d, a, b0, b1) \
    asm volatile("mma.sync.aligned.m16n8k16.row.col.f32.f16.f16.f32 " \
        "{%0,%1,%2,%3}, {%4,%5,%6,%7}, {%8,%9}, {%0,%1,%2,%3};" \
        : "+f"((d)[0]), "+f"((d)[1]), "+f"((d)[2]), "+f"((d)[3]) \
        : "r"((a)[0]), "r"((a)[1]), "r"((a)[2]), "r"((a)[3]), "r"(b0), "r"(b1))
#define CPASYNC16(dst, src) \
    asm volatile("cp.async.cg.shared.global [%0], [%1], 16;" :: "r"(dst), "l"(src))
#define CPCOMMIT() asm volatile("cp.async.commit_group;" ::: "memory")
#define CPWAIT0() asm volatile("cp.async.wait_group 0;" ::: "memory")

// bf16 helpers (attn2 internals)
__device__ __forceinline__ void split4(float4 v, uint2& ph, uint2& pl) {
    __nv_bfloat16 h0 = __float2bfloat16_rn(v.x), h1 = __float2bfloat16_rn(v.y);
    __nv_bfloat16 h2 = __float2bfloat16_rn(v.z), h3 = __float2bfloat16_rn(v.w);
    __nv_bfloat16 l0 = __float2bfloat16_rn(v.x - __bfloat162float(h0));
    __nv_bfloat16 l1 = __float2bfloat16_rn(v.y - __bfloat162float(h1));
    __nv_bfloat16 l2 = __float2bfloat16_rn(v.z - __bfloat162float(h2));
    __nv_bfloat16 l3 = __float2bfloat16_rn(v.w - __bfloat162float(h3));
    ph.x = (uint32_t)__bfloat16_as_ushort(h0) | ((uint32_t)__bfloat16_as_ushort(h1) << 16);
    ph.y = (uint32_t)__bfloat16_as_ushort(h2) | ((uint32_t)__bfloat16_as_ushort(h3) << 16);
    pl.x = (uint32_t)__bfloat16_as_ushort(l0) | ((uint32_t)__bfloat16_as_ushort(l1) << 16);
    pl.y = (uint32_t)__bfloat16_as_ushort(l2) | ((uint32_t)__bfloat16_as_ushort(l3) << 16);
}
__device__ __forceinline__ void pack2(float a, float b, uint32_t& h, uint32_t& l) {
    __nv_bfloat16 ha = __float2bfloat16_rn(a), hb = __float2bfloat16_rn(b);
    __nv_bfloat16 la = __float2bfloat16_rn(a - __bfloat162float(ha));
    __nv_bfloat16 lb = __float2bfloat16_rn(b - __bfloat162float(hb));
    h = (uint32_t)__bfloat16_as_ushort(ha) | ((uint32_t)__bfloat16_as_ushort(hb) << 16);
    l = (uint32_t)__bfloat16_as_ushort(la) | ((uint32_t)__bfloat16_as_ushort(lb) << 16);
}
// fp16 helpers
__device__ __forceinline__ uint32_t packh2(float a, float b) {
    __half2 hv = __floats2half2_rn(a, b);
    return *(uint32_t*)&hv;
}
__device__ __forceinline__ void packh2hl(float a, float b, uint32_t& h, uint32_t& l) {
    __half ha = __float2half_rn(a), hb = __float2half_rn(b);
    __half la = __float2half_rn(a - __half2float(ha));
    __half lb = __float2half_rn(b - __half2float(hb));
    h = (uint32_t)__half_as_ushort(ha) | ((uint32_t)__half_as_ushort(hb) << 16);
    l = (uint32_t)__half_as_ushort(la) | ((uint32_t)__half_as_ushort(lb) << 16);
}
__device__ __forceinline__ uint2 h4(float4 v) {
    uint2 r;
    r.x = packh2(v.x, v.y);
    r.y = packh2(v.z, v.w);
    return r;
}

// --------------------------- GroupNorm ---------------------------
__global__ void __launch_bounds__(256) gn_kernel(const float* __restrict__ x,
                                                 const float* __restrict__ gamma,
                                                 const float* __restrict__ beta) {
    int b = blockIdx.x / NG, g = blockIdx.x % NG;
    const float* xp = x + ((size_t)b * CC + g * CPG) * TT;
    float* op = g_xn + ((size_t)b * CC + g * CPG) * TT;
    int tid = threadIdx.x;
    const int N = CPG * TT;
    float s = 0.f, s2 = 0.f;
    const float4* xp4 = (const float4*)xp;
    for (int i = tid; i < N / 4; i += 256) {
        float4 v = xp4[i];
        s += v.x + v.y + v.z + v.w;
        s2 += v.x * v.x + v.y * v.y + v.z * v.z + v.w * v.w;
    }
    __shared__ float rs[256], rs2[256];
    rs[tid] = s; rs2[tid] = s2;
    __syncthreads();
    for (int st = 128; st > 0; st >>= 1) {
        if (tid < st) { rs[tid] += rs[tid + st]; rs2[tid] += rs2[tid + st]; }
        __syncthreads();
    }
    float mu = rs[0] / N;
    float rstd = rsqrtf(rs2[0] / N - mu * mu + 1e-5f);
    float4* op4 = (float4*)op;
    for (int i = tid; i < N / 4; i += 256) {
        int c = g * CPG + (i * 4) / TT;
        float ga = gamma[c] * rstd, be = beta[c] - mu * ga;
        float4 v = xp4[i];
        v.x = v.x * ga + be; v.y = v.y * ga + be;
        v.z = v.z * ga + be; v.w = v.w * ga + be;
        op4[i] = v;
    }
}

// ------------- zero pad rows (qkv input, pad 15; hi plane only) --------------
__global__ void __launch_bounds__(256) zed_kernel() {
    int b = blockIdx.x;
    size_t base = (size_t)b * TP * CC;
    __half z = __float2half(0.f);
    for (int i = threadIdx.x; i < 32 * CC; i += 256) {
        int rr = i / CC, c = i % CC;
        int row = (rr < 15) ? rr : (4096 + rr);
        g_xth[base + (size_t)row * CC + c] = z;
    }
}

// ------------- zero pad rows for attn output (pad 2; both planes) ------------
__global__ void __launch_bounds__(256) zed2_kernel() {
    int b = blockIdx.x;
    size_t base = (size_t)b * TP * CC;
    __half z = __float2half(0.f);
    for (int i = threadIdx.x; i < 8 * CC; i += 256) {
        int rr = i / CC, c = i % CC;
        int row = (rr < 2) ? rr : (4096 + rr);
        g_xth[base + (size_t)row * CC + c] = z;
        g_xtl[base + (size_t)row * CC + c] = z;
    }
}

// xt transform (pad 15): fp16 hi only
__global__ void __launch_bounds__(256) xt_kernel() {
    __shared__ float s[64][65];
    int t0 = blockIdx.x * 64, c0 = blockIdx.y * 64, b = blockIdx.z;
    int tid = threadIdx.x;
    const float* xp = g_xn + ((size_t)b * CC + c0) * TT + t0;
#pragma unroll
    for (int p = 0; p < 16; p++) {
        int idx = tid + p * 256;
        s[idx >> 6][idx & 63] = xp[(size_t)(idx >> 6) * TT + (idx & 63)];
    }
    __syncthreads();
    int tl0 = tid >> 4, c4 = (tid & 15) * 4;
    size_t rb = (size_t)b * TP * CC;
#pragma unroll
    for (int p = 0; p < 4; p++) {
        int tl = tl0 + p * 16;
        int tp = t0 + tl + 15;
        float4 v = make_float4(s[c4 + 0][tl], s[c4 + 1][tl], s[c4 + 2][tl], s[c4 + 3][tl]);
        *(uint2*)(g_xth + rb + (size_t)tp * CC + c0 + c4) = h4(v);
    }
}

// wt transform (qkv weights): fp16 hi/lo
__global__ void __launch_bounds__(256) wt_kernel(const float* __restrict__ w) {
    __shared__ float s[KQ][129];
    int co = blockIdx.x, ci0 = blockIdx.y * 128;
    int tid = threadIdx.x;
    const float* wp = w + ((size_t)co * CC + ci0) * KQ;
#pragma unroll
    for (int p = 0; p < 16; p++) {
        int idx = tid + p * 256;
        s[idx & 31][idx >> 5] = wp[(size_t)(idx >> 5) * KQ + (idx & 31)];
    }
    __syncthreads();
#pragma unroll
    for (int p = 0; p < 16; p++) {
        int idx = tid + p * 256;
        int dk = idx >> 7, cil = idx & 127;
        float v = s[dk][cil];
        __half h = __float2half_rn(v);
        size_t off = ((size_t)dk * COUT3 + co) * CC + ci0 + cil;
        g_wth[off] = h;
        g_wtl[off] = __float2half_rn(v - __half2float(h));
    }
}

// wt2 transform (proj weights): fp16 hi/lo
__global__ void __launch_bounds__(256) wt2_kernel(const float* __restrict__ w) {
    __shared__ float s[KP][129];
    int co = blockIdx.x, ci0 = blockIdx.y * 128;
    int tid = threadIdx.x;
    const float* wp = w + ((size_t)co * CC + ci0) * KP;
    for (int idx = tid; idx < 128 * KP; idx += 256)
        s[idx % KP][idx / KP] = wp[(size_t)(idx / KP) * KP + idx % KP];
    __syncthreads();
    for (int idx = tid; idx < KP * 128; idx += 256) {
        int dk = idx / 128, cil = idx % 128;
        float v = s[dk][cil];
        __half h = __float2half_rn(v);
        size_t off = ((size_t)dk * CC + co) * CC + ci0 + cil;
        g_w2h[off] = h;
        g_w2l[off] = __float2half_rn(v - __half2float(h));
    }
}

// -------------- QKV conv warp-mma fp16 2-pass, t-tile 128, 2 CTAs/SM ---------
#define PITCH 144
#define AB_STRIDE 36864
#define QB_H 73728
#define QSMEM 96768          // 73728 + 160*144

extern __shared__ char qsm[];

__global__ void __launch_bounds__(512, 2) qkvmma_kernel(const float* __restrict__ bias) {
    int t0 = blockIdx.x * 128, co0 = blockIdx.y * 128, b = blockIdx.z;
    int tid = threadIdx.x, wid = tid >> 5, lane = tid & 31;
    int co_w = (wid >> 2) * 32, t_w = (wid & 3) * 32;
    uint32_t sb = smem_to_u32(qsm);
    float acc[2][4][4] = {};

    {
        const __half* ah = g_wth + (size_t)co0 * CC;
        const __half* al = g_wtl + (size_t)co0 * CC;
        for (int i = tid; i < 2048; i += 512) {
            int part = i >> 10, j = i & 1023, row = j >> 3, g = j & 7;
            const __half* src = (part ? al : ah) + (size_t)row * CC + g * 8;
            CPASYNC16(sb + part * 18432 + row * PITCH + g * 16, src);
        }
        CPCOMMIT();
    }

    for (int s = 0; s < 256; s++) {
        int dk = s & 31;
        if (dk == 0) {
            int ci0 = (s >> 5) * 64;
            __syncthreads();
            const __half* bh = g_xth + ((size_t)b * TP + t0) * CC + ci0;
            for (int i = tid; i < 160 * 8; i += 512) {
                int row = i >> 3, g = i & 7;
                *(uint4*)(qsm + QB_H + row * PITCH + g * 16) =
                    *(const uint4*)(bh + (size_t)row * CC + g * 8);
            }
        }
        CPWAIT0();
        __syncthreads();

        if (s + 1 < 256) {
            int s1 = s + 1;
            int dk1 = s1 & 31, ci1 = (s1 >> 5) * 64;
            uint32_t ab = (uint32_t)(s1 & 1) * AB_STRIDE;
            const __half* ah = g_wth + ((size_t)dk1 * COUT3 + co0) * CC + ci1;
            const __half* al = g_wtl + ((size_t)dk1 * COUT3 + co0) * CC + ci1;
            for (int i = tid; i < 2048; i += 512) {
                int part = i >> 10, j = i & 1023, row = j >> 3, g = j & 7;
                const __half* src = (part ? al : ah) + (size_t)row * CC + g * 8;
                CPASYNC16(sb + ab + part * 18432 + row * PITCH + g * 16, src);
            }
            CPCOMMIT();
        }

        uint32_t abase = sb + (uint32_t)(s & 1) * AB_STRIDE;
        int mtx = lane >> 3, r8 = lane & 7;
        int vr = (lane & 7) + (lane >> 4) * 8;
        int vsel = ((lane >> 3) & 1) * 16;
#pragma unroll
        for (int ks = 0; ks < 4; ks++) {
            uint32_t a_h[2][4], a_l[2][4];
            int aoff = ((mtx & 1) * 8 + r8) * PITCH + ks * 32 + (mtx >> 1) * 16;
#pragma unroll
            for (int m = 0; m < 2; m++) {
                uint32_t ad = abase + (co_w + m * 16) * PITCH + aoff;
                LDSM4(a_h[m], ad);
                LDSM4(a_l[m], ad + 18432);
            }
            int vcb = ks * 32 + vsel;
#pragma unroll
            for (int nn = 0; nn < 2; nn++) {
                int brow = t_w + nn * 16 + vr + dk;
                uint32_t bd = sb + brow * PITCH + vcb;
                uint32_t b_h[4];
                LDSM4(b_h, bd + QB_H);
#pragma unroll
                for (int m = 0; m < 2; m++)
#pragma unroll
                    for (int j = 0; j < 2; j++) {
                        int n = nn * 2 + j, o = j * 2;
                        MMA16816H(acc[m][n], a_h[m], b_h[o], b_h[o + 1]);
                        MMA16816H(acc[m][n], a_l[m], b_h[o], b_h[o + 1]);
                    }
            }
        }
    }

#pragma unroll
    for (int m = 0; m < 2; m++) {
        int r0 = co_w + m * 16 + (lane >> 2);
        float bv0 = bias[co0 + r0];
        float bv1 = bias[co0 + r0 + 8];
        float* d0 = g_qkv + ((size_t)b * COUT3 + co0 + r0) * TT + t0;
        float* d1 = d0 + (size_t)8 * TT;
#pragma unroll
        for (int n = 0; n < 4; n++) {
            int cp = t_w + n * 8 + (lane & 3) * 2;
            float2 v0, v1;
            v0.x = acc[m][n][0] + bv0; v0.y = acc[m][n][1] + bv0;
            v1.x = acc[m][n][2] + bv1; v1.y = acc[m][n][3] + bv1;
            *(float2*)(d0 + cp) = v0;
            *(float2*)(d1 + cp) = v1;
        }
    }
}

// ---------------- Flash attention (bf16x3 internals, fp16 hi/lo epilogue) ----
#define AT_QH 0
#define AT_QL 18432
#define AT_KH 36864
#define AT_KL 55296
#define AT_VH 73728
#define AT_VL 92160
#define AT_S  110592
#define AT_PH 127488
#define AT_PL 136704
#define AT_M  145920
#define AT_L  146176
#define AT_AL 146432
#define AT_RED 146688
#define ASMEM 147712

__global__ void __launch_bounds__(256, 1) attn2_kernel() {
    int q0 = blockIdx.x * 64;
    int bh = blockIdx.y;
    int b = bh / HEADS, hh = bh % HEADS;
    const float* qkv = g_qkv + (size_t)b * COUT3 * TT + (size_t)hh * (3 * HC) * TT;
    char* sm = qsm;
    uint32_t sb = smem_to_u32(sm);
    int tid = threadIdx.x, wid = tid >> 5, lane = tid & 31;
    int qw = (wid >> 2) * 32;
    int kw = (wid & 3) * 16;
    int cw = (wid & 3) * 32;
    int row = tid & 63, quad = tid >> 6;

    float* s_s = (float*)(sm + AT_S);
    float* m_s = (float*)(sm + AT_M);
    float* l_s = (float*)(sm + AT_L);
    float* al_s = (float*)(sm + AT_AL);
    float* red = (float*)(sm + AT_RED);

    const float scale = 0.0883883476483184f;
    for (int i = tid; i < 2048; i += 256) {
        int c = i >> 4, j4 = (i & 15) * 4;
        float4 v = *(const float4*)(qkv + (size_t)c * TT + q0 + j4);
        v.x *= scale; v.y *= scale; v.z *= scale; v.w *= scale;
        uint2 ph, pl;
        split4(v, ph, pl);
        *(uint2*)(sm + AT_QH + c * 144 + j4 * 2) = ph;
        *(uint2*)(sm + AT_QL + c * 144 + j4 * 2) = pl;
    }
    if (tid < 64) { m_s[tid] = -1e30f; l_s[tid] = 0.f; }

    float oacc[2][4][4] = {};
    __syncthreads();

    for (int kt = 0; kt < TT; kt += 64) {
        for (int i = tid; i < 2048; i += 256) {
            int c = i >> 4, j4 = (i & 15) * 4;
            float4 kv4 = *(const float4*)(qkv + (size_t)(HC + c) * TT + kt + j4);
            uint2 ph, pl;
            split4(kv4, ph, pl);
            *(uint2*)(sm + AT_KH + c * 144 + j4 * 2) = ph;
            *(uint2*)(sm + AT_KL + c * 144 + j4 * 2) = pl;
            float4 vv4 = *(const float4*)(qkv + (size_t)(2 * HC + c) * TT + kt + j4);
            split4(vv4, ph, pl);
            *(uint2*)(sm + AT_VH + c * 144 + j4 * 2) = ph;
            *(uint2*)(sm + AT_VL + c * 144 + j4 * 2) = pl;
        }
        __syncthreads();

        float sacc[2][2][4] = {};
#pragma unroll
        for (int ks = 0; ks < 8; ks++) {
            int kk0 = ks * 16;
            int ar = kk0 + (lane & 7) + (lane >> 4) * 8;
            int acb = ((lane >> 3) & 1) * 16;
            uint32_t a_h[2][4], a_l[2][4];
#pragma unroll
            for (int m = 0; m < 2; m++) {
                uint32_t ad = sb + ar * 144 + (qw + m * 16) * 2 + acb;
                LDSM4T(a_h[m], ad + AT_QH);
                LDSM4T(a_l[m], ad + AT_QL);
            }
            int br = kk0 + (lane & 7) + ((lane >> 3) & 1) * 8;
            uint32_t bd = sb + br * 144 + kw * 2 + (lane >> 4) * 16;
            uint32_t b_h[4], b_l[4];
            LDSM4T(b_h, bd + AT_KH);
            LDSM4T(b_l, bd + AT_KL);
#pragma unroll
            for (int m = 0; m < 2; m++)
#pragma unroll
                for (int n = 0; n < 2; n++) {
                    MMA16816(sacc[m][n], a_h[m], b_h[2 * n], b_h[2 * n + 1]);
                    MMA16816(sacc[m][n], a_h[m], b_l[2 * n], b_l[2 * n + 1]);
                    MMA16816(sacc[m][n], a_l[m], b_h[2 * n], b_h[2 * n + 1]);
                }
        }
#pragma unroll
        for (int m = 0; m < 2; m++) {
            int r0 = qw + m * 16 + (lane >> 2);
#pragma unroll
            for (int n = 0; n < 2; n++) {
                int c0 = kw + n * 8 + (lane & 3) * 2;
                s_s[r0 * 66 + c0] = sacc[m][n][0];
                s_s[r0 * 66 + c0 + 1] = sacc[m][n][1];
                s_s[(r0 + 8) * 66 + c0] = sacc[m][n][2];
                s_s[(r0 + 8) * 66 + c0 + 1] = sacc[m][n][3];
            }
        }
        __syncthreads();

        float mx = -1e30f;
#pragma unroll
        for (int j = 0; j < 16; j++) mx = fmaxf(mx, s_s[row * 66 + quad * 16 + j]);
        red[row * 4 + quad] = mx;
        __syncthreads();
        if (tid < 64) {
            float m_old = m_s[tid];
            float mm = fmaxf(fmaxf(red[tid * 4], red[tid * 4 + 1]),
                             fmaxf(red[tid * 4 + 2], red[tid * 4 + 3]));
            float m_new = fmaxf(m_old, mm);
            al_s[tid] = __expf(m_old - m_new);
            m_s[tid] = m_new;
        }
        __syncthreads();
        {
            float m_new = m_s[row];
            float ssum = 0.f;
#pragma unroll
            for (int j = 0; j < 16; j += 2) {
                int cc0 = quad * 16 + j;
                float p0 = __expf(s_s[row * 66 + cc0] - m_new);
                float p1 = __expf(s_s[row * 66 + cc0 + 1] - m_new);
                ssum += p0 + p1;
                uint32_t ph, pl;
                pack2(p0, p1, ph, pl);
                *(uint32_t*)(sm + AT_PH + row * 144 + cc0 * 2) = ph;
                *(uint32_t*)(sm + AT_PL + row * 144 + cc0 * 2) = pl;
            }
            red[row * 4 + quad] = ssum;
        }
        __syncthreads();
        if (tid < 64)
            l_s[tid] = l_s[tid] * al_s[tid] +
                       red[tid * 4] + red[tid * 4 + 1] + red[tid * 4 + 2] + red[tid * 4 + 3];
        __syncthreads();

#pragma unroll
        for (int m = 0; m < 2; m++) {
            float a0 = al_s[qw + m * 16 + (lane >> 2)];
            float a1 = al_s[qw + m * 16 + 8 + (lane >> 2)];
#pragma unroll
            for (int n = 0; n < 4; n++) {
                oacc[m][n][0] *= a0; oacc[m][n][1] *= a0;
                oacc[m][n][2] *= a1; oacc[m][n][3] *= a1;
            }
        }
#pragma unroll
        for (int ks = 0; ks < 4; ks++) {
            int kk0 = ks * 16;
            int pr = (lane & 7) + ((lane >> 3) & 1) * 8;
            int pcb = kk0 * 2 + (lane >> 4) * 16;
            uint32_t pa_h[2][4], pa_l[2][4];
#pragma unroll
            for (int m = 0; m < 2; m++) {
                uint32_t ad = sb + (qw + m * 16 + pr) * 144 + pcb;
                LDSM4(pa_h[m], ad + AT_PH);
                LDSM4(pa_l[m], ad + AT_PL);
            }
            int vr = (lane & 7) + (lane >> 4) * 8;
            int vcb = kk0 * 2 + ((lane >> 3) & 1) * 16;
            uint32_t vb_h[2][4], vb_l[2][4];
#pragma unroll
            for (int nn = 0; nn < 2; nn++) {
                uint32_t vd = sb + (cw + nn * 16 + vr) * 144 + vcb;
                LDSM4(vb_h[nn], vd + AT_VH);
                LDSM4(vb_l[nn], vd + AT_VL);
            }
#pragma unroll
            for (int m = 0; m < 2; m++)
#pragma unroll
                for (int n = 0; n < 4; n++) {
                    int nn = n >> 1, o = (n & 1) * 2;
                    MMA16816(oacc[m][n], pa_h[m], vb_h[nn][o], vb_h[nn][o + 1]);
                    MMA16816(oacc[m][n], pa_h[m], vb_l[nn][o], vb_l[nn][o + 1]);
                    MMA16816(oacc[m][n], pa_l[m], vb_h[nn][o], vb_h[nn][o + 1]);
                }
        }
        __syncthreads();
    }

    // epilogue: write fp16 hi+lo to g_xth/g_xtl[b][q + 2][hh*HC + c]
#pragma unroll
    for (int m = 0; m < 2; m++) {
        int r0 = qw + m * 16 + (lane >> 2);
        float inv0 = 1.f / l_s[r0];
        float inv1 = 1.f / l_s[r0 + 8];
        size_t row0 = ((size_t)b * TP + q0 + r0 + 2) * CC;
        size_t row1 = ((size_t)b * TP + q0 + r0 + 10) * CC;
#pragma unroll
        for (int n = 0; n < 4; n++) {
            int c0 = hh * HC + cw + n * 8 + (lane & 3) * 2;
            uint32_t h0, l0, h1, l1;
            packh2hl(oacc[m][n][0] * inv0, oacc[m][n][1] * inv0, h0, l0);
            packh2hl(oacc[m][n][2] * inv1, oacc[m][n][3] * inv1, h1, l1);
            *(uint32_t*)(g_xth + row0 + c0) = h0;
            *(uint32_t*)(g_xtl + row0 + c0) = l0;
            *(uint32_t*)(g_xth + row1 + c0) = h1;
            *(uint32_t*)(g_xtl + row1 + c0) = l1;
        }
    }
}

// -------------- Proj conv warp-mma fp16 3-pass (hi/lo activations) -----------
#define PB_H 73728
#define PB_L 111168
#define PSMEM 148608

__global__ void __launch_bounds__(512, 1) projmma_kernel(const float* __restrict__ bias,
                                                         const float* __restrict__ x,
                                                         float* __restrict__ out) {
    int t0 = blockIdx.x * 256, co0 = blockIdx.y * 128, b = blockIdx.z;
    int tid = threadIdx.x, wid = tid >> 5, lane = tid & 31;
    int co_w = (wid >> 2) * 32, t_w = (wid & 3) * 64;
    uint32_t sb = smem_to_u32(qsm);
    float acc[2][8][4] = {};

    {
        const __half* ah = g_w2h + (size_t)co0 * CC;
        const __half* al = g_w2l + (size_t)co0 * CC;
        for (int i = tid; i < 2048; i += 512) {
            int part = i >> 10, j = i & 1023, row = j >> 3, g = j & 7;
            const __half* src = (part ? al : ah) + (size_t)row * CC + g * 8;
            CPASYNC16(sb + part * 18432 + row * PITCH + g * 16, src);
        }
        CPCOMMIT();
    }

    for (int s = 0; s < 40; s++) {
        int dk = s % 5;
        if (dk == 0) {
            int ci0 = (s / 5) * 64;
            __syncthreads();
            const __half* bh = g_xth + ((size_t)b * TP + t0) * CC + ci0;
            const __half* bl = g_xtl + ((size_t)b * TP + t0) * CC + ci0;
            for (int i = tid; i < 260 * 8; i += 512) {
                int row = i >> 3, g = i & 7;
                size_t go = (size_t)row * CC + g * 8;
                *(uint4*)(qsm + PB_H + row * PITCH + g * 16) = *(const uint4*)(bh + go);
                *(uint4*)(qsm + PB_L + row * PITCH + g * 16) = *(const uint4*)(bl + go);
            }
        }
        CPWAIT0();
        __syncthreads();

        if (s + 1 < 40) {
            int s1 = s + 1;
            int dk1 = s1 % 5, ci1 = (s1 / 5) * 64;
            uint32_t ab = (uint32_t)(s1 & 1) * AB_STRIDE;
            const __half* ah = g_w2h + ((size_t)dk1 * CC + co0) * CC + ci1;
            const __half* al = g_w2l + ((size_t)dk1 * CC + co0) * CC + ci1;
            for (int i = tid; i < 2048; i += 512) {
                int part = i >> 10, j = i & 1023, row = j >> 3, g = j & 7;
                const __half* src = (part ? al : ah) + (size_t)row * CC + g * 8;
                CPASYNC16(sb + ab + part * 18432 + row * PITCH + g * 16, src);
            }
            CPCOMMIT();
        }

        uint32_t abase = sb + (uint32_t)(s & 1) * AB_STRIDE;
        int mtx = lane >> 3, r8 = lane & 7;
        int vr = (lane & 7) + (lane >> 4) * 8;
        int vsel = ((lane >> 3) & 1) * 16;
#pragma unroll
        for (int ks = 0; ks < 4; ks++) {
            uint32_t a_h[2][4], a_l[2][4];
            int aoff = ((mtx & 1) * 8 + r8) * PITCH + ks * 32 + (mtx >> 1) * 16;
#pragma unroll
            for (int m = 0; m < 2; m++) {
                uint32_t ad = abase + (co_w + m * 16) * PITCH + aoff;
                LDSM4(a_h[m], ad);
                LDSM4(a_l[m], ad + 18432);
            }
            int vcb = ks * 32 + vsel;
#pragma unroll
            for (int nn = 0; nn < 4; nn++) {
                int brow = t_w + nn * 16 + vr + dk;
                uint32_t bd = sb + brow * PITCH + vcb;
                uint32_t b_h[4], b_l[4];
                LDSM4(b_h, bd + PB_H);
                LDSM4(b_l, bd + PB_L);
#pragma unroll
                for (int m = 0; m < 2; m++)
#pragma unroll
                    for (int j = 0; j < 2; j++) {
                        int n = nn * 2 + j, o = j * 2;
                        MMA16816H(acc[m][n], a_h[m], b_h[o], b_h[o + 1]);
                        MMA16816H(acc[m][n], a_l[m], b_h[o], b_h[o + 1]);
                        MMA16816H(acc[m][n], a_h[m], b_l[o], b_l[o + 1]);
                    }
            }
        }
    }

#pragma unroll
    for (int m = 0; m < 2; m++) {
        int r0 = co_w + m * 16 + (lane >> 2);
        float bv0 = bias[co0 + r0];
        float bv1 = bias[co0 + r0 + 8];
        const float* x0 = x + ((size_t)b * CC + co0 + r0) * TT + t0;
        const float* x1 = x0 + (size_t)8 * TT;
        float* d0 = out + ((size_t)b * CC + co0 + r0) * TT + t0;
        float* d1 = d0 + (size_t)8 * TT;
#pragma unroll
        for (int n = 0; n < 8; n++) {
            int cp = t_w + n * 8 + (lane & 3) * 2;
            float2 r0v = *(const float2*)(x0 + cp);
            float2 r1v = *(const float2*)(x1 + cp);
            float2 v0, v1;
            v0.x = acc[m][n][0] + bv0 + r0v.x; v0.y = acc[m][n][1] + bv0 + r0v.y;
            v1.x = acc[m][n][2] + bv1 + r1v.x; v1.y = acc[m][n][3] + bv1 + r1v.y;
            *(float2*)(d0 + cp) = v0;
            *(float2*)(d1 + cp) = v1;
        }
    }
}

// -----------------------------------------------------------------------------
extern "C" void kernel_launch(void* const* d_in, const int* in_sizes, int n_in,
                              void* d_out, int out_size) {
    const float* x = (const float*)d_in[0];
    const float* gn_gamma = (const float*)d_in[1];
    const float* gn_beta = (const float*)d_in[2];
    const float* qkv_w = (const float*)d_in[3];
    const float* qkv_b = (const float*)d_in[4];
    const float* proj_w = (const float*)d_in[5];
    const float* proj_b = (const float*)d_in[6];
    float* out = (float*)d_out;

    cudaFuncSetAttribute(qkvmma_kernel, cudaFuncAttributeMaxDynamicSharedMemorySize, QSMEM);
    cudaFuncSetAttribute(attn2_kernel, cudaFuncAttributeMaxDynamicSharedMemorySize, ASMEM);
    cudaFuncSetAttribute(projmma_kernel, cudaFuncAttributeMaxDynamicSharedMemorySize, PSMEM);

    gn_kernel<<<BB * NG, 256>>>(x, gn_gamma, gn_beta);
    zed_kernel<<<BB, 256>>>();
    xt_kernel<<<dim3(TT / 64, CC / 64, BB), 256>>>();
    wt_kernel<<<dim3(COUT3, CC / 128), 256>>>(qkv_w);
    qkvmma_kernel<<<dim3(TT / 128, COUT3 / 128, BB), 512, QSMEM>>>(qkv_b);
    wt2_kernel<<<dim3(CC, CC / 128), 256>>>(proj_w);
    zed2_kernel<<<BB, 256>>>();
    attn2_kernel<<<dim3(TT / 64, BB * HEADS), 256, ASMEM>>>();
    projmma_kernel<<<dim3(TT / 256, CC / 128, BB), 512, PSMEM>>>(proj_b, x, out);
}